// round 1
// baseline (speedup 1.0000x reference)
#include <cuda_runtime.h>
#include <cuda_bf16.h>
#include <math.h>

// ---------------- problem constants ----------------
#define B_    2
#define T_    64
#define N_    4096
#define HOR_  24
#define C_    16
#define HID_  32
#define BD_   8
#define HEADS_ 4
#define HD_   8
#define CT_   (C_*T_)          // 1024
#define BH_   (B_*HEADS_)      // 8
#define LOG2E 1.4426950408889634f
#define INV_SQRT8 0.35355339059327373f

// ---------------- scratch (device globals; no allocation) ----------------
__device__ float d_Qp[BH_ * N_ * 16];   // [b*4+h][n][16]  (log2e folded, q scaled)
__device__ float d_Kp[BH_ * N_ * 16];   // [b*4+h][n][16]
__device__ float d_Vv[BH_ * N_ * 8];    // [b*4+h][n][8]
__device__ float d_att[BH_ * N_ * 8];   // attention output (normalized)
__device__ float d_s[B_ * N_ * HID_];   // after output projection

__device__ __forceinline__ float ex2f(float x) {
    float y; asm("ex2.approx.ftz.f32 %0, %1;" : "=f"(y) : "f"(x)); return y;
}
__device__ __forceinline__ float elu1(float x) {
    return x > 0.f ? x + 1.f : __expf(x);
}

// =====================================================================
// Kernel A: per-node conv feature extractor -> p1 -> p2 -> qkv -> Q'/K'/V
// one warp per node, 8 nodes per 256-thread block
// =====================================================================
__global__ void __launch_bounds__(256)
feat_kernel(const float* __restrict__ x,
            const float* __restrict__ fe_w, const float* __restrict__ fe_b,
            const float* __restrict__ bn_g, const float* __restrict__ bn_b,
            const float* __restrict__ p1_w, const float* __restrict__ p1_b,
            const float* __restrict__ p2_w, const float* __restrict__ p2_b,
            const float* __restrict__ qkv_w, const float* __restrict__ qkv_b,
            const float* __restrict__ u, const float* __restrict__ v)
{
    __shared__ float p1s[8192];       // [8][1024]
    __shared__ float xs[8][66];       // padded time series per node
    __shared__ float fs[8][32];
    __shared__ float cw[48];          // bn-scaled conv weights
    __shared__ float csh[16];         // fused shift

    const int tid = threadIdx.x;
    const int blk = blockIdx.x;
    const int b   = blk >> 9;
    const int n0  = (blk & 511) << 3;

    for (int i = tid; i < 8192; i += 256) p1s[i] = p1_w[i];
    if (tid < 48) {
        int c = tid / 3;
        float sc = bn_g[c] * rsqrtf(1.f + 1e-5f);
        cw[tid] = fe_w[tid] * sc;
    }
    if (tid < 16) {
        float sc = bn_g[tid] * rsqrtf(1.f + 1e-5f);
        csh[tid] = fe_b[tid] * sc + bn_b[tid];
    }
    for (int i = tid; i < 512; i += 256) {
        int node = i & 7, t = i >> 3;
        xs[node][t + 1] = x[(size_t)b * T_ * N_ + (size_t)t * N_ + n0 + node];
    }
    if (tid < 8) { xs[tid][0] = 0.f; xs[tid][65] = 0.f; }
    __syncthreads();

    const int w = tid >> 5, lane = tid & 31;
    const int n = n0 + w;

    float acc[8];
#pragma unroll
    for (int j = 0; j < 8; j++) acc[j] = 0.f;

#pragma unroll
    for (int i = 0; i < 32; i++) {
        int c = i >> 1;
        int t = lane + ((i & 1) << 5);
        float val = xs[w][t] * cw[c * 3] + xs[w][t + 1] * cw[c * 3 + 1]
                  + xs[w][t + 2] * cw[c * 3 + 2] + csh[c];
        val = fmaxf(val, 0.f);
        int base = i * 32 + lane;
#pragma unroll
        for (int j = 0; j < 8; j++) acc[j] += val * p1s[j * 1024 + base];
    }
#pragma unroll
    for (int j = 0; j < 8; j++)
#pragma unroll
        for (int off = 16; off; off >>= 1)
            acc[j] += __shfl_xor_sync(0xffffffffu, acc[j], off);

    float r1[8];
#pragma unroll
    for (int j = 0; j < 8; j++) r1[j] = fmaxf(acc[j] + __ldg(p1_b + j), 0.f);

    // p2: lane -> f[lane]
    float f = __ldg(p2_b + lane);
#pragma unroll
    for (int j = 0; j < 8; j++) f += r1[j] * __ldg(p2_w + lane * 8 + j);
    fs[w][lane] = f;
    __syncwarp();

    // qkv: lane computes outputs lane, lane+32, lane+64
    float oq = __ldg(qkv_b + lane);
    float ok = __ldg(qkv_b + lane + 32);
    float ov = __ldg(qkv_b + lane + 64);
#pragma unroll
    for (int i = 0; i < 32; i++) {
        float fi = fs[w][i];
        oq += fi * __ldg(qkv_w + lane * 32 + i);
        ok += fi * __ldg(qkv_w + (lane + 32) * 32 + i);
        ov += fi * __ldg(qkv_w + (lane + 64) * 32 + i);
    }

    const int head = lane >> 3, d = lane & 7;
    const size_t ridx = ((size_t)(b * 4 + head) * N_ + n);
    const size_t qidx = ridx * 16;

    d_Qp[qidx + d]     = elu1(oq) * (LOG2E * INV_SQRT8);
    d_Qp[qidx + 8 + d] = u[(size_t)n * 8 + d] * LOG2E;
    d_Kp[qidx + d]     = elu1(ok);
    d_Kp[qidx + 8 + d] = v[(size_t)d * N_ + n];
    d_Vv[ridx * 8 + d] = ov;
}

// =====================================================================
// Kernel B: flash attention (no-max softmax), d_qk=16, d_v=8
// grid (N/128, B*H), 128 threads, one query row per thread
// =====================================================================
#define ATT_BN 128
__global__ void __launch_bounds__(128)
attn_kernel()
{
    const int bh = blockIdx.y;
    const int r  = blockIdx.x * 128 + threadIdx.x;
    const float* Qb = d_Qp + (size_t)bh * N_ * 16;
    const float* Kb = d_Kp + (size_t)bh * N_ * 16;
    const float* Vb = d_Vv + (size_t)bh * N_ * 8;

    __shared__ float Ks[ATT_BN * 16];
    __shared__ float Vs[ATT_BN * 8];

    const float4* qp = (const float4*)(Qb + (size_t)r * 16);
    const float4 q0 = qp[0], q1 = qp[1], q2 = qp[2], q3 = qp[3];

    float acc0 = 0.f, acc1 = 0.f, acc2 = 0.f, acc3 = 0.f;
    float acc4 = 0.f, acc5 = 0.f, acc6 = 0.f, acc7 = 0.f;
    float l = 0.f;

    for (int kt = 0; kt < N_; kt += ATT_BN) {
        __syncthreads();
        {
            const float4* src = (const float4*)(Kb + (size_t)kt * 16);
            float4* dst = (float4*)Ks;
#pragma unroll
            for (int i = 0; i < 4; i++) dst[threadIdx.x + i * 128] = src[threadIdx.x + i * 128];
            const float4* vsrc = (const float4*)(Vb + (size_t)kt * 8);
            float4* vdst = (float4*)Vs;
#pragma unroll
            for (int i = 0; i < 2; i++) vdst[threadIdx.x + i * 128] = vsrc[threadIdx.x + i * 128];
        }
        __syncthreads();

#pragma unroll 4
        for (int j = 0; j < ATT_BN; j++) {
            const float4* kr = (const float4*)(Ks + j * 16);
            float4 k0 = kr[0], k1 = kr[1], k2 = kr[2], k3 = kr[3];
            float s = q0.x * k0.x + q0.y * k0.y + q0.z * k0.z + q0.w * k0.w
                    + q1.x * k1.x + q1.y * k1.y + q1.z * k1.z + q1.w * k1.w
                    + q2.x * k2.x + q2.y * k2.y + q2.z * k2.z + q2.w * k2.w
                    + q3.x * k3.x + q3.y * k3.y + q3.z * k3.z + q3.w * k3.w;
            float p = ex2f(s);
            l += p;
            const float4* vr = (const float4*)(Vs + j * 8);
            float4 v0 = vr[0], v1 = vr[1];
            acc0 += p * v0.x; acc1 += p * v0.y; acc2 += p * v0.z; acc3 += p * v0.w;
            acc4 += p * v1.x; acc5 += p * v1.y; acc6 += p * v1.z; acc7 += p * v1.w;
        }
    }

    float inv = 1.f / l;
    float* o = d_att + ((size_t)bh * N_ + r) * 8;
    float4* o4 = (float4*)o;
    o4[0] = make_float4(acc0 * inv, acc1 * inv, acc2 * inv, acc3 * inv);
    o4[1] = make_float4(acc4 * inv, acc5 * inv, acc6 * inv, acc7 * inv);
}

// =====================================================================
// Kernel C1: attention output -> op projection -> s
// =====================================================================
__global__ void __launch_bounds__(256)
proj_kernel(const float* __restrict__ op_w, const float* __restrict__ op_b)
{
    __shared__ float fs[8][32];
    const int tid = threadIdx.x;
    const int blk = blockIdx.x;
    const int b   = blk >> 9;
    const int n0  = (blk & 511) << 3;
    const int w = tid >> 5, lane = tid & 31;
    const int n = n0 + w;
    const int head = lane >> 3, e = lane & 7;

    fs[w][lane] = d_att[((size_t)(b * 4 + head) * N_ + n) * 8 + e];
    __syncwarp();

    float acc = __ldg(op_b + lane);
#pragma unroll
    for (int i = 0; i < 32; i++)
        acc += fs[w][i] * __ldg(op_w + lane * 32 + i);
    d_s[((size_t)b * N_ + n) * 32 + lane] = acc;
}

// =====================================================================
// Kernel C2: dilated convs over node axis + BN + relu + residual LN
//            -> horizon MLP (h1, LN, relu, h2) -> output [B,24,N]
// one warp per node, 8 nodes per 256-thread block
// =====================================================================
__global__ void __launch_bounds__(256)
tail_kernel(const float* __restrict__ tc0_w, const float* __restrict__ tc0_b,
            const float* __restrict__ tc1_w, const float* __restrict__ tc1_b,
            const float* __restrict__ bn_g, const float* __restrict__ bn_b,
            const float* __restrict__ ln_g, const float* __restrict__ ln_b,
            const float* __restrict__ h1_w, const float* __restrict__ h1_b,
            const float* __restrict__ hln_g, const float* __restrict__ hln_b,
            const float* __restrict__ h2_w, const float* __restrict__ h2_b,
            float* __restrict__ out)
{
    __shared__ float ss[12 * 32];     // s rows n0-2 .. n0+9 (zero-padded)
    __shared__ float tw0[96 * 32];    // transposed conv weights: [(ci*3+k)][co]
    __shared__ float tw1[96 * 32];

    const int tid = threadIdx.x;
    const int blk = blockIdx.x;
    const int b   = blk >> 9;
    const int n0  = (blk & 511) << 3;

    for (int idx = tid; idx < 3072; idx += 256) {
        int co = idx / 96, rem = idx % 96;
        tw0[rem * 32 + co] = tc0_w[idx];
        tw1[rem * 32 + co] = tc1_w[idx];
    }
    for (int idx = tid; idx < 384; idx += 256) {
        int rr = idx >> 5, c = idx & 31;
        int gn = n0 - 2 + rr;
        ss[idx] = (gn >= 0 && gn < N_) ? d_s[((size_t)b * N_ + gn) * 32 + c] : 0.f;
    }
    __syncthreads();

    const int w = tid >> 5, lane = tid & 31;
    const int n = n0 + w;
    const int lr = w + 2;

    float v0 = __ldg(tc0_b + lane), v1 = __ldg(tc1_b + lane);
#pragma unroll
    for (int ci = 0; ci < 32; ci++) {
        float sm2 = ss[(lr - 2) * 32 + ci];
        float sm1 = ss[(lr - 1) * 32 + ci];
        float s0  = ss[lr * 32 + ci];
        float sp1 = ss[(lr + 1) * 32 + ci];
        float sp2 = ss[(lr + 2) * 32 + ci];
        v0 += sm1 * tw0[(ci * 3 + 0) * 32 + lane]
            + s0  * tw0[(ci * 3 + 1) * 32 + lane]
            + sp1 * tw0[(ci * 3 + 2) * 32 + lane];
        v1 += sm2 * tw1[(ci * 3 + 0) * 32 + lane]
            + s0  * tw1[(ci * 3 + 1) * 32 + lane]
            + sp2 * tw1[(ci * 3 + 2) * 32 + lane];
    }
    float bs = __ldg(bn_g + lane) * rsqrtf(1.f + 1e-5f);
    float bb = __ldg(bn_b + lane);
    float y0 = fmaxf(v0 * bs + bb, 0.f);
    float y1 = fmaxf(v1 * bs + bb, 0.f);
    float resid = 0.5f * (y0 + y1) + ss[lr * 32 + lane];

    // layernorm over 32 channels (warp-wide)
    float sum = resid, sq = resid * resid;
#pragma unroll
    for (int off = 16; off; off >>= 1) {
        sum += __shfl_xor_sync(0xffffffffu, sum, off);
        sq  += __shfl_xor_sync(0xffffffffu, sq, off);
    }
    float mu = sum * (1.f / 32.f);
    float var = sq * (1.f / 32.f) - mu * mu;
    float rstd = rsqrtf(var + 1e-5f);
    float tout = (resid - mu) * rstd * __ldg(ln_g + lane) + __ldg(ln_b + lane);

    // h1: 8 outputs via per-lane partial + butterfly reduce
    float hj[8];
#pragma unroll
    for (int j = 0; j < 8; j++) hj[j] = tout * __ldg(h1_w + j * 32 + lane);
#pragma unroll
    for (int j = 0; j < 8; j++)
#pragma unroll
        for (int off = 16; off; off >>= 1)
            hj[j] += __shfl_xor_sync(0xffffffffu, hj[j], off);

    float hsum = 0.f;
#pragma unroll
    for (int j = 0; j < 8; j++) { hj[j] += __ldg(h1_b + j); hsum += hj[j]; }
    float hmu = hsum * (1.f / 8.f);
    float hsq = 0.f;
#pragma unroll
    for (int j = 0; j < 8; j++) { float dd = hj[j] - hmu; hsq += dd * dd; }
    float hrstd = rsqrtf(hsq * (1.f / 8.f) + 1e-5f);
    float hh[8];
#pragma unroll
    for (int j = 0; j < 8; j++)
        hh[j] = fmaxf((hj[j] - hmu) * hrstd * __ldg(hln_g + j) + __ldg(hln_b + j), 0.f);

    if (lane < HOR_) {
        float p = __ldg(h2_b + lane);
#pragma unroll
        for (int j = 0; j < 8; j++) p += hh[j] * __ldg(h2_w + lane * 8 + j);
        out[(size_t)b * HOR_ * N_ + (size_t)lane * N_ + n] = p;
    }
}

// =====================================================================
extern "C" void kernel_launch(void* const* d_in, const int* in_sizes, int n_in,
                              void* d_out, int out_size)
{
    const float* x      = (const float*)d_in[0];
    const float* fe_w   = (const float*)d_in[1];
    const float* fe_b   = (const float*)d_in[2];
    const float* fe_bng = (const float*)d_in[3];
    const float* fe_bnb = (const float*)d_in[4];
    const float* p1_w   = (const float*)d_in[5];
    const float* p1_b   = (const float*)d_in[6];
    const float* p2_w   = (const float*)d_in[7];
    const float* p2_b   = (const float*)d_in[8];
    const float* qkv_w  = (const float*)d_in[9];
    const float* qkv_b  = (const float*)d_in[10];
    const float* op_w   = (const float*)d_in[11];
    const float* op_b   = (const float*)d_in[12];
    const float* u      = (const float*)d_in[13];
    const float* v      = (const float*)d_in[14];
    const float* tc0_w  = (const float*)d_in[15];
    const float* tc0_b  = (const float*)d_in[16];
    const float* tc1_w  = (const float*)d_in[17];
    const float* tc1_b  = (const float*)d_in[18];
    const float* t_bng  = (const float*)d_in[19];
    const float* t_bnb  = (const float*)d_in[20];
    const float* t_lng  = (const float*)d_in[21];
    const float* t_lnb  = (const float*)d_in[22];
    const float* h1_w   = (const float*)d_in[23];
    const float* h1_b   = (const float*)d_in[24];
    const float* h_lng  = (const float*)d_in[25];
    const float* h_lnb  = (const float*)d_in[26];
    const float* h2_w   = (const float*)d_in[27];
    const float* h2_b   = (const float*)d_in[28];
    float* out = (float*)d_out;

    const int nodeblocks = (B_ * N_) / 8;   // 1024

    feat_kernel<<<nodeblocks, 256>>>(x, fe_w, fe_b, fe_bng, fe_bnb,
                                     p1_w, p1_b, p2_w, p2_b,
                                     qkv_w, qkv_b, u, v);

    dim3 agrid(N_ / 128, BH_);
    attn_kernel<<<agrid, 128>>>();

    proj_kernel<<<nodeblocks, 256>>>(op_w, op_b);

    tail_kernel<<<nodeblocks, 256>>>(tc0_w, tc0_b, tc1_w, tc1_b,
                                     t_bng, t_bnb, t_lng, t_lnb,
                                     h1_w, h1_b, h_lng, h_lnb,
                                     h2_w, h2_b, out);
}

// round 2
// speedup vs baseline: 1.0789x; 1.0789x over previous
#include <cuda_runtime.h>
#include <cuda_bf16.h>
#include <math.h>

// ---------------- problem constants ----------------
#define B_    2
#define T_    64
#define N_    4096
#define HOR_  24
#define C_    16
#define HID_  32
#define BD_   8
#define HEADS_ 4
#define HD_   8
#define CT_   (C_*T_)          // 1024
#define BH_   (B_*HEADS_)      // 8
#define LOG2E 1.4426950408889634f
#define INV_SQRT8 0.35355339059327373f

// ---------------- scratch (device globals; no allocation) ----------------
__device__ float d_Qp[BH_ * N_ * 16];   // [b*4+h][n][16]  (log2e folded, q scaled)
__device__ float d_Kp[BH_ * N_ * 16];   // [b*4+h][n][16]
__device__ float d_Vv[BH_ * N_ * 8];    // [b*4+h][n][8]
__device__ float d_att[BH_ * N_ * 8];   // attention output (normalized)
__device__ float d_s[B_ * N_ * HID_];   // after output projection

__device__ __forceinline__ float ex2f(float x) {
    float y; asm("ex2.approx.ftz.f32 %0, %1;" : "=f"(y) : "f"(x)); return y;
}
__device__ __forceinline__ float elu1(float x) {
    return x > 0.f ? x + 1.f : __expf(x);
}

// packed fp32x2 helpers (Blackwell packed FMA — PTX-only pattern)
__device__ __forceinline__ unsigned long long ffma2(unsigned long long a,
                                                    unsigned long long b,
                                                    unsigned long long c) {
    unsigned long long d;
    asm("fma.rn.f32x2 %0, %1, %2, %3;" : "=l"(d) : "l"(a), "l"(b), "l"(c));
    return d;
}
__device__ __forceinline__ unsigned long long fadd2(unsigned long long a,
                                                    unsigned long long b) {
    unsigned long long d;
    asm("add.rn.f32x2 %0, %1, %2;" : "=l"(d) : "l"(a), "l"(b));
    return d;
}
__device__ __forceinline__ unsigned long long pk2(float lo, float hi) {
    unsigned long long r;
    asm("mov.b64 %0, {%1, %2};" : "=l"(r) : "f"(lo), "f"(hi));
    return r;
}
__device__ __forceinline__ void upk2(unsigned long long v, float& lo, float& hi) {
    asm("mov.b64 {%0, %1}, %2;" : "=f"(lo), "=f"(hi) : "l"(v));
}

// =====================================================================
// Kernel A: per-node conv feature extractor -> p1 -> p2 -> qkv -> Q'/K'/V
// one warp per node, 8 nodes per 256-thread block
// =====================================================================
__global__ void __launch_bounds__(256)
feat_kernel(const float* __restrict__ x,
            const float* __restrict__ fe_w, const float* __restrict__ fe_b,
            const float* __restrict__ bn_g, const float* __restrict__ bn_b,
            const float* __restrict__ p1_w, const float* __restrict__ p1_b,
            const float* __restrict__ p2_w, const float* __restrict__ p2_b,
            const float* __restrict__ qkv_w, const float* __restrict__ qkv_b,
            const float* __restrict__ u, const float* __restrict__ v)
{
    __shared__ float p1s[8192];       // [8][1024]
    __shared__ float xs[8][66];       // padded time series per node
    __shared__ float fs[8][32];
    __shared__ float cw[48];          // bn-scaled conv weights
    __shared__ float csh[16];         // fused shift

    const int tid = threadIdx.x;
    const int blk = blockIdx.x;
    const int b   = blk >> 9;
    const int n0  = (blk & 511) << 3;

    for (int i = tid; i < 8192; i += 256) p1s[i] = p1_w[i];
    if (tid < 48) {
        int c = tid / 3;
        float sc = bn_g[c] * rsqrtf(1.f + 1e-5f);
        cw[tid] = fe_w[tid] * sc;
    }
    if (tid < 16) {
        float sc = bn_g[tid] * rsqrtf(1.f + 1e-5f);
        csh[tid] = fe_b[tid] * sc + bn_b[tid];
    }
    for (int i = tid; i < 512; i += 256) {
        int node = i & 7, t = i >> 3;
        xs[node][t + 1] = x[(size_t)b * T_ * N_ + (size_t)t * N_ + n0 + node];
    }
    if (tid < 8) { xs[tid][0] = 0.f; xs[tid][65] = 0.f; }
    __syncthreads();

    const int w = tid >> 5, lane = tid & 31;
    const int n = n0 + w;

    float acc[8];
#pragma unroll
    for (int j = 0; j < 8; j++) acc[j] = 0.f;

#pragma unroll
    for (int i = 0; i < 32; i++) {
        int c = i >> 1;
        int t = lane + ((i & 1) << 5);
        float val = xs[w][t] * cw[c * 3] + xs[w][t + 1] * cw[c * 3 + 1]
                  + xs[w][t + 2] * cw[c * 3 + 2] + csh[c];
        val = fmaxf(val, 0.f);
        int base = i * 32 + lane;
#pragma unroll
        for (int j = 0; j < 8; j++) acc[j] += val * p1s[j * 1024 + base];
    }
#pragma unroll
    for (int j = 0; j < 8; j++)
#pragma unroll
        for (int off = 16; off; off >>= 1)
            acc[j] += __shfl_xor_sync(0xffffffffu, acc[j], off);

    float r1[8];
#pragma unroll
    for (int j = 0; j < 8; j++) r1[j] = fmaxf(acc[j] + __ldg(p1_b + j), 0.f);

    // p2: lane -> f[lane]
    float f = __ldg(p2_b + lane);
#pragma unroll
    for (int j = 0; j < 8; j++) f += r1[j] * __ldg(p2_w + lane * 8 + j);
    fs[w][lane] = f;
    __syncwarp();

    // qkv: lane computes outputs lane, lane+32, lane+64
    float oq = __ldg(qkv_b + lane);
    float ok = __ldg(qkv_b + lane + 32);
    float ov = __ldg(qkv_b + lane + 64);
#pragma unroll
    for (int i = 0; i < 32; i++) {
        float fi = fs[w][i];
        oq += fi * __ldg(qkv_w + lane * 32 + i);
        ok += fi * __ldg(qkv_w + (lane + 32) * 32 + i);
        ov += fi * __ldg(qkv_w + (lane + 64) * 32 + i);
    }

    const int head = lane >> 3, d = lane & 7;
    const size_t ridx = ((size_t)(b * 4 + head) * N_ + n);
    const size_t qidx = ridx * 16;

    d_Qp[qidx + d]     = elu1(oq) * (LOG2E * INV_SQRT8);
    d_Qp[qidx + 8 + d] = u[(size_t)n * 8 + d] * LOG2E;
    d_Kp[qidx + d]     = elu1(ok);
    d_Kp[qidx + 8 + d] = v[(size_t)d * N_ + n];
    d_Vv[ridx * 8 + d] = ov;
}

// =====================================================================
// Kernel B: flash attention (no-max softmax), d_qk=16, d_v=8
// packed fp32x2 FMA path. grid (N/128, B*H), 128 threads, 1 query/thread
// =====================================================================
#define ATT_BN 128
__global__ void __launch_bounds__(128)
attn_kernel()
{
    const int bh = blockIdx.y;
    const int r  = blockIdx.x * 128 + threadIdx.x;
    const float* Qb = d_Qp + (size_t)bh * N_ * 16;
    const float* Kb = d_Kp + (size_t)bh * N_ * 16;
    const float* Vb = d_Vv + (size_t)bh * N_ * 8;

    __shared__ __align__(16) float Ks[ATT_BN * 16];
    __shared__ __align__(16) float Vs[ATT_BN * 8];

    // q row as 8 packed f32x2
    unsigned long long q2[8];
    {
        const ulonglong2* qp = (const ulonglong2*)(Qb + (size_t)r * 16);
#pragma unroll
        for (int i = 0; i < 4; i++) {
            ulonglong2 t = qp[i];
            q2[i * 2] = t.x; q2[i * 2 + 1] = t.y;
        }
    }

    unsigned long long av[4];
#pragma unroll
    for (int i = 0; i < 4; i++) av[i] = 0ull;
    float l = 0.f;

    for (int kt = 0; kt < N_; kt += ATT_BN) {
        __syncthreads();
        {
            const float4* src = (const float4*)(Kb + (size_t)kt * 16);
            float4* dst = (float4*)Ks;
#pragma unroll
            for (int i = 0; i < 4; i++) dst[threadIdx.x + i * 128] = src[threadIdx.x + i * 128];
            const float4* vsrc = (const float4*)(Vb + (size_t)kt * 8);
            float4* vdst = (float4*)Vs;
#pragma unroll
            for (int i = 0; i < 2; i++) vdst[threadIdx.x + i * 128] = vsrc[threadIdx.x + i * 128];
        }
        __syncthreads();

#pragma unroll 4
        for (int j = 0; j < ATT_BN; j++) {
            const ulonglong2* kr = (const ulonglong2*)(Ks + j * 16);
            ulonglong2 ka = kr[0], kb2 = kr[1], kc = kr[2], kd = kr[3];
            unsigned long long d0 = ffma2(q2[0], ka.x, 0ull);
            unsigned long long d1 = ffma2(q2[1], ka.y, 0ull);
            d0 = ffma2(q2[2], kb2.x, d0);
            d1 = ffma2(q2[3], kb2.y, d1);
            d0 = ffma2(q2[4], kc.x, d0);
            d1 = ffma2(q2[5], kc.y, d1);
            d0 = ffma2(q2[6], kd.x, d0);
            d1 = ffma2(q2[7], kd.y, d1);
            d0 = fadd2(d0, d1);
            float lo, hi; upk2(d0, lo, hi);
            float p = ex2f(lo + hi);
            l += p;
            unsigned long long pp = pk2(p, p);
            const ulonglong2* vr = (const ulonglong2*)(Vs + j * 8);
            ulonglong2 va = vr[0], vb = vr[1];
            av[0] = ffma2(pp, va.x, av[0]);
            av[1] = ffma2(pp, va.y, av[1]);
            av[2] = ffma2(pp, vb.x, av[2]);
            av[3] = ffma2(pp, vb.y, av[3]);
        }
    }

    float inv = 1.f / l;
    float o[8];
#pragma unroll
    for (int i = 0; i < 4; i++) {
        float lo, hi; upk2(av[i], lo, hi);
        o[i * 2] = lo * inv; o[i * 2 + 1] = hi * inv;
    }
    float4* o4 = (float4*)(d_att + ((size_t)bh * N_ + r) * 8);
    o4[0] = make_float4(o[0], o[1], o[2], o[3]);
    o4[1] = make_float4(o[4], o[5], o[6], o[7]);
}

// =====================================================================
// Kernel C1: attention output -> op projection -> s
// =====================================================================
__global__ void __launch_bounds__(256)
proj_kernel(const float* __restrict__ op_w, const float* __restrict__ op_b)
{
    __shared__ float fs[8][32];
    const int tid = threadIdx.x;
    const int blk = blockIdx.x;
    const int b   = blk >> 9;
    const int n0  = (blk & 511) << 3;
    const int w = tid >> 5, lane = tid & 31;
    const int n = n0 + w;
    const int head = lane >> 3, e = lane & 7;

    fs[w][lane] = d_att[((size_t)(b * 4 + head) * N_ + n) * 8 + e];
    __syncwarp();

    float acc = __ldg(op_b + lane);
#pragma unroll
    for (int i = 0; i < 32; i++)
        acc += fs[w][i] * __ldg(op_w + lane * 32 + i);
    d_s[((size_t)b * N_ + n) * 32 + lane] = acc;
}

// =====================================================================
// Kernel C2: dilated convs over node axis + BN + relu + residual LN
//            -> horizon MLP. 32 nodes/block (8 warps x 4 nodes),
//            padded (stride-33) transposed weights: conflict-free STS/LDS.
// =====================================================================
__global__ void __launch_bounds__(256)
tail_kernel(const float* __restrict__ tc0_w, const float* __restrict__ tc0_b,
            const float* __restrict__ tc1_w, const float* __restrict__ tc1_b,
            const float* __restrict__ bn_g, const float* __restrict__ bn_b,
            const float* __restrict__ ln_g, const float* __restrict__ ln_b,
            const float* __restrict__ h1_w, const float* __restrict__ h1_b,
            const float* __restrict__ hln_g, const float* __restrict__ hln_b,
            const float* __restrict__ h2_w, const float* __restrict__ h2_b,
            float* __restrict__ out)
{
    __shared__ float ss[36 * 32];     // s rows n0-2 .. n0+33 (zero-padded)
    __shared__ float tw0[96 * 33];    // [(ci*3+k)*33 + co], pad avoids conflicts
    __shared__ float tw1[96 * 33];

    const int tid = threadIdx.x;
    const int blk = blockIdx.x;
    const int b   = blk >> 7;
    const int n0  = (blk & 127) << 5;

    for (int idx = tid; idx < 3072; idx += 256) {
        int co = idx / 96, rem = idx % 96;
        tw0[rem * 33 + co] = tc0_w[idx];
        tw1[rem * 33 + co] = tc1_w[idx];
    }
    for (int idx = tid; idx < 1152; idx += 256) {
        int rr = idx >> 5, c = idx & 31;
        int gn = n0 - 2 + rr;
        ss[idx] = (gn >= 0 && gn < N_) ? d_s[((size_t)b * N_ + gn) * 32 + c] : 0.f;
    }
    __syncthreads();

    const int w = tid >> 5, lane = tid & 31;
    const float b0 = __ldg(tc0_b + lane), b1 = __ldg(tc1_b + lane);

    float v0[4], v1[4];
#pragma unroll
    for (int t = 0; t < 4; t++) { v0[t] = b0; v1[t] = b1; }

#pragma unroll 8
    for (int ci = 0; ci < 32; ci++) {
        float w00 = tw0[(ci * 3 + 0) * 33 + lane];
        float w01 = tw0[(ci * 3 + 1) * 33 + lane];
        float w02 = tw0[(ci * 3 + 2) * 33 + lane];
        float w10 = tw1[(ci * 3 + 0) * 33 + lane];
        float w11 = tw1[(ci * 3 + 1) * 33 + lane];
        float w12 = tw1[(ci * 3 + 2) * 33 + lane];
#pragma unroll
        for (int t = 0; t < 4; t++) {
            int lr = w * 4 + t + 2;
            float sm2 = ss[(lr - 2) * 32 + ci];
            float sm1 = ss[(lr - 1) * 32 + ci];
            float s0  = ss[lr * 32 + ci];
            float sp1 = ss[(lr + 1) * 32 + ci];
            float sp2 = ss[(lr + 2) * 32 + ci];
            v0[t] += sm1 * w00 + s0 * w01 + sp1 * w02;
            v1[t] += sm2 * w10 + s0 * w11 + sp2 * w12;
        }
    }

    const float bs = __ldg(bn_g + lane) * rsqrtf(1.f + 1e-5f);
    const float bb = __ldg(bn_b + lane);
    const float lng = __ldg(ln_g + lane), lnb = __ldg(ln_b + lane);

#pragma unroll
    for (int t = 0; t < 4; t++) {
        const int lr = w * 4 + t + 2;
        const int n = n0 + w * 4 + t;
        float y0 = fmaxf(v0[t] * bs + bb, 0.f);
        float y1 = fmaxf(v1[t] * bs + bb, 0.f);
        float resid = 0.5f * (y0 + y1) + ss[lr * 32 + lane];

        // layernorm over 32 channels (warp-wide)
        float sum = resid, sq = resid * resid;
#pragma unroll
        for (int off = 16; off; off >>= 1) {
            sum += __shfl_xor_sync(0xffffffffu, sum, off);
            sq  += __shfl_xor_sync(0xffffffffu, sq, off);
        }
        float mu = sum * (1.f / 32.f);
        float var = sq * (1.f / 32.f) - mu * mu;
        float rstd = rsqrtf(var + 1e-5f);
        float tout = (resid - mu) * rstd * lng + lnb;

        // h1: 8 outputs via per-lane partial + butterfly reduce
        float hj[8];
#pragma unroll
        for (int j = 0; j < 8; j++) hj[j] = tout * __ldg(h1_w + j * 32 + lane);
#pragma unroll
        for (int j = 0; j < 8; j++)
#pragma unroll
            for (int off = 16; off; off >>= 1)
                hj[j] += __shfl_xor_sync(0xffffffffu, hj[j], off);

        float hsum = 0.f;
#pragma unroll
        for (int j = 0; j < 8; j++) { hj[j] += __ldg(h1_b + j); hsum += hj[j]; }
        float hmu = hsum * (1.f / 8.f);
        float hsq = 0.f;
#pragma unroll
        for (int j = 0; j < 8; j++) { float dd = hj[j] - hmu; hsq += dd * dd; }
        float hrstd = rsqrtf(hsq * (1.f / 8.f) + 1e-5f);
        float hh[8];
#pragma unroll
        for (int j = 0; j < 8; j++)
            hh[j] = fmaxf((hj[j] - hmu) * hrstd * __ldg(hln_g + j) + __ldg(hln_b + j), 0.f);

        if (lane < HOR_) {
            float p = __ldg(h2_b + lane);
#pragma unroll
            for (int j = 0; j < 8; j++) p += hh[j] * __ldg(h2_w + lane * 8 + j);
            out[(size_t)b * HOR_ * N_ + (size_t)lane * N_ + n] = p;
        }
    }
}

// =====================================================================
extern "C" void kernel_launch(void* const* d_in, const int* in_sizes, int n_in,
                              void* d_out, int out_size)
{
    const float* x      = (const float*)d_in[0];
    const float* fe_w   = (const float*)d_in[1];
    const float* fe_b   = (const float*)d_in[2];
    const float* fe_bng = (const float*)d_in[3];
    const float* fe_bnb = (const float*)d_in[4];
    const float* p1_w   = (const float*)d_in[5];
    const float* p1_b   = (const float*)d_in[6];
    const float* p2_w   = (const float*)d_in[7];
    const float* p2_b   = (const float*)d_in[8];
    const float* qkv_w  = (const float*)d_in[9];
    const float* qkv_b  = (const float*)d_in[10];
    const float* op_w   = (const float*)d_in[11];
    const float* op_b   = (const float*)d_in[12];
    const float* u      = (const float*)d_in[13];
    const float* v      = (const float*)d_in[14];
    const float* tc0_w  = (const float*)d_in[15];
    const float* tc0_b  = (const float*)d_in[16];
    const float* tc1_w  = (const float*)d_in[17];
    const float* tc1_b  = (const float*)d_in[18];
    const float* t_bng  = (const float*)d_in[19];
    const float* t_bnb  = (const float*)d_in[20];
    const float* t_lng  = (const float*)d_in[21];
    const float* t_lnb  = (const float*)d_in[22];
    const float* h1_w   = (const float*)d_in[23];
    const float* h1_b   = (const float*)d_in[24];
    const float* h_lng  = (const float*)d_in[25];
    const float* h_lnb  = (const float*)d_in[26];
    const float* h2_w   = (const float*)d_in[27];
    const float* h2_b   = (const float*)d_in[28];
    float* out = (float*)d_out;

    const int nodeblocks = (B_ * N_) / 8;   // 1024

    feat_kernel<<<nodeblocks, 256>>>(x, fe_w, fe_b, fe_bng, fe_bnb,
                                     p1_w, p1_b, p2_w, p2_b,
                                     qkv_w, qkv_b, u, v);

    dim3 agrid(N_ / 128, BH_);
    attn_kernel<<<agrid, 128>>>();

    proj_kernel<<<nodeblocks, 256>>>(op_w, op_b);

    tail_kernel<<<(B_ * N_) / 32, 256>>>(tc0_w, tc0_b, tc1_w, tc1_b,
                                         t_bng, t_bnb, t_lng, t_lnb,
                                         h1_w, h1_b, h_lng, h_lnb,
                                         h2_w, h2_b, out);
}

// round 3
// speedup vs baseline: 1.2948x; 1.2001x over previous
#include <cuda_runtime.h>
#include <cuda_bf16.h>
#include <math.h>

// ---------------- problem constants ----------------
#define B_    2
#define T_    64
#define N_    4096
#define HOR_  24
#define C_    16
#define HID_  32
#define BD_   8
#define HEADS_ 4
#define HD_   8
#define BH_   (B_*HEADS_)      // 8
#define LOG2E 1.4426950408889634f
#define INV_SQRT8 0.35355339059327373f

#define SPLIT_ 4               // key-axis split for attention
#define QPT_   4               // queries per thread
#define QBLK_  512             // queries per attention block (128 thr * 4)
#define KCH_   (N_/SPLIT_)     // 1024 keys per split

// ---------------- scratch (device globals; no allocation) ----------------
__device__ float d_Qp[BH_ * N_ * 16];
__device__ float d_Kp[BH_ * N_ * 16];
__device__ float d_Vv[BH_ * N_ * 8];
__device__ float d_pl[SPLIT_ * BH_ * N_];        // partial sum of p
__device__ float d_pacc[SPLIT_ * BH_ * N_ * 8];  // partial sum of p*v
__device__ float d_s[B_ * N_ * HID_];

__device__ __forceinline__ float ex2f(float x) {
    float y; asm("ex2.approx.ftz.f32 %0, %1;" : "=f"(y) : "f"(x)); return y;
}
__device__ __forceinline__ float elu1(float x) {
    return x > 0.f ? x + 1.f : __expf(x);
}

// packed fp32x2 helpers
typedef unsigned long long ull;
__device__ __forceinline__ ull ffma2(ull a, ull b, ull c) {
    ull d; asm("fma.rn.f32x2 %0, %1, %2, %3;" : "=l"(d) : "l"(a), "l"(b), "l"(c)); return d;
}
__device__ __forceinline__ ull fadd2(ull a, ull b) {
    ull d; asm("add.rn.f32x2 %0, %1, %2;" : "=l"(d) : "l"(a), "l"(b)); return d;
}
__device__ __forceinline__ ull pk2(float lo, float hi) {
    ull r; asm("mov.b64 %0, {%1, %2};" : "=l"(r) : "f"(lo), "f"(hi)); return r;
}
__device__ __forceinline__ void upk2(ull v, float& lo, float& hi) {
    asm("mov.b64 {%0, %1}, %2;" : "=f"(lo), "=f"(hi) : "l"(v));
}

// =====================================================================
// Kernel A: conv feature extractor -> p1 -> p2 -> qkv -> Q'/K'/V
// =====================================================================
__global__ void __launch_bounds__(256)
feat_kernel(const float* __restrict__ x,
            const float* __restrict__ fe_w, const float* __restrict__ fe_b,
            const float* __restrict__ bn_g, const float* __restrict__ bn_b,
            const float* __restrict__ p1_w, const float* __restrict__ p1_b,
            const float* __restrict__ p2_w, const float* __restrict__ p2_b,
            const float* __restrict__ qkv_w, const float* __restrict__ qkv_b,
            const float* __restrict__ u, const float* __restrict__ v)
{
    __shared__ float p1s[8192];
    __shared__ float xs[8][66];
    __shared__ float fs[8][32];
    __shared__ float cw[48];
    __shared__ float csh[16];

    const int tid = threadIdx.x;
    const int blk = blockIdx.x;
    const int b   = blk >> 9;
    const int n0  = (blk & 511) << 3;

    for (int i = tid; i < 8192; i += 256) p1s[i] = p1_w[i];
    if (tid < 48) {
        int c = tid / 3;
        float sc = bn_g[c] * rsqrtf(1.f + 1e-5f);
        cw[tid] = fe_w[tid] * sc;
    }
    if (tid < 16) {
        float sc = bn_g[tid] * rsqrtf(1.f + 1e-5f);
        csh[tid] = fe_b[tid] * sc + bn_b[tid];
    }
    for (int i = tid; i < 512; i += 256) {
        int node = i & 7, t = i >> 3;
        xs[node][t + 1] = x[(size_t)b * T_ * N_ + (size_t)t * N_ + n0 + node];
    }
    if (tid < 8) { xs[tid][0] = 0.f; xs[tid][65] = 0.f; }
    __syncthreads();

    const int w = tid >> 5, lane = tid & 31;
    const int n = n0 + w;

    float acc[8];
#pragma unroll
    for (int j = 0; j < 8; j++) acc[j] = 0.f;

#pragma unroll
    for (int i = 0; i < 32; i++) {
        int c = i >> 1;
        int t = lane + ((i & 1) << 5);
        float val = xs[w][t] * cw[c * 3] + xs[w][t + 1] * cw[c * 3 + 1]
                  + xs[w][t + 2] * cw[c * 3 + 2] + csh[c];
        val = fmaxf(val, 0.f);
        int base = i * 32 + lane;
#pragma unroll
        for (int j = 0; j < 8; j++) acc[j] += val * p1s[j * 1024 + base];
    }
#pragma unroll
    for (int j = 0; j < 8; j++)
#pragma unroll
        for (int off = 16; off; off >>= 1)
            acc[j] += __shfl_xor_sync(0xffffffffu, acc[j], off);

    float r1[8];
#pragma unroll
    for (int j = 0; j < 8; j++) r1[j] = fmaxf(acc[j] + __ldg(p1_b + j), 0.f);

    float f = __ldg(p2_b + lane);
#pragma unroll
    for (int j = 0; j < 8; j++) f += r1[j] * __ldg(p2_w + lane * 8 + j);
    fs[w][lane] = f;
    __syncwarp();

    float oq = __ldg(qkv_b + lane);
    float ok = __ldg(qkv_b + lane + 32);
    float ov = __ldg(qkv_b + lane + 64);
#pragma unroll
    for (int i = 0; i < 32; i++) {
        float fi = fs[w][i];
        oq += fi * __ldg(qkv_w + lane * 32 + i);
        ok += fi * __ldg(qkv_w + (lane + 32) * 32 + i);
        ov += fi * __ldg(qkv_w + (lane + 64) * 32 + i);
    }

    const int head = lane >> 3, d = lane & 7;
    const size_t ridx = ((size_t)(b * 4 + head) * N_ + n);
    const size_t qidx = ridx * 16;

    d_Qp[qidx + d]     = elu1(oq) * (LOG2E * INV_SQRT8);
    d_Qp[qidx + 8 + d] = u[(size_t)n * 8 + d] * LOG2E;
    d_Kp[qidx + d]     = elu1(ok);
    d_Kp[qidx + 8 + d] = v[(size_t)d * N_ + n];
    d_Vv[ridx * 8 + d] = ov;
}

// =====================================================================
// Kernel B: attention partials. 4 queries/thread, key-split over grid.z
// grid (N/512, BH, SPLIT), 128 threads
// =====================================================================
#define ATT_BN 128
__global__ void __launch_bounds__(128)
attn_kernel()
{
    const int bh = blockIdx.y;
    const int qbase = blockIdx.x * QBLK_;
    const int kz = blockIdx.z;
    const int tid = threadIdx.x;

    const float* Qb = d_Qp + (size_t)bh * N_ * 16;
    const float* Kb = d_Kp + (size_t)bh * N_ * 16;
    const float* Vb = d_Vv + (size_t)bh * N_ * 8;

    __shared__ __align__(16) float Ks[ATT_BN * 16];
    __shared__ __align__(16) float Vs[ATT_BN * 8];

    // load 4 query rows (strided by 128 for coalescing)
    ull q2[QPT_][8];
#pragma unroll
    for (int i = 0; i < QPT_; i++) {
        const ulonglong2* qp = (const ulonglong2*)(Qb + (size_t)(qbase + tid + i * 128) * 16);
#pragma unroll
        for (int c = 0; c < 4; c++) {
            ulonglong2 t = qp[c];
            q2[i][c * 2] = t.x; q2[i][c * 2 + 1] = t.y;
        }
    }

    ull av[QPT_][4];
    float l[QPT_];
#pragma unroll
    for (int i = 0; i < QPT_; i++) {
        l[i] = 0.f;
#pragma unroll
        for (int c = 0; c < 4; c++) av[i][c] = 0ull;
    }

    const int k0 = kz * KCH_;
    for (int kt = k0; kt < k0 + KCH_; kt += ATT_BN) {
        __syncthreads();
        {
            const float4* src = (const float4*)(Kb + (size_t)kt * 16);
            float4* dst = (float4*)Ks;
#pragma unroll
            for (int i = 0; i < 4; i++) dst[tid + i * 128] = src[tid + i * 128];
            const float4* vsrc = (const float4*)(Vb + (size_t)kt * 8);
            float4* vdst = (float4*)Vs;
#pragma unroll
            for (int i = 0; i < 2; i++) vdst[tid + i * 128] = vsrc[tid + i * 128];
        }
        __syncthreads();

#pragma unroll 2
        for (int j = 0; j < ATT_BN; j++) {
            const ulonglong2* kr = (const ulonglong2*)(Ks + j * 16);
            ulonglong2 ka = kr[0], kb2 = kr[1], kc = kr[2], kd = kr[3];
            const ulonglong2* vr = (const ulonglong2*)(Vs + j * 8);
            ulonglong2 va = vr[0], vb = vr[1];

            float p[QPT_];
#pragma unroll
            for (int i = 0; i < QPT_; i++) {
                ull d0 = ffma2(q2[i][0], ka.x, 0ull);
                ull d1 = ffma2(q2[i][1], ka.y, 0ull);
                d0 = ffma2(q2[i][2], kb2.x, d0);
                d1 = ffma2(q2[i][3], kb2.y, d1);
                d0 = ffma2(q2[i][4], kc.x, d0);
                d1 = ffma2(q2[i][5], kc.y, d1);
                d0 = ffma2(q2[i][6], kd.x, d0);
                d1 = ffma2(q2[i][7], kd.y, d1);
                d0 = fadd2(d0, d1);
                float lo, hi; upk2(d0, lo, hi);
                p[i] = ex2f(lo + hi);
            }
#pragma unroll
            for (int i = 0; i < QPT_; i++) {
                l[i] += p[i];
                ull pp = pk2(p[i], p[i]);
                av[i][0] = ffma2(pp, va.x, av[i][0]);
                av[i][1] = ffma2(pp, va.y, av[i][1]);
                av[i][2] = ffma2(pp, vb.x, av[i][2]);
                av[i][3] = ffma2(pp, vb.y, av[i][3]);
            }
        }
    }

    const size_t pbase = ((size_t)kz * BH_ + bh) * N_;
#pragma unroll
    for (int i = 0; i < QPT_; i++) {
        const int r = qbase + tid + i * 128;
        d_pl[pbase + r] = l[i];
        float o[8];
#pragma unroll
        for (int c = 0; c < 4; c++) upk2(av[i][c], o[c * 2], o[c * 2 + 1]);
        float4* o4 = (float4*)(d_pacc + (pbase + r) * 8);
        o4[0] = make_float4(o[0], o[1], o[2], o[3]);
        o4[1] = make_float4(o[4], o[5], o[6], o[7]);
    }
}

// =====================================================================
// Kernel C1: combine partials + op projection -> s
// =====================================================================
__global__ void __launch_bounds__(256)
proj_kernel(const float* __restrict__ op_w, const float* __restrict__ op_b)
{
    __shared__ float fs[8][32];
    const int tid = threadIdx.x;
    const int blk = blockIdx.x;
    const int b   = blk >> 9;
    const int n0  = (blk & 511) << 3;
    const int w = tid >> 5, lane = tid & 31;
    const int n = n0 + w;
    const int head = lane >> 3, e = lane & 7;

    float acc = 0.f, l = 0.f;
#pragma unroll
    for (int s = 0; s < SPLIT_; s++) {
        const size_t idx = ((size_t)s * BH_ + b * 4 + head) * N_ + n;
        acc += d_pacc[idx * 8 + e];
        l   += d_pl[idx];
    }
    fs[w][lane] = acc / l;
    __syncwarp();

    float o = __ldg(op_b + lane);
#pragma unroll
    for (int i = 0; i < 32; i++)
        o += fs[w][i] * __ldg(op_w + lane * 32 + i);
    d_s[((size_t)b * N_ + n) * 32 + lane] = o;
}

// =====================================================================
// Kernel C2: dilated convs + BN + residual LN + horizon MLP
// 16 nodes/block (8 warps x 2 nodes), grid 512
// =====================================================================
__global__ void __launch_bounds__(256)
tail_kernel(const float* __restrict__ tc0_w, const float* __restrict__ tc0_b,
            const float* __restrict__ tc1_w, const float* __restrict__ tc1_b,
            const float* __restrict__ bn_g, const float* __restrict__ bn_b,
            const float* __restrict__ ln_g, const float* __restrict__ ln_b,
            const float* __restrict__ h1_w, const float* __restrict__ h1_b,
            const float* __restrict__ hln_g, const float* __restrict__ hln_b,
            const float* __restrict__ h2_w, const float* __restrict__ h2_b,
            float* __restrict__ out)
{
    __shared__ float ss[20 * 32];     // rows n0-2 .. n0+17
    __shared__ float tw0[96 * 33];
    __shared__ float tw1[96 * 33];

    const int tid = threadIdx.x;
    const int blk = blockIdx.x;
    const int b   = blk >> 8;
    const int n0  = (blk & 255) << 4;

    for (int idx = tid; idx < 3072; idx += 256) {
        int co = idx / 96, rem = idx % 96;
        tw0[rem * 33 + co] = tc0_w[idx];
        tw1[rem * 33 + co] = tc1_w[idx];
    }
    for (int idx = tid; idx < 640; idx += 256) {
        int rr = idx >> 5, c = idx & 31;
        int gn = n0 - 2 + rr;
        ss[idx] = (gn >= 0 && gn < N_) ? d_s[((size_t)b * N_ + gn) * 32 + c] : 0.f;
    }
    __syncthreads();

    const int w = tid >> 5, lane = tid & 31;
    const float b0 = __ldg(tc0_b + lane), b1 = __ldg(tc1_b + lane);

    float v0[2], v1[2];
#pragma unroll
    for (int t = 0; t < 2; t++) { v0[t] = b0; v1[t] = b1; }

#pragma unroll 8
    for (int ci = 0; ci < 32; ci++) {
        float w00 = tw0[(ci * 3 + 0) * 33 + lane];
        float w01 = tw0[(ci * 3 + 1) * 33 + lane];
        float w02 = tw0[(ci * 3 + 2) * 33 + lane];
        float w10 = tw1[(ci * 3 + 0) * 33 + lane];
        float w11 = tw1[(ci * 3 + 1) * 33 + lane];
        float w12 = tw1[(ci * 3 + 2) * 33 + lane];
#pragma unroll
        for (int t = 0; t < 2; t++) {
            int lr = w * 2 + t + 2;
            float sm2 = ss[(lr - 2) * 32 + ci];
            float sm1 = ss[(lr - 1) * 32 + ci];
            float s0  = ss[lr * 32 + ci];
            float sp1 = ss[(lr + 1) * 32 + ci];
            float sp2 = ss[(lr + 2) * 32 + ci];
            v0[t] += sm1 * w00 + s0 * w01 + sp1 * w02;
            v1[t] += sm2 * w10 + s0 * w11 + sp2 * w12;
        }
    }

    const float bs = __ldg(bn_g + lane) * rsqrtf(1.f + 1e-5f);
    const float bb = __ldg(bn_b + lane);
    const float lng = __ldg(ln_g + lane), lnb = __ldg(ln_b + lane);

#pragma unroll
    for (int t = 0; t < 2; t++) {
        const int lr = w * 2 + t + 2;
        const int n = n0 + w * 2 + t;
        float y0 = fmaxf(v0[t] * bs + bb, 0.f);
        float y1 = fmaxf(v1[t] * bs + bb, 0.f);
        float resid = 0.5f * (y0 + y1) + ss[lr * 32 + lane];

        float sum = resid, sq = resid * resid;
#pragma unroll
        for (int off = 16; off; off >>= 1) {
            sum += __shfl_xor_sync(0xffffffffu, sum, off);
            sq  += __shfl_xor_sync(0xffffffffu, sq, off);
        }
        float mu = sum * (1.f / 32.f);
        float var = sq * (1.f / 32.f) - mu * mu;
        float rstd = rsqrtf(var + 1e-5f);
        float tout = (resid - mu) * rstd * lng + lnb;

        float hj[8];
#pragma unroll
        for (int j = 0; j < 8; j++) hj[j] = tout * __ldg(h1_w + j * 32 + lane);
#pragma unroll
        for (int j = 0; j < 8; j++)
#pragma unroll
            for (int off = 16; off; off >>= 1)
                hj[j] += __shfl_xor_sync(0xffffffffu, hj[j], off);

        float hsum = 0.f;
#pragma unroll
        for (int j = 0; j < 8; j++) { hj[j] += __ldg(h1_b + j); hsum += hj[j]; }
        float hmu = hsum * (1.f / 8.f);
        float hsq = 0.f;
#pragma unroll
        for (int j = 0; j < 8; j++) { float dd = hj[j] - hmu; hsq += dd * dd; }
        float hrstd = rsqrtf(hsq * (1.f / 8.f) + 1e-5f);
        float hh[8];
#pragma unroll
        for (int j = 0; j < 8; j++)
            hh[j] = fmaxf((hj[j] - hmu) * hrstd * __ldg(hln_g + j) + __ldg(hln_b + j), 0.f);

        if (lane < HOR_) {
            float p = __ldg(h2_b + lane);
#pragma unroll
            for (int j = 0; j < 8; j++) p += hh[j] * __ldg(h2_w + lane * 8 + j);
            out[(size_t)b * HOR_ * N_ + (size_t)lane * N_ + n] = p;
        }
    }
}

// =====================================================================
extern "C" void kernel_launch(void* const* d_in, const int* in_sizes, int n_in,
                              void* d_out, int out_size)
{
    const float* x      = (const float*)d_in[0];
    const float* fe_w   = (const float*)d_in[1];
    const float* fe_b   = (const float*)d_in[2];
    const float* fe_bng = (const float*)d_in[3];
    const float* fe_bnb = (const float*)d_in[4];
    const float* p1_w   = (const float*)d_in[5];
    const float* p1_b   = (const float*)d_in[6];
    const float* p2_w   = (const float*)d_in[7];
    const float* p2_b   = (const float*)d_in[8];
    const float* qkv_w  = (const float*)d_in[9];
    const float* qkv_b  = (const float*)d_in[10];
    const float* op_w   = (const float*)d_in[11];
    const float* op_b   = (const float*)d_in[12];
    const float* u      = (const float*)d_in[13];
    const float* v      = (const float*)d_in[14];
    const float* tc0_w  = (const float*)d_in[15];
    const float* tc0_b  = (const float*)d_in[16];
    const float* tc1_w  = (const float*)d_in[17];
    const float* tc1_b  = (const float*)d_in[18];
    const float* t_bng  = (const float*)d_in[19];
    const float* t_bnb  = (const float*)d_in[20];
    const float* t_lng  = (const float*)d_in[21];
    const float* t_lnb  = (const float*)d_in[22];
    const float* h1_w   = (const float*)d_in[23];
    const float* h1_b   = (const float*)d_in[24];
    const float* h_lng  = (const float*)d_in[25];
    const float* h_lnb  = (const float*)d_in[26];
    const float* h2_w   = (const float*)d_in[27];
    const float* h2_b   = (const float*)d_in[28];
    float* out = (float*)d_out;

    const int nodeblocks = (B_ * N_) / 8;   // 1024

    feat_kernel<<<nodeblocks, 256>>>(x, fe_w, fe_b, fe_bng, fe_bnb,
                                     p1_w, p1_b, p2_w, p2_b,
                                     qkv_w, qkv_b, u, v);

    dim3 agrid(N_ / QBLK_, BH_, SPLIT_);    // (8, 8, 4) = 256 blocks
    attn_kernel<<<agrid, 128>>>();

    proj_kernel<<<nodeblocks, 256>>>(op_w, op_b);

    tail_kernel<<<(B_ * N_) / 16, 256>>>(tc0_w, tc0_b, tc1_w, tc1_b,
                                         t_bng, t_bnb, t_lng, t_lnb,
                                         h1_w, h1_b, h_lng, h_lnb,
                                         h2_w, h2_b, out);
}

// round 4
// speedup vs baseline: 1.3352x; 1.0312x over previous
#include <cuda_runtime.h>
#include <cuda_bf16.h>
#include <math.h>

// ---------------- problem constants ----------------
#define B_    2
#define T_    64
#define N_    4096
#define HOR_  24
#define C_    16
#define HID_  32
#define BD_   8
#define HEADS_ 4
#define HD_   8
#define BH_   (B_*HEADS_)      // 8
#define LOG2E 1.4426950408889634f
#define INV_SQRT8 0.35355339059327373f

#define SPLIT_ 8               // key-axis split for attention
#define QPT_   4               // queries per thread
#define QBLK_  512             // queries per attention block (128 thr * 4)
#define KCH_   (N_/SPLIT_)     // 512 keys per split

// ---------------- scratch (device globals; no allocation) ----------------
__device__ float d_Qp[BH_ * N_ * 16];
__device__ float d_Kp[BH_ * N_ * 16];
__device__ float d_Vv[BH_ * N_ * 8];
__device__ float d_pl[SPLIT_ * BH_ * N_];        // partial sum of p
__device__ float d_pacc[SPLIT_ * BH_ * N_ * 8];  // partial sum of p*v
__device__ float d_s[B_ * N_ * HID_];

__device__ __forceinline__ float ex2f(float x) {
    float y; asm("ex2.approx.ftz.f32 %0, %1;" : "=f"(y) : "f"(x)); return y;
}
__device__ __forceinline__ float elu1(float x) {
    return x > 0.f ? x + 1.f : __expf(x);
}

// packed fp32x2 helpers
typedef unsigned long long ull;
__device__ __forceinline__ ull ffma2(ull a, ull b, ull c) {
    ull d; asm("fma.rn.f32x2 %0, %1, %2, %3;" : "=l"(d) : "l"(a), "l"(b), "l"(c)); return d;
}
__device__ __forceinline__ ull fadd2(ull a, ull b) {
    ull d; asm("add.rn.f32x2 %0, %1, %2;" : "=l"(d) : "l"(a), "l"(b)); return d;
}
__device__ __forceinline__ ull pk2(float lo, float hi) {
    ull r; asm("mov.b64 %0, {%1, %2};" : "=l"(r) : "f"(lo), "f"(hi)); return r;
}
__device__ __forceinline__ void upk2(ull v, float& lo, float& hi) {
    asm("mov.b64 {%0, %1}, %2;" : "=f"(lo), "=f"(hi) : "l"(v));
}

// =====================================================================
// Kernel A: conv feature extractor -> p1 -> p2 -> qkv -> Q'/K'/V
// =====================================================================
__global__ void __launch_bounds__(256)
feat_kernel(const float* __restrict__ x,
            const float* __restrict__ fe_w, const float* __restrict__ fe_b,
            const float* __restrict__ bn_g, const float* __restrict__ bn_b,
            const float* __restrict__ p1_w, const float* __restrict__ p1_b,
            const float* __restrict__ p2_w, const float* __restrict__ p2_b,
            const float* __restrict__ qkv_w, const float* __restrict__ qkv_b,
            const float* __restrict__ u, const float* __restrict__ v)
{
    __shared__ float p1s[8192];
    __shared__ float xs[8][66];
    __shared__ float fs[8][32];
    __shared__ float cw[48];
    __shared__ float csh[16];

    const int tid = threadIdx.x;
    const int blk = blockIdx.x;
    const int b   = blk >> 9;
    const int n0  = (blk & 511) << 3;

    for (int i = tid; i < 8192; i += 256) p1s[i] = p1_w[i];
    if (tid < 48) {
        int c = tid / 3;
        float sc = bn_g[c] * rsqrtf(1.f + 1e-5f);
        cw[tid] = fe_w[tid] * sc;
    }
    if (tid < 16) {
        float sc = bn_g[tid] * rsqrtf(1.f + 1e-5f);
        csh[tid] = fe_b[tid] * sc + bn_b[tid];
    }
    for (int i = tid; i < 512; i += 256) {
        int node = i & 7, t = i >> 3;
        xs[node][t + 1] = x[(size_t)b * T_ * N_ + (size_t)t * N_ + n0 + node];
    }
    if (tid < 8) { xs[tid][0] = 0.f; xs[tid][65] = 0.f; }
    __syncthreads();

    const int w = tid >> 5, lane = tid & 31;
    const int n = n0 + w;

    float acc[8];
#pragma unroll
    for (int j = 0; j < 8; j++) acc[j] = 0.f;

#pragma unroll
    for (int i = 0; i < 32; i++) {
        int c = i >> 1;
        int t = lane + ((i & 1) << 5);
        float val = xs[w][t] * cw[c * 3] + xs[w][t + 1] * cw[c * 3 + 1]
                  + xs[w][t + 2] * cw[c * 3 + 2] + csh[c];
        val = fmaxf(val, 0.f);
        int base = i * 32 + lane;
#pragma unroll
        for (int j = 0; j < 8; j++) acc[j] += val * p1s[j * 1024 + base];
    }
#pragma unroll
    for (int j = 0; j < 8; j++)
#pragma unroll
        for (int off = 16; off; off >>= 1)
            acc[j] += __shfl_xor_sync(0xffffffffu, acc[j], off);

    float r1[8];
#pragma unroll
    for (int j = 0; j < 8; j++) r1[j] = fmaxf(acc[j] + __ldg(p1_b + j), 0.f);

    float f = __ldg(p2_b + lane);
#pragma unroll
    for (int j = 0; j < 8; j++) f += r1[j] * __ldg(p2_w + lane * 8 + j);
    fs[w][lane] = f;
    __syncwarp();

    float oq = __ldg(qkv_b + lane);
    float ok = __ldg(qkv_b + lane + 32);
    float ov = __ldg(qkv_b + lane + 64);
#pragma unroll
    for (int i = 0; i < 32; i++) {
        float fi = fs[w][i];
        oq += fi * __ldg(qkv_w + lane * 32 + i);
        ok += fi * __ldg(qkv_w + (lane + 32) * 32 + i);
        ov += fi * __ldg(qkv_w + (lane + 64) * 32 + i);
    }

    const int head = lane >> 3, d = lane & 7;
    const size_t ridx = ((size_t)(b * 4 + head) * N_ + n);
    const size_t qidx = ridx * 16;

    d_Qp[qidx + d]     = elu1(oq) * (LOG2E * INV_SQRT8);
    d_Qp[qidx + 8 + d] = u[(size_t)n * 8 + d] * LOG2E;
    d_Kp[qidx + d]     = elu1(ok);
    d_Kp[qidx + 8 + d] = v[(size_t)d * N_ + n];
    d_Vv[ridx * 8 + d] = ov;
}

// =====================================================================
// Kernel B: attention partials. 4 queries/thread, key-split over grid.z
// grid (N/512, BH, SPLIT=8) = 512 blocks, 128 threads
// =====================================================================
#define ATT_BN 128
__global__ void __launch_bounds__(128)
attn_kernel()
{
    const int bh = blockIdx.y;
    const int qbase = blockIdx.x * QBLK_;
    const int kz = blockIdx.z;
    const int tid = threadIdx.x;

    const float* Qb = d_Qp + (size_t)bh * N_ * 16;
    const float* Kb = d_Kp + (size_t)bh * N_ * 16;
    const float* Vb = d_Vv + (size_t)bh * N_ * 8;

    __shared__ __align__(16) float Ks[ATT_BN * 16];
    __shared__ __align__(16) float Vs[ATT_BN * 8];

    // load 4 query rows (strided by 128 for coalescing)
    ull q2[QPT_][8];
#pragma unroll
    for (int i = 0; i < QPT_; i++) {
        const ulonglong2* qp = (const ulonglong2*)(Qb + (size_t)(qbase + tid + i * 128) * 16);
#pragma unroll
        for (int c = 0; c < 4; c++) {
            ulonglong2 t = qp[c];
            q2[i][c * 2] = t.x; q2[i][c * 2 + 1] = t.y;
        }
    }

    ull av[QPT_][4];
    float l[QPT_];
#pragma unroll
    for (int i = 0; i < QPT_; i++) {
        l[i] = 0.f;
#pragma unroll
        for (int c = 0; c < 4; c++) av[i][c] = 0ull;
    }

    const int k0 = kz * KCH_;
    for (int kt = k0; kt < k0 + KCH_; kt += ATT_BN) {
        __syncthreads();
        {
            const float4* src = (const float4*)(Kb + (size_t)kt * 16);
            float4* dst = (float4*)Ks;
#pragma unroll
            for (int i = 0; i < 4; i++) dst[tid + i * 128] = src[tid + i * 128];
            const float4* vsrc = (const float4*)(Vb + (size_t)kt * 8);
            float4* vdst = (float4*)Vs;
#pragma unroll
            for (int i = 0; i < 2; i++) vdst[tid + i * 128] = vsrc[tid + i * 128];
        }
        __syncthreads();

#pragma unroll 2
        for (int j = 0; j < ATT_BN; j++) {
            const ulonglong2* kr = (const ulonglong2*)(Ks + j * 16);
            ulonglong2 ka = kr[0], kb2 = kr[1], kc = kr[2], kd = kr[3];
            const ulonglong2* vr = (const ulonglong2*)(Vs + j * 8);
            ulonglong2 va = vr[0], vb = vr[1];

            float p[QPT_];
#pragma unroll
            for (int i = 0; i < QPT_; i++) {
                ull d0 = ffma2(q2[i][0], ka.x, 0ull);
                ull d1 = ffma2(q2[i][1], ka.y, 0ull);
                d0 = ffma2(q2[i][2], kb2.x, d0);
                d1 = ffma2(q2[i][3], kb2.y, d1);
                d0 = ffma2(q2[i][4], kc.x, d0);
                d1 = ffma2(q2[i][5], kc.y, d1);
                d0 = ffma2(q2[i][6], kd.x, d0);
                d1 = ffma2(q2[i][7], kd.y, d1);
                d0 = fadd2(d0, d1);
                float lo, hi; upk2(d0, lo, hi);
                p[i] = ex2f(lo + hi);
            }
#pragma unroll
            for (int i = 0; i < QPT_; i++) {
                l[i] += p[i];
                ull pp = pk2(p[i], p[i]);
                av[i][0] = ffma2(pp, va.x, av[i][0]);
                av[i][1] = ffma2(pp, va.y, av[i][1]);
                av[i][2] = ffma2(pp, vb.x, av[i][2]);
                av[i][3] = ffma2(pp, vb.y, av[i][3]);
            }
        }
    }

    const size_t pbase = ((size_t)kz * BH_ + bh) * N_;
#pragma unroll
    for (int i = 0; i < QPT_; i++) {
        const int r = qbase + tid + i * 128;
        d_pl[pbase + r] = l[i];
        float o[8];
#pragma unroll
        for (int c = 0; c < 4; c++) upk2(av[i][c], o[c * 2], o[c * 2 + 1]);
        float4* o4 = (float4*)(d_pacc + (pbase + r) * 8);
        o4[0] = make_float4(o[0], o[1], o[2], o[3]);
        o4[1] = make_float4(o[4], o[5], o[6], o[7]);
    }
}

// =====================================================================
// Kernel C1: combine partials + op projection -> s
// =====================================================================
__global__ void __launch_bounds__(256)
proj_kernel(const float* __restrict__ op_w, const float* __restrict__ op_b)
{
    __shared__ float fs[8][32];
    const int tid = threadIdx.x;
    const int blk = blockIdx.x;
    const int b   = blk >> 9;
    const int n0  = (blk & 511) << 3;
    const int w = tid >> 5, lane = tid & 31;
    const int n = n0 + w;
    const int head = lane >> 3, e = lane & 7;

    float acc = 0.f, l = 0.f;
#pragma unroll
    for (int s = 0; s < SPLIT_; s++) {
        const size_t idx = ((size_t)s * BH_ + b * 4 + head) * N_ + n;
        acc += d_pacc[idx * 8 + e];
        l   += d_pl[idx];
    }
    fs[w][lane] = acc / l;
    __syncwarp();

    float o = __ldg(op_b + lane);
#pragma unroll
    for (int i = 0; i < 32; i++)
        o += fs[w][i] * __ldg(op_w + lane * 32 + i);
    d_s[((size_t)b * N_ + n) * 32 + lane] = o;
}

// =====================================================================
// Kernel C2: dilated convs + BN + residual LN + horizon MLP
// 16 nodes/block (8 warps x 2 nodes), grid 512
// =====================================================================
__global__ void __launch_bounds__(256)
tail_kernel(const float* __restrict__ tc0_w, const float* __restrict__ tc0_b,
            const float* __restrict__ tc1_w, const float* __restrict__ tc1_b,
            const float* __restrict__ bn_g, const float* __restrict__ bn_b,
            const float* __restrict__ ln_g, const float* __restrict__ ln_b,
            const float* __restrict__ h1_w, const float* __restrict__ h1_b,
            const float* __restrict__ hln_g, const float* __restrict__ hln_b,
            const float* __restrict__ h2_w, const float* __restrict__ h2_b,
            float* __restrict__ out)
{
    __shared__ float ss[20 * 32];     // rows n0-2 .. n0+17
    __shared__ float tw0[96 * 33];
    __shared__ float tw1[96 * 33];

    const int tid = threadIdx.x;
    const int blk = blockIdx.x;
    const int b   = blk >> 8;
    const int n0  = (blk & 255) << 4;

    for (int idx = tid; idx < 3072; idx += 256) {
        int co = idx / 96, rem = idx % 96;
        tw0[rem * 33 + co] = tc0_w[idx];
        tw1[rem * 33 + co] = tc1_w[idx];
    }
    for (int idx = tid; idx < 640; idx += 256) {
        int rr = idx >> 5, c = idx & 31;
        int gn = n0 - 2 + rr;
        ss[idx] = (gn >= 0 && gn < N_) ? d_s[((size_t)b * N_ + gn) * 32 + c] : 0.f;
    }
    __syncthreads();

    const int w = tid >> 5, lane = tid & 31;
    const float b0 = __ldg(tc0_b + lane), b1 = __ldg(tc1_b + lane);

    float v0[2], v1[2];
#pragma unroll
    for (int t = 0; t < 2; t++) { v0[t] = b0; v1[t] = b1; }

#pragma unroll 8
    for (int ci = 0; ci < 32; ci++) {
        float w00 = tw0[(ci * 3 + 0) * 33 + lane];
        float w01 = tw0[(ci * 3 + 1) * 33 + lane];
        float w02 = tw0[(ci * 3 + 2) * 33 + lane];
        float w10 = tw1[(ci * 3 + 0) * 33 + lane];
        float w11 = tw1[(ci * 3 + 1) * 33 + lane];
        float w12 = tw1[(ci * 3 + 2) * 33 + lane];
#pragma unroll
        for (int t = 0; t < 2; t++) {
            int lr = w * 2 + t + 2;
            float sm2 = ss[(lr - 2) * 32 + ci];
            float sm1 = ss[(lr - 1) * 32 + ci];
            float s0  = ss[lr * 32 + ci];
            float sp1 = ss[(lr + 1) * 32 + ci];
            float sp2 = ss[(lr + 2) * 32 + ci];
            v0[t] += sm1 * w00 + s0 * w01 + sp1 * w02;
            v1[t] += sm2 * w10 + s0 * w11 + sp2 * w12;
        }
    }

    const float bs = __ldg(bn_g + lane) * rsqrtf(1.f + 1e-5f);
    const float bb = __ldg(bn_b + lane);
    const float lng = __ldg(ln_g + lane), lnb = __ldg(ln_b + lane);

#pragma unroll
    for (int t = 0; t < 2; t++) {
        const int lr = w * 2 + t + 2;
        const int n = n0 + w * 2 + t;
        float y0 = fmaxf(v0[t] * bs + bb, 0.f);
        float y1 = fmaxf(v1[t] * bs + bb, 0.f);
        float resid = 0.5f * (y0 + y1) + ss[lr * 32 + lane];

        float sum = resid, sq = resid * resid;
#pragma unroll
        for (int off = 16; off; off >>= 1) {
            sum += __shfl_xor_sync(0xffffffffu, sum, off);
            sq  += __shfl_xor_sync(0xffffffffu, sq, off);
        }
        float mu = sum * (1.f / 32.f);
        float var = sq * (1.f / 32.f) - mu * mu;
        float rstd = rsqrtf(var + 1e-5f);
        float tout = (resid - mu) * rstd * lng + lnb;

        float hj[8];
#pragma unroll
        for (int j = 0; j < 8; j++) hj[j] = tout * __ldg(h1_w + j * 32 + lane);
#pragma unroll
        for (int j = 0; j < 8; j++)
#pragma unroll
            for (int off = 16; off; off >>= 1)
                hj[j] += __shfl_xor_sync(0xffffffffu, hj[j], off);

        float hsum = 0.f;
#pragma unroll
        for (int j = 0; j < 8; j++) { hj[j] += __ldg(h1_b + j); hsum += hj[j]; }
        float hmu = hsum * (1.f / 8.f);
        float hsq = 0.f;
#pragma unroll
        for (int j = 0; j < 8; j++) { float dd = hj[j] - hmu; hsq += dd * dd; }
        float hrstd = rsqrtf(hsq * (1.f / 8.f) + 1e-5f);
        float hh[8];
#pragma unroll
        for (int j = 0; j < 8; j++)
            hh[j] = fmaxf((hj[j] - hmu) * hrstd * __ldg(hln_g + j) + __ldg(hln_b + j), 0.f);

        if (lane < HOR_) {
            float p = __ldg(h2_b + lane);
#pragma unroll
            for (int j = 0; j < 8; j++) p += hh[j] * __ldg(h2_w + lane * 8 + j);
            out[(size_t)b * HOR_ * N_ + (size_t)lane * N_ + n] = p;
        }
    }
}

// =====================================================================
extern "C" void kernel_launch(void* const* d_in, const int* in_sizes, int n_in,
                              void* d_out, int out_size)
{
    const float* x      = (const float*)d_in[0];
    const float* fe_w   = (const float*)d_in[1];
    const float* fe_b   = (const float*)d_in[2];
    const float* fe_bng = (const float*)d_in[3];
    const float* fe_bnb = (const float*)d_in[4];
    const float* p1_w   = (const float*)d_in[5];
    const float* p1_b   = (const float*)d_in[6];
    const float* p2_w   = (const float*)d_in[7];
    const float* p2_b   = (const float*)d_in[8];
    const float* qkv_w  = (const float*)d_in[9];
    const float* qkv_b  = (const float*)d_in[10];
    const float* op_w   = (const float*)d_in[11];
    const float* op_b   = (const float*)d_in[12];
    const float* u      = (const float*)d_in[13];
    const float* v      = (const float*)d_in[14];
    const float* tc0_w  = (const float*)d_in[15];
    const float* tc0_b  = (const float*)d_in[16];
    const float* tc1_w  = (const float*)d_in[17];
    const float* tc1_b  = (const float*)d_in[18];
    const float* t_bng  = (const float*)d_in[19];
    const float* t_bnb  = (const float*)d_in[20];
    const float* t_lng  = (const float*)d_in[21];
    const float* t_lnb  = (const float*)d_in[22];
    const float* h1_w   = (const float*)d_in[23];
    const float* h1_b   = (const float*)d_in[24];
    const float* h_lng  = (const float*)d_in[25];
    const float* h_lnb  = (const float*)d_in[26];
    const float* h2_w   = (const float*)d_in[27];
    const float* h2_b   = (const float*)d_in[28];
    float* out = (float*)d_out;

    const int nodeblocks = (B_ * N_) / 8;   // 1024

    feat_kernel<<<nodeblocks, 256>>>(x, fe_w, fe_b, fe_bng, fe_bnb,
                                     p1_w, p1_b, p2_w, p2_b,
                                     qkv_w, qkv_b, u, v);

    dim3 agrid(N_ / QBLK_, BH_, SPLIT_);    // (8, 8, 8) = 512 blocks
    attn_kernel<<<agrid, 128>>>();

    proj_kernel<<<nodeblocks, 256>>>(op_w, op_b);

    tail_kernel<<<(B_ * N_) / 16, 256>>>(tc0_w, tc0_b, tc1_w, tc1_b,
                                         t_bng, t_bnb, t_lng, t_lnb,
                                         h1_w, h1_b, h_lng, h_lnb,
                                         h2_w, h2_b, out);
}

// round 5
// speedup vs baseline: 1.4926x; 1.1179x over previous
#include <cuda_runtime.h>
#include <cuda_bf16.h>
#include <math.h>

// ---------------- problem constants ----------------
#define B_    2
#define T_    64
#define N_    4096
#define HOR_  24
#define C_    16
#define HID_  32
#define BD_   8
#define HEADS_ 4
#define HD_   8
#define BH_   (B_*HEADS_)      // 8
#define LOG2E 1.4426950408889634f
#define INV_SQRT8 0.35355339059327373f

// ---------------- scratch (device globals; no allocation) ----------------
__device__ __align__(16) __nv_bfloat16 d_Qh[BH_ * N_ * 16];
__device__ __align__(16) __nv_bfloat16 d_Ql[BH_ * N_ * 16];
__device__ __align__(16) __nv_bfloat16 d_Kh[BH_ * N_ * 16];
__device__ __align__(16) __nv_bfloat16 d_Kl[BH_ * N_ * 16];
__device__ __align__(16) __nv_bfloat16 d_Vh[BH_ * N_ * 8];
__device__ __align__(16) __nv_bfloat16 d_Vl[BH_ * N_ * 8];
__device__ float d_att[BH_ * N_ * 8];   // normalized attention output
__device__ float d_s[B_ * N_ * HID_];

__device__ __forceinline__ float ex2f(float x) {
    float y; asm("ex2.approx.ftz.f32 %0, %1;" : "=f"(y) : "f"(x)); return y;
}
__device__ __forceinline__ float elu1(float x) {
    return x > 0.f ? x + 1.f : __expf(x);
}
__device__ __forceinline__ void bsplit(float x, __nv_bfloat16& hi, __nv_bfloat16& lo) {
    __nv_bfloat16 h = __float2bfloat16(x);
    hi = h;
    lo = __float2bfloat16(x - __bfloat162float(h));
}

// bf16 m16n8k16 mma, fp32 accumulate
__device__ __forceinline__ void mma16816(float d[4], const unsigned a[4],
                                         const unsigned b[2], const float c[4]) {
    asm volatile(
        "mma.sync.aligned.m16n8k16.row.col.f32.bf16.bf16.f32 "
        "{%0,%1,%2,%3}, {%4,%5,%6,%7}, {%8,%9}, {%10,%11,%12,%13};"
        : "=f"(d[0]), "=f"(d[1]), "=f"(d[2]), "=f"(d[3])
        : "r"(a[0]), "r"(a[1]), "r"(a[2]), "r"(a[3]),
          "r"(b[0]), "r"(b[1]),
          "f"(c[0]), "f"(c[1]), "f"(c[2]), "f"(c[3]));
}

// pack two fp32 -> bf16x2 hi/lo split (lo 16 bits = first arg)
__device__ __forceinline__ void split2(float x, float y, unsigned& hi, unsigned& lo) {
    __nv_bfloat162 h2 = __floats2bfloat162_rn(x, y);    // .x = x (low half)
    hi = *(unsigned*)&h2;
    __nv_bfloat162 l2 = __floats2bfloat162_rn(x - __bfloat162float(h2.x),
                                              y - __bfloat162float(h2.y));
    lo = *(unsigned*)&l2;
}

// =====================================================================
// Kernel A: conv feature extractor -> p1 -> p2 -> qkv -> split-bf16 Q'/K'/V
// =====================================================================
__global__ void __launch_bounds__(256)
feat_kernel(const float* __restrict__ x,
            const float* __restrict__ fe_w, const float* __restrict__ fe_b,
            const float* __restrict__ bn_g, const float* __restrict__ bn_b,
            const float* __restrict__ p1_w, const float* __restrict__ p1_b,
            const float* __restrict__ p2_w, const float* __restrict__ p2_b,
            const float* __restrict__ qkv_w, const float* __restrict__ qkv_b,
            const float* __restrict__ u, const float* __restrict__ v)
{
    __shared__ float p1s[8192];
    __shared__ float xs[8][66];
    __shared__ float fs[8][32];
    __shared__ float cw[48];
    __shared__ float csh[16];

    const int tid = threadIdx.x;
    const int blk = blockIdx.x;
    const int b   = blk >> 9;
    const int n0  = (blk & 511) << 3;

    for (int i = tid; i < 8192; i += 256) p1s[i] = p1_w[i];
    if (tid < 48) {
        int c = tid / 3;
        float sc = bn_g[c] * rsqrtf(1.f + 1e-5f);
        cw[tid] = fe_w[tid] * sc;
    }
    if (tid < 16) {
        float sc = bn_g[tid] * rsqrtf(1.f + 1e-5f);
        csh[tid] = fe_b[tid] * sc + bn_b[tid];
    }
    for (int i = tid; i < 512; i += 256) {
        int node = i & 7, t = i >> 3;
        xs[node][t + 1] = x[(size_t)b * T_ * N_ + (size_t)t * N_ + n0 + node];
    }
    if (tid < 8) { xs[tid][0] = 0.f; xs[tid][65] = 0.f; }
    __syncthreads();

    const int w = tid >> 5, lane = tid & 31;
    const int n = n0 + w;

    float acc[8];
#pragma unroll
    for (int j = 0; j < 8; j++) acc[j] = 0.f;

#pragma unroll
    for (int i = 0; i < 32; i++) {
        int c = i >> 1;
        int t = lane + ((i & 1) << 5);
        float val = xs[w][t] * cw[c * 3] + xs[w][t + 1] * cw[c * 3 + 1]
                  + xs[w][t + 2] * cw[c * 3 + 2] + csh[c];
        val = fmaxf(val, 0.f);
        int base = i * 32 + lane;
#pragma unroll
        for (int j = 0; j < 8; j++) acc[j] += val * p1s[j * 1024 + base];
    }
#pragma unroll
    for (int j = 0; j < 8; j++)
#pragma unroll
        for (int off = 16; off; off >>= 1)
            acc[j] += __shfl_xor_sync(0xffffffffu, acc[j], off);

    float r1[8];
#pragma unroll
    for (int j = 0; j < 8; j++) r1[j] = fmaxf(acc[j] + __ldg(p1_b + j), 0.f);

    float f = __ldg(p2_b + lane);
#pragma unroll
    for (int j = 0; j < 8; j++) f += r1[j] * __ldg(p2_w + lane * 8 + j);
    fs[w][lane] = f;
    __syncwarp();

    float oq = __ldg(qkv_b + lane);
    float ok = __ldg(qkv_b + lane + 32);
    float ov = __ldg(qkv_b + lane + 64);
#pragma unroll
    for (int i = 0; i < 32; i++) {
        float fi = fs[w][i];
        oq += fi * __ldg(qkv_w + lane * 32 + i);
        ok += fi * __ldg(qkv_w + (lane + 32) * 32 + i);
        ov += fi * __ldg(qkv_w + (lane + 64) * 32 + i);
    }

    const int head = lane >> 3, d = lane & 7;
    const size_t ridx = ((size_t)(b * 4 + head) * N_ + n);
    const size_t qidx = ridx * 16;

    float qv = elu1(oq) * (LOG2E * INV_SQRT8);
    float uv = u[(size_t)n * 8 + d] * LOG2E;
    float kv = elu1(ok);
    float vv = v[(size_t)d * N_ + n];

    bsplit(qv, d_Qh[qidx + d],     d_Ql[qidx + d]);
    bsplit(uv, d_Qh[qidx + 8 + d], d_Ql[qidx + 8 + d]);
    bsplit(kv, d_Kh[qidx + d],     d_Kl[qidx + d]);
    bsplit(vv, d_Kh[qidx + 8 + d], d_Kl[qidx + 8 + d]);
    bsplit(ov, d_Vh[ridx * 8 + d], d_Vl[ridx * 8 + d]);
}

// =====================================================================
// Kernel B: tensor-core flash attention (bf16 split-precision)
// grid (N/64, BH), 128 threads = 4 warps; each warp owns 16 query rows.
// =====================================================================
#define KTILE 64
__global__ void __launch_bounds__(128)
attn_kernel()
{
    const int bh = blockIdx.y;
    const int qbase = blockIdx.x * 64;
    const int tid = threadIdx.x, w = tid >> 5, l = tid & 31;

    // K staged [64 keys][12 uints] (8 used, 12 stride -> conflict-free)
    __shared__ unsigned Kh_s[KTILE * 12], Kl_s[KTILE * 12];
    // V transposed [8 vdim][36 uints] (32 used = 64 keys, 36 stride)
    __shared__ unsigned Vh_s[8 * 36], Vl_s[8 * 36];

    const unsigned* Qh_u = (const unsigned*)d_Qh + (size_t)bh * N_ * 8;
    const unsigned* Ql_u = (const unsigned*)d_Ql + (size_t)bh * N_ * 8;
    const unsigned* Kh_u = (const unsigned*)d_Kh + (size_t)bh * N_ * 8;
    const unsigned* Kl_u = (const unsigned*)d_Kl + (size_t)bh * N_ * 8;
    const __nv_bfloat16* Vh_g = d_Vh + (size_t)bh * N_ * 8;
    const __nv_bfloat16* Vl_g = d_Vl + (size_t)bh * N_ * 8;

    const int qr0 = qbase + w * 16 + (l >> 2);
    const int qr1 = qr0 + 8;
    const int c4 = l & 3;

    unsigned ah[4], al[4];
    ah[0] = Qh_u[qr0 * 8 + c4];     ah[1] = Qh_u[qr1 * 8 + c4];
    ah[2] = Qh_u[qr0 * 8 + c4 + 4]; ah[3] = Qh_u[qr1 * 8 + c4 + 4];
    al[0] = Ql_u[qr0 * 8 + c4];     al[1] = Ql_u[qr1 * 8 + c4];
    al[2] = Ql_u[qr0 * 8 + c4 + 4]; al[3] = Ql_u[qr1 * 8 + c4 + 4];

    float O[4] = {0.f, 0.f, 0.f, 0.f};
    float la = 0.f, lb = 0.f;

    __nv_bfloat16* Vh_sh = (__nv_bfloat16*)Vh_s;
    __nv_bfloat16* Vl_sh = (__nv_bfloat16*)Vl_s;

    for (int kt = 0; kt < N_; kt += KTILE) {
        __syncthreads();
#pragma unroll
        for (int i = 0; i < 4; i++) {
            int idx = tid + i * 128;
            int key = idx >> 3, du = idx & 7;
            Kh_s[key * 12 + du] = Kh_u[(size_t)(kt + key) * 8 + du];
            Kl_s[key * 12 + du] = Kl_u[(size_t)(kt + key) * 8 + du];
        }
#pragma unroll
        for (int i = 0; i < 4; i++) {
            int idx = tid + i * 128;
            int key = idx >> 3, vd = idx & 7;
            Vh_sh[vd * 72 + key] = Vh_g[(size_t)(kt + key) * 8 + vd];
            Vl_sh[vd * 72 + key] = Vl_g[(size_t)(kt + key) * 8 + vd];
        }
        __syncthreads();

#pragma unroll
        for (int c16 = 0; c16 < KTILE; c16 += 16) {
            float S0[4] = {0.f, 0.f, 0.f, 0.f};
            float S1[4] = {0.f, 0.f, 0.f, 0.f};

            const int kr0 = c16 + (l >> 2);
            const int kr1 = kr0 + 8;
            unsigned kh0[2] = {Kh_s[kr0 * 12 + c4], Kh_s[kr0 * 12 + c4 + 4]};
            unsigned kl0[2] = {Kl_s[kr0 * 12 + c4], Kl_s[kr0 * 12 + c4 + 4]};
            unsigned kh1[2] = {Kh_s[kr1 * 12 + c4], Kh_s[kr1 * 12 + c4 + 4]};
            unsigned kl1[2] = {Kl_s[kr1 * 12 + c4], Kl_s[kr1 * 12 + c4 + 4]};

            mma16816(S0, ah, kh0, S0);
            mma16816(S0, al, kh0, S0);
            mma16816(S0, ah, kl0, S0);
            mma16816(S1, ah, kh1, S1);
            mma16816(S1, al, kh1, S1);
            mma16816(S1, ah, kl1, S1);

            float p00 = ex2f(S0[0]), p01 = ex2f(S0[1]);
            float p02 = ex2f(S0[2]), p03 = ex2f(S0[3]);
            float p10 = ex2f(S1[0]), p11 = ex2f(S1[1]);
            float p12 = ex2f(S1[2]), p13 = ex2f(S1[3]);
            la += p00 + p01 + p10 + p11;
            lb += p02 + p03 + p12 + p13;

            unsigned pa_h[4], pa_l[4];
            split2(p00, p01, pa_h[0], pa_l[0]);
            split2(p02, p03, pa_h[1], pa_l[1]);
            split2(p10, p11, pa_h[2], pa_l[2]);
            split2(p12, p13, pa_h[3], pa_l[3]);

            const int vbase = (l >> 2) * 36 + (c16 >> 1) + c4;
            unsigned vh[2] = {Vh_s[vbase], Vh_s[vbase + 4]};
            unsigned vl[2] = {Vl_s[vbase], Vl_s[vbase + 4]};

            mma16816(O, pa_h, vh, O);
            mma16816(O, pa_l, vh, O);
            mma16816(O, pa_h, vl, O);
        }
    }

    la += __shfl_xor_sync(0xffffffffu, la, 1);
    la += __shfl_xor_sync(0xffffffffu, la, 2);
    lb += __shfl_xor_sync(0xffffffffu, lb, 1);
    lb += __shfl_xor_sync(0xffffffffu, lb, 2);

    float inva = 1.f / la, invb = 1.f / lb;
    float* o0 = d_att + ((size_t)bh * N_ + qr0) * 8 + 2 * c4;
    float* o1 = d_att + ((size_t)bh * N_ + qr1) * 8 + 2 * c4;
    o0[0] = O[0] * inva; o0[1] = O[1] * inva;
    o1[0] = O[2] * invb; o1[1] = O[3] * invb;
}

// =====================================================================
// Kernel C1: attention output -> op projection -> s
// =====================================================================
__global__ void __launch_bounds__(256)
proj_kernel(const float* __restrict__ op_w, const float* __restrict__ op_b)
{
    __shared__ float fs[8][32];
    const int tid = threadIdx.x;
    const int blk = blockIdx.x;
    const int b   = blk >> 9;
    const int n0  = (blk & 511) << 3;
    const int w = tid >> 5, lane = tid & 31;
    const int n = n0 + w;
    const int head = lane >> 3, e = lane & 7;

    fs[w][lane] = d_att[((size_t)(b * 4 + head) * N_ + n) * 8 + e];
    __syncwarp();

    float o = __ldg(op_b + lane);
#pragma unroll
    for (int i = 0; i < 32; i++)
        o += fs[w][i] * __ldg(op_w + lane * 32 + i);
    d_s[((size_t)b * N_ + n) * 32 + lane] = o;
}

// =====================================================================
// Kernel C2: dilated convs + BN + residual LN + horizon MLP
// =====================================================================
__global__ void __launch_bounds__(256)
tail_kernel(const float* __restrict__ tc0_w, const float* __restrict__ tc0_b,
            const float* __restrict__ tc1_w, const float* __restrict__ tc1_b,
            const float* __restrict__ bn_g, const float* __restrict__ bn_b,
            const float* __restrict__ ln_g, const float* __restrict__ ln_b,
            const float* __restrict__ h1_w, const float* __restrict__ h1_b,
            const float* __restrict__ hln_g, const float* __restrict__ hln_b,
            const float* __restrict__ h2_w, const float* __restrict__ h2_b,
            float* __restrict__ out)
{
    __shared__ float ss[20 * 32];
    __shared__ float tw0[96 * 33];
    __shared__ float tw1[96 * 33];

    const int tid = threadIdx.x;
    const int blk = blockIdx.x;
    const int b   = blk >> 8;
    const int n0  = (blk & 255) << 4;

    for (int idx = tid; idx < 3072; idx += 256) {
        int co = idx / 96, rem = idx % 96;
        tw0[rem * 33 + co] = tc0_w[idx];
        tw1[rem * 33 + co] = tc1_w[idx];
    }
    for (int idx = tid; idx < 640; idx += 256) {
        int rr = idx >> 5, c = idx & 31;
        int gn = n0 - 2 + rr;
        ss[idx] = (gn >= 0 && gn < N_) ? d_s[((size_t)b * N_ + gn) * 32 + c] : 0.f;
    }
    __syncthreads();

    const int w = tid >> 5, lane = tid & 31;
    const float b0 = __ldg(tc0_b + lane), b1 = __ldg(tc1_b + lane);

    float v0[2], v1[2];
#pragma unroll
    for (int t = 0; t < 2; t++) { v0[t] = b0; v1[t] = b1; }

#pragma unroll 8
    for (int ci = 0; ci < 32; ci++) {
        float w00 = tw0[(ci * 3 + 0) * 33 + lane];
        float w01 = tw0[(ci * 3 + 1) * 33 + lane];
        float w02 = tw0[(ci * 3 + 2) * 33 + lane];
        float w10 = tw1[(ci * 3 + 0) * 33 + lane];
        float w11 = tw1[(ci * 3 + 1) * 33 + lane];
        float w12 = tw1[(ci * 3 + 2) * 33 + lane];
#pragma unroll
        for (int t = 0; t < 2; t++) {
            int lr = w * 2 + t + 2;
            float sm2 = ss[(lr - 2) * 32 + ci];
            float sm1 = ss[(lr - 1) * 32 + ci];
            float s0  = ss[lr * 32 + ci];
            float sp1 = ss[(lr + 1) * 32 + ci];
            float sp2 = ss[(lr + 2) * 32 + ci];
            v0[t] += sm1 * w00 + s0 * w01 + sp1 * w02;
            v1[t] += sm2 * w10 + s0 * w11 + sp2 * w12;
        }
    }

    const float bs = __ldg(bn_g + lane) * rsqrtf(1.f + 1e-5f);
    const float bb = __ldg(bn_b + lane);
    const float lng = __ldg(ln_g + lane), lnb = __ldg(ln_b + lane);

#pragma unroll
    for (int t = 0; t < 2; t++) {
        const int lr = w * 2 + t + 2;
        const int n = n0 + w * 2 + t;
        float y0 = fmaxf(v0[t] * bs + bb, 0.f);
        float y1 = fmaxf(v1[t] * bs + bb, 0.f);
        float resid = 0.5f * (y0 + y1) + ss[lr * 32 + lane];

        float sum = resid, sq = resid * resid;
#pragma unroll
        for (int off = 16; off; off >>= 1) {
            sum += __shfl_xor_sync(0xffffffffu, sum, off);
            sq  += __shfl_xor_sync(0xffffffffu, sq, off);
        }
        float mu = sum * (1.f / 32.f);
        float var = sq * (1.f / 32.f) - mu * mu;
        float rstd = rsqrtf(var + 1e-5f);
        float tout = (resid - mu) * rstd * lng + lnb;

        float hj[8];
#pragma unroll
        for (int j = 0; j < 8; j++) hj[j] = tout * __ldg(h1_w + j * 32 + lane);
#pragma unroll
        for (int j = 0; j < 8; j++)
#pragma unroll
            for (int off = 16; off; off >>= 1)
                hj[j] += __shfl_xor_sync(0xffffffffu, hj[j], off);

        float hsum = 0.f;
#pragma unroll
        for (int j = 0; j < 8; j++) { hj[j] += __ldg(h1_b + j); hsum += hj[j]; }
        float hmu = hsum * (1.f / 8.f);
        float hsq = 0.f;
#pragma unroll
        for (int j = 0; j < 8; j++) { float dd = hj[j] - hmu; hsq += dd * dd; }
        float hrstd = rsqrtf(hsq * (1.f / 8.f) + 1e-5f);
        float hh[8];
#pragma unroll
        for (int j = 0; j < 8; j++)
            hh[j] = fmaxf((hj[j] - hmu) * hrstd * __ldg(hln_g + j) + __ldg(hln_b + j), 0.f);

        if (lane < HOR_) {
            float p = __ldg(h2_b + lane);
#pragma unroll
            for (int j = 0; j < 8; j++) p += hh[j] * __ldg(h2_w + lane * 8 + j);
            out[(size_t)b * HOR_ * N_ + (size_t)lane * N_ + n] = p;
        }
    }
}

// =====================================================================
extern "C" void kernel_launch(void* const* d_in, const int* in_sizes, int n_in,
                              void* d_out, int out_size)
{
    const float* x      = (const float*)d_in[0];
    const float* fe_w   = (const float*)d_in[1];
    const float* fe_b   = (const float*)d_in[2];
    const float* fe_bng = (const float*)d_in[3];
    const float* fe_bnb = (const float*)d_in[4];
    const float* p1_w   = (const float*)d_in[5];
    const float* p1_b   = (const float*)d_in[6];
    const float* p2_w   = (const float*)d_in[7];
    const float* p2_b   = (const float*)d_in[8];
    const float* qkv_w  = (const float*)d_in[9];
    const float* qkv_b  = (const float*)d_in[10];
    const float* op_w   = (const float*)d_in[11];
    const float* op_b   = (const float*)d_in[12];
    const float* u      = (const float*)d_in[13];
    const float* v      = (const float*)d_in[14];
    const float* tc0_w  = (const float*)d_in[15];
    const float* tc0_b  = (const float*)d_in[16];
    const float* tc1_w  = (const float*)d_in[17];
    const float* tc1_b  = (const float*)d_in[18];
    const float* t_bng  = (const float*)d_in[19];
    const float* t_bnb  = (const float*)d_in[20];
    const float* t_lng  = (const float*)d_in[21];
    const float* t_lnb  = (const float*)d_in[22];
    const float* h1_w   = (const float*)d_in[23];
    const float* h1_b   = (const float*)d_in[24];
    const float* h_lng  = (const float*)d_in[25];
    const float* h_lnb  = (const float*)d_in[26];
    const float* h2_w   = (const float*)d_in[27];
    const float* h2_b   = (const float*)d_in[28];
    float* out = (float*)d_out;

    const int nodeblocks = (B_ * N_) / 8;   // 1024

    feat_kernel<<<nodeblocks, 256>>>(x, fe_w, fe_b, fe_bng, fe_bnb,
                                     p1_w, p1_b, p2_w, p2_b,
                                     qkv_w, qkv_b, u, v);

    dim3 agrid(N_ / 64, BH_);               // (64, 8) = 512 blocks
    attn_kernel<<<agrid, 128>>>();

    proj_kernel<<<nodeblocks, 256>>>(op_w, op_b);

    tail_kernel<<<(B_ * N_) / 16, 256>>>(tc0_w, tc0_b, tc1_w, tc1_b,
                                         t_bng, t_bnb, t_lng, t_lnb,
                                         h1_w, h1_b, h_lng, h_lnb,
                                         h2_w, h2_b, out);
}

// round 7
// speedup vs baseline: 2.5133x; 1.6839x over previous
#include <cuda_runtime.h>
#include <cuda_bf16.h>
#include <math.h>

// ---------------- problem constants ----------------
#define B_    2
#define T_    64
#define N_    4096
#define HOR_  24
#define C_    16
#define HID_  32
#define BD_   8
#define HEADS_ 4
#define HD_   8
#define BH_   (B_*HEADS_)      // 8
#define LOG2E 1.4426950408889634f
#define INV_SQRT8 0.35355339059327373f

// ---------------- scratch (device globals; no allocation) ----------------
__device__ __align__(16) __nv_bfloat16 d_Qh[BH_ * N_ * 16];
__device__ __align__(16) __nv_bfloat16 d_Ql[BH_ * N_ * 16];
__device__ __align__(16) __nv_bfloat16 d_Kh[BH_ * N_ * 16];
__device__ __align__(16) __nv_bfloat16 d_Kl[BH_ * N_ * 16];
__device__ __align__(16) __nv_bfloat16 d_Vh[BH_ * N_ * 8];
__device__ __align__(16) __nv_bfloat16 d_Vl[BH_ * N_ * 8];
__device__ float d_att[BH_ * N_ * 8];   // normalized attention output
__device__ float d_s[B_ * N_ * HID_];

__device__ __forceinline__ float ex2f(float x) {
    float y; asm("ex2.approx.ftz.f32 %0, %1;" : "=f"(y) : "f"(x)); return y;
}
__device__ __forceinline__ float elu1(float x) {
    return x > 0.f ? x + 1.f : __expf(x);
}
__device__ __forceinline__ void bsplit(float x, __nv_bfloat16& hi, __nv_bfloat16& lo) {
    __nv_bfloat16 h = __float2bfloat16(x);
    hi = h;
    lo = __float2bfloat16(x - __bfloat162float(h));
}

// bf16 m16n8k16 mma, fp32 accumulate
__device__ __forceinline__ void mma16816(float d[4], const unsigned a[4],
                                         const unsigned b[2], const float c[4]) {
    asm volatile(
        "mma.sync.aligned.m16n8k16.row.col.f32.bf16.bf16.f32 "
        "{%0,%1,%2,%3}, {%4,%5,%6,%7}, {%8,%9}, {%10,%11,%12,%13};"
        : "=f"(d[0]), "=f"(d[1]), "=f"(d[2]), "=f"(d[3])
        : "r"(a[0]), "r"(a[1]), "r"(a[2]), "r"(a[3]),
          "r"(b[0]), "r"(b[1]),
          "f"(c[0]), "f"(c[1]), "f"(c[2]), "f"(c[3]));
}

// pack two fp32 -> bf16x2 hi/lo split
__device__ __forceinline__ void split2(float x, float y, unsigned& hi, unsigned& lo) {
    __nv_bfloat162 h2 = __floats2bfloat162_rn(x, y);
    hi = *(unsigned*)&h2;
    __nv_bfloat162 l2 = __floats2bfloat162_rn(x - __bfloat162float(h2.x),
                                              y - __bfloat162float(h2.y));
    lo = *(unsigned*)&l2;
}

// =====================================================================
// Kernel A: conv feature extractor -> p1 -> p2 -> qkv -> split-bf16 Q'/K'/V
// qkv_w staged in smem (transposed, stride-97) to kill L1tex wavefront storm
// =====================================================================
__global__ void __launch_bounds__(256)
feat_kernel(const float* __restrict__ x,
            const float* __restrict__ fe_w, const float* __restrict__ fe_b,
            const float* __restrict__ bn_g, const float* __restrict__ bn_b,
            const float* __restrict__ p1_w, const float* __restrict__ p1_b,
            const float* __restrict__ p2_w, const float* __restrict__ p2_b,
            const float* __restrict__ qkv_w, const float* __restrict__ qkv_b,
            const float* __restrict__ u, const float* __restrict__ v)
{
    __shared__ float p1s[8192];          // 32768 B
    __shared__ float xs[8][66];          //  2112 B
    __shared__ float fs[8][32];          //  1024 B
    __shared__ float cw[48];             //   192 B
    __shared__ float csh[16];            //    64 B
    __shared__ float wt[32 * 97];        // 12416 B  qkv_w transposed: wt[i*97+o]
    // total 48576 B < 49152

    const int tid = threadIdx.x;
    const int blk = blockIdx.x;
    const int b   = blk >> 9;
    const int n0  = (blk & 511) << 3;

    for (int i = tid; i < 8192; i += 256) p1s[i] = p1_w[i];
    // qkv_w [96 out][32 in] -> wt[i*97+o]; gmem read coalesced,
    // STS bank = (i*97+o)%32 = (i+o)%32 distinct per lane -> conflict-free
    for (int idx = tid; idx < 3072; idx += 256) {
        int o = idx >> 5, i = idx & 31;
        wt[i * 97 + o] = qkv_w[idx];
    }
    if (tid < 48) {
        int c = tid / 3;
        float sc = bn_g[c] * rsqrtf(1.f + 1e-5f);
        cw[tid] = fe_w[tid] * sc;
    }
    if (tid < 16) {
        float sc = bn_g[tid] * rsqrtf(1.f + 1e-5f);
        csh[tid] = fe_b[tid] * sc + bn_b[tid];
    }
    for (int i = tid; i < 512; i += 256) {
        int node = i & 7, t = i >> 3;
        xs[node][t + 1] = x[(size_t)b * T_ * N_ + (size_t)t * N_ + n0 + node];
    }
    if (tid < 8) { xs[tid][0] = 0.f; xs[tid][65] = 0.f; }
    __syncthreads();

    const int w = tid >> 5, lane = tid & 31;
    const int n = n0 + w;

    float acc[8];
#pragma unroll
    for (int j = 0; j < 8; j++) acc[j] = 0.f;

#pragma unroll
    for (int i = 0; i < 32; i++) {
        int c = i >> 1;
        int t = lane + ((i & 1) << 5);
        float val = xs[w][t] * cw[c * 3] + xs[w][t + 1] * cw[c * 3 + 1]
                  + xs[w][t + 2] * cw[c * 3 + 2] + csh[c];
        val = fmaxf(val, 0.f);
        int base = i * 32 + lane;
#pragma unroll
        for (int j = 0; j < 8; j++) acc[j] += val * p1s[j * 1024 + base];
    }
#pragma unroll
    for (int j = 0; j < 8; j++)
#pragma unroll
        for (int off = 16; off; off >>= 1)
            acc[j] += __shfl_xor_sync(0xffffffffu, acc[j], off);

    float r1[8];
#pragma unroll
    for (int j = 0; j < 8; j++) r1[j] = fmaxf(acc[j] + __ldg(p1_b + j), 0.f);

    float f = __ldg(p2_b + lane);
#pragma unroll
    for (int j = 0; j < 8; j++) f += r1[j] * __ldg(p2_w + lane * 8 + j);
    fs[w][lane] = f;
    __syncwarp();

    float oq = __ldg(qkv_b + lane);
    float ok = __ldg(qkv_b + lane + 32);
    float ov = __ldg(qkv_b + lane + 64);
#pragma unroll
    for (int i = 0; i < 32; i++) {
        float fi = fs[w][i];
        const float* wr = wt + i * 97;
        oq += fi * wr[lane];
        ok += fi * wr[lane + 32];
        ov += fi * wr[lane + 64];
    }

    const int head = lane >> 3, d = lane & 7;
    const size_t ridx = ((size_t)(b * 4 + head) * N_ + n);
    const size_t qidx = ridx * 16;

    float qv = elu1(oq) * (LOG2E * INV_SQRT8);
    float uv = u[(size_t)n * 8 + d] * LOG2E;
    float kv = elu1(ok);
    float vv = v[(size_t)d * N_ + n];

    bsplit(qv, d_Qh[qidx + d],     d_Ql[qidx + d]);
    bsplit(uv, d_Qh[qidx + 8 + d], d_Ql[qidx + 8 + d]);
    bsplit(kv, d_Kh[qidx + d],     d_Kl[qidx + d]);
    bsplit(vv, d_Kh[qidx + 8 + d], d_Kl[qidx + 8 + d]);
    bsplit(ov, d_Vh[ridx * 8 + d], d_Vl[ridx * 8 + d]);
}

// =====================================================================
// Kernel B: tensor-core flash attention (bf16 split-precision)
// grid (N/64, BH), 128 threads = 4 warps; each warp owns 16 query rows.
// =====================================================================
#define KTILE 64
__global__ void __launch_bounds__(128)
attn_kernel()
{
    const int bh = blockIdx.y;
    const int qbase = blockIdx.x * 64;
    const int tid = threadIdx.x, w = tid >> 5, l = tid & 31;

    __shared__ unsigned Kh_s[KTILE * 12], Kl_s[KTILE * 12];
    __shared__ unsigned Vh_s[8 * 36], Vl_s[8 * 36];

    const unsigned* Qh_u = (const unsigned*)d_Qh + (size_t)bh * N_ * 8;
    const unsigned* Ql_u = (const unsigned*)d_Ql + (size_t)bh * N_ * 8;
    const unsigned* Kh_u = (const unsigned*)d_Kh + (size_t)bh * N_ * 8;
    const unsigned* Kl_u = (const unsigned*)d_Kl + (size_t)bh * N_ * 8;
    const __nv_bfloat16* Vh_g = d_Vh + (size_t)bh * N_ * 8;
    const __nv_bfloat16* Vl_g = d_Vl + (size_t)bh * N_ * 8;

    const int qr0 = qbase + w * 16 + (l >> 2);
    const int qr1 = qr0 + 8;
    const int c4 = l & 3;

    unsigned ah[4], al[4];
    ah[0] = Qh_u[qr0 * 8 + c4];     ah[1] = Qh_u[qr1 * 8 + c4];
    ah[2] = Qh_u[qr0 * 8 + c4 + 4]; ah[3] = Qh_u[qr1 * 8 + c4 + 4];
    al[0] = Ql_u[qr0 * 8 + c4];     al[1] = Ql_u[qr1 * 8 + c4];
    al[2] = Ql_u[qr0 * 8 + c4 + 4]; al[3] = Ql_u[qr1 * 8 + c4 + 4];

    float O[4] = {0.f, 0.f, 0.f, 0.f};
    float la = 0.f, lb = 0.f;

    __nv_bfloat16* Vh_sh = (__nv_bfloat16*)Vh_s;
    __nv_bfloat16* Vl_sh = (__nv_bfloat16*)Vl_s;

    for (int kt = 0; kt < N_; kt += KTILE) {
        __syncthreads();
#pragma unroll
        for (int i = 0; i < 4; i++) {
            int idx = tid + i * 128;
            int key = idx >> 3, du = idx & 7;
            Kh_s[key * 12 + du] = Kh_u[(size_t)(kt + key) * 8 + du];
            Kl_s[key * 12 + du] = Kl_u[(size_t)(kt + key) * 8 + du];
        }
#pragma unroll
        for (int i = 0; i < 4; i++) {
            int idx = tid + i * 128;
            int key = idx >> 3, vd = idx & 7;
            Vh_sh[vd * 72 + key] = Vh_g[(size_t)(kt + key) * 8 + vd];
            Vl_sh[vd * 72 + key] = Vl_g[(size_t)(kt + key) * 8 + vd];
        }
        __syncthreads();

#pragma unroll
        for (int c16 = 0; c16 < KTILE; c16 += 16) {
            float S0[4] = {0.f, 0.f, 0.f, 0.f};
            float S1[4] = {0.f, 0.f, 0.f, 0.f};

            const int kr0 = c16 + (l >> 2);
            const int kr1 = kr0 + 8;
            unsigned kh0[2] = {Kh_s[kr0 * 12 + c4], Kh_s[kr0 * 12 + c4 + 4]};
            unsigned kl0[2] = {Kl_s[kr0 * 12 + c4], Kl_s[kr0 * 12 + c4 + 4]};
            unsigned kh1[2] = {Kh_s[kr1 * 12 + c4], Kh_s[kr1 * 12 + c4 + 4]};
            unsigned kl1[2] = {Kl_s[kr1 * 12 + c4], Kl_s[kr1 * 12 + c4 + 4]};

            mma16816(S0, ah, kh0, S0);
            mma16816(S0, al, kh0, S0);
            mma16816(S0, ah, kl0, S0);
            mma16816(S1, ah, kh1, S1);
            mma16816(S1, al, kh1, S1);
            mma16816(S1, ah, kl1, S1);

            float p00 = ex2f(S0[0]), p01 = ex2f(S0[1]);
            float p02 = ex2f(S0[2]), p03 = ex2f(S0[3]);
            float p10 = ex2f(S1[0]), p11 = ex2f(S1[1]);
            float p12 = ex2f(S1[2]), p13 = ex2f(S1[3]);
            la += p00 + p01 + p10 + p11;
            lb += p02 + p03 + p12 + p13;

            unsigned pa_h[4], pa_l[4];
            split2(p00, p01, pa_h[0], pa_l[0]);
            split2(p02, p03, pa_h[1], pa_l[1]);
            split2(p10, p11, pa_h[2], pa_l[2]);
            split2(p12, p13, pa_h[3], pa_l[3]);

            const int vbase = (l >> 2) * 36 + (c16 >> 1) + c4;
            unsigned vh[2] = {Vh_s[vbase], Vh_s[vbase + 4]};
            unsigned vl[2] = {Vl_s[vbase], Vl_s[vbase + 4]};

            mma16816(O, pa_h, vh, O);
            mma16816(O, pa_l, vh, O);
            mma16816(O, pa_h, vl, O);
        }
    }

    la += __shfl_xor_sync(0xffffffffu, la, 1);
    la += __shfl_xor_sync(0xffffffffu, la, 2);
    lb += __shfl_xor_sync(0xffffffffu, lb, 1);
    lb += __shfl_xor_sync(0xffffffffu, lb, 2);

    float inva = 1.f / la, invb = 1.f / lb;
    float* o0 = d_att + ((size_t)bh * N_ + qr0) * 8 + 2 * c4;
    float* o1 = d_att + ((size_t)bh * N_ + qr1) * 8 + 2 * c4;
    o0[0] = O[0] * inva; o0[1] = O[1] * inva;
    o1[0] = O[2] * invb; o1[1] = O[3] * invb;
}

// =====================================================================
// Kernel C1: attention output -> op projection -> s (op_w staged in smem)
// =====================================================================
__global__ void __launch_bounds__(256)
proj_kernel(const float* __restrict__ op_w, const float* __restrict__ op_b)
{
    __shared__ float fs[8][32];
    __shared__ float ow[32 * 33];        // op_w transposed: ow[i*33+o]

    const int tid = threadIdx.x;
    const int blk = blockIdx.x;
    const int b   = blk >> 9;
    const int n0  = (blk & 511) << 3;
    const int w = tid >> 5, lane = tid & 31;
    const int n = n0 + w;
    const int head = lane >> 3, e = lane & 7;

    for (int idx = tid; idx < 1024; idx += 256) {
        int o = idx >> 5, i = idx & 31;
        ow[i * 33 + o] = op_w[idx];
    }
    fs[w][lane] = d_att[((size_t)(b * 4 + head) * N_ + n) * 8 + e];
    __syncthreads();

    float o = __ldg(op_b + lane);
#pragma unroll
    for (int i = 0; i < 32; i++)
        o += fs[w][i] * ow[i * 33 + lane];
    d_s[((size_t)b * N_ + n) * 32 + lane] = o;
}

// =====================================================================
// Kernel C2: dilated convs + BN + residual LN + horizon MLP
// =====================================================================
__global__ void __launch_bounds__(256)
tail_kernel(const float* __restrict__ tc0_w, const float* __restrict__ tc0_b,
            const float* __restrict__ tc1_w, const float* __restrict__ tc1_b,
            const float* __restrict__ bn_g, const float* __restrict__ bn_b,
            const float* __restrict__ ln_g, const float* __restrict__ ln_b,
            const float* __restrict__ h1_w, const float* __restrict__ h1_b,
            const float* __restrict__ hln_g, const float* __restrict__ hln_b,
            const float* __restrict__ h2_w, const float* __restrict__ h2_b,
            float* __restrict__ out)
{
    __shared__ float ss[20 * 32];
    __shared__ float tw0[96 * 33];
    __shared__ float tw1[96 * 33];

    const int tid = threadIdx.x;
    const int blk = blockIdx.x;
    const int b   = blk >> 8;
    const int n0  = (blk & 255) << 4;

    for (int idx = tid; idx < 3072; idx += 256) {
        int co = idx / 96, rem = idx % 96;
        tw0[rem * 33 + co] = tc0_w[idx];
        tw1[rem * 33 + co] = tc1_w[idx];
    }
    for (int idx = tid; idx < 640; idx += 256) {
        int rr = idx >> 5, c = idx & 31;
        int gn = n0 - 2 + rr;
        ss[idx] = (gn >= 0 && gn < N_) ? d_s[((size_t)b * N_ + gn) * 32 + c] : 0.f;
    }
    __syncthreads();

    const int w = tid >> 5, lane = tid & 31;
    const float b0 = __ldg(tc0_b + lane), b1 = __ldg(tc1_b + lane);

    float v0[2], v1[2];
#pragma unroll
    for (int t = 0; t < 2; t++) { v0[t] = b0; v1[t] = b1; }

#pragma unroll 8
    for (int ci = 0; ci < 32; ci++) {
        float w00 = tw0[(ci * 3 + 0) * 33 + lane];
        float w01 = tw0[(ci * 3 + 1) * 33 + lane];
        float w02 = tw0[(ci * 3 + 2) * 33 + lane];
        float w10 = tw1[(ci * 3 + 0) * 33 + lane];
        float w11 = tw1[(ci * 3 + 1) * 33 + lane];
        float w12 = tw1[(ci * 3 + 2) * 33 + lane];
#pragma unroll
        for (int t = 0; t < 2; t++) {
            int lr = w * 2 + t + 2;
            float sm2 = ss[(lr - 2) * 32 + ci];
            float sm1 = ss[(lr - 1) * 32 + ci];
            float s0  = ss[lr * 32 + ci];
            float sp1 = ss[(lr + 1) * 32 + ci];
            float sp2 = ss[(lr + 2) * 32 + ci];
            v0[t] += sm1 * w00 + s0 * w01 + sp1 * w02;
            v1[t] += sm2 * w10 + s0 * w11 + sp2 * w12;
        }
    }

    const float bs = __ldg(bn_g + lane) * rsqrtf(1.f + 1e-5f);
    const float bb = __ldg(bn_b + lane);
    const float lng = __ldg(ln_g + lane), lnb = __ldg(ln_b + lane);

#pragma unroll
    for (int t = 0; t < 2; t++) {
        const int lr = w * 2 + t + 2;
        const int n = n0 + w * 2 + t;
        float y0 = fmaxf(v0[t] * bs + bb, 0.f);
        float y1 = fmaxf(v1[t] * bs + bb, 0.f);
        float resid = 0.5f * (y0 + y1) + ss[lr * 32 + lane];

        float sum = resid, sq = resid * resid;
#pragma unroll
        for (int off = 16; off; off >>= 1) {
            sum += __shfl_xor_sync(0xffffffffu, sum, off);
            sq  += __shfl_xor_sync(0xffffffffu, sq, off);
        }
        float mu = sum * (1.f / 32.f);
        float var = sq * (1.f / 32.f) - mu * mu;
        float rstd = rsqrtf(var + 1e-5f);
        float tout = (resid - mu) * rstd * lng + lnb;

        float hj[8];
#pragma unroll
        for (int j = 0; j < 8; j++) hj[j] = tout * __ldg(h1_w + j * 32 + lane);
#pragma unroll
        for (int j = 0; j < 8; j++)
#pragma unroll
            for (int off = 16; off; off >>= 1)
                hj[j] += __shfl_xor_sync(0xffffffffu, hj[j], off);

        float hsum = 0.f;
#pragma unroll
        for (int j = 0; j < 8; j++) { hj[j] += __ldg(h1_b + j); hsum += hj[j]; }
        float hmu = hsum * (1.f / 8.f);
        float hsq = 0.f;
#pragma unroll
        for (int j = 0; j < 8; j++) { float dd = hj[j] - hmu; hsq += dd * dd; }
        float hrstd = rsqrtf(hsq * (1.f / 8.f) + 1e-5f);
        float hh[8];
#pragma unroll
        for (int j = 0; j < 8; j++)
            hh[j] = fmaxf((hj[j] - hmu) * hrstd * __ldg(hln_g + j) + __ldg(hln_b + j), 0.f);

        if (lane < HOR_) {
            float p = __ldg(h2_b + lane);
#pragma unroll
            for (int j = 0; j < 8; j++) p += hh[j] * __ldg(h2_w + lane * 8 + j);
            out[(size_t)b * HOR_ * N_ + (size_t)lane * N_ + n] = p;
        }
    }
}

// =====================================================================
extern "C" void kernel_launch(void* const* d_in, const int* in_sizes, int n_in,
                              void* d_out, int out_size)
{
    const float* x      = (const float*)d_in[0];
    const float* fe_w   = (const float*)d_in[1];
    const float* fe_b   = (const float*)d_in[2];
    const float* fe_bng = (const float*)d_in[3];
    const float* fe_bnb = (const float*)d_in[4];
    const float* p1_w   = (const float*)d_in[5];
    const float* p1_b   = (const float*)d_in[6];
    const float* p2_w   = (const float*)d_in[7];
    const float* p2_b   = (const float*)d_in[8];
    const float* qkv_w  = (const float*)d_in[9];
    const float* qkv_b  = (const float*)d_in[10];
    const float* op_w   = (const float*)d_in[11];
    const float* op_b   = (const float*)d_in[12];
    const float* u      = (const float*)d_in[13];
    const float* v      = (const float*)d_in[14];
    const float* tc0_w  = (const float*)d_in[15];
    const float* tc0_b  = (const float*)d_in[16];
    const float* tc1_w  = (const float*)d_in[17];
    const float* tc1_b  = (const float*)d_in[18];
    const float* t_bng  = (const float*)d_in[19];
    const float* t_bnb  = (const float*)d_in[20];
    const float* t_lng  = (const float*)d_in[21];
    const float* t_lnb  = (const float*)d_in[22];
    const float* h1_w   = (const float*)d_in[23];
    const float* h1_b   = (const float*)d_in[24];
    const float* h_lng  = (const float*)d_in[25];
    const float* h_lnb  = (const float*)d_in[26];
    const float* h2_w   = (const float*)d_in[27];
    const float* h2_b   = (const float*)d_in[28];
    float* out = (float*)d_out;

    const int nodeblocks = (B_ * N_) / 8;   // 1024

    feat_kernel<<<nodeblocks, 256>>>(x, fe_w, fe_b, fe_bng, fe_bnb,
                                     p1_w, p1_b, p2_w, p2_b,
                                     qkv_w, qkv_b, u, v);

    dim3 agrid(N_ / 64, BH_);               // (64, 8) = 512 blocks
    attn_kernel<<<agrid, 128>>>();

    proj_kernel<<<nodeblocks, 256>>>(op_w, op_b);

    tail_kernel<<<(B_ * N_) / 16, 256>>>(tc0_w, tc0_b, tc1_w, tc1_b,
                                         t_bng, t_bnb, t_lng, t_lnb,
                                         h1_w, h1_b, h_lng, h_lnb,
                                         h2_w, h2_b, out);
}

// round 8
// speedup vs baseline: 2.8088x; 1.1175x over previous
#include <cuda_runtime.h>
#include <cuda_bf16.h>
#include <math.h>

// ---------------- problem constants ----------------
#define B_    2
#define T_    64
#define N_    4096
#define HOR_  24
#define C_    16
#define HID_  32
#define BD_   8
#define HEADS_ 4
#define HD_   8
#define BH_   (B_*HEADS_)      // 8
#define LOG2E 1.4426950408889634f
#define INV_SQRT8 0.35355339059327373f

// ---------------- scratch (device globals; no allocation) ----------------
__device__ __align__(16) __nv_bfloat16 d_Qh[BH_ * N_ * 16];
__device__ __align__(16) __nv_bfloat16 d_Ql[BH_ * N_ * 16];
__device__ __align__(16) __nv_bfloat16 d_Kh[BH_ * N_ * 16];
__device__ __align__(16) __nv_bfloat16 d_Kl[BH_ * N_ * 16];
__device__ __align__(16) __nv_bfloat16 d_Vh[BH_ * N_ * 8];
__device__ __align__(16) __nv_bfloat16 d_Vl[BH_ * N_ * 8];
__device__ float d_att[BH_ * N_ * 8];   // normalized attention output

__device__ __forceinline__ float ex2f(float x) {
    float y; asm("ex2.approx.ftz.f32 %0, %1;" : "=f"(y) : "f"(x)); return y;
}
__device__ __forceinline__ float elu1(float x) {
    return x > 0.f ? x + 1.f : __expf(x);
}
__device__ __forceinline__ void bsplit(float x, __nv_bfloat16& hi, __nv_bfloat16& lo) {
    __nv_bfloat16 h = __float2bfloat16(x);
    hi = h;
    lo = __float2bfloat16(x - __bfloat162float(h));
}

// bf16 m16n8k16 mma, fp32 accumulate
__device__ __forceinline__ void mma16816(float d[4], const unsigned a[4],
                                         const unsigned b[2], const float c[4]) {
    asm volatile(
        "mma.sync.aligned.m16n8k16.row.col.f32.bf16.bf16.f32 "
        "{%0,%1,%2,%3}, {%4,%5,%6,%7}, {%8,%9}, {%10,%11,%12,%13};"
        : "=f"(d[0]), "=f"(d[1]), "=f"(d[2]), "=f"(d[3])
        : "r"(a[0]), "r"(a[1]), "r"(a[2]), "r"(a[3]),
          "r"(b[0]), "r"(b[1]),
          "f"(c[0]), "f"(c[1]), "f"(c[2]), "f"(c[3]));
}

// pack two fp32 -> bf16x2 hi/lo split
__device__ __forceinline__ void split2(float x, float y, unsigned& hi, unsigned& lo) {
    __nv_bfloat162 h2 = __floats2bfloat162_rn(x, y);
    hi = *(unsigned*)&h2;
    __nv_bfloat162 l2 = __floats2bfloat162_rn(x - __bfloat162float(h2.x),
                                              y - __bfloat162float(h2.y));
    lo = *(unsigned*)&l2;
}

// =====================================================================
// Kernel A: conv feature extractor -> p1 -> p2 -> qkv -> split-bf16 Q'/K'/V
// =====================================================================
__global__ void __launch_bounds__(256)
feat_kernel(const float* __restrict__ x,
            const float* __restrict__ fe_w, const float* __restrict__ fe_b,
            const float* __restrict__ bn_g, const float* __restrict__ bn_b,
            const float* __restrict__ p1_w, const float* __restrict__ p1_b,
            const float* __restrict__ p2_w, const float* __restrict__ p2_b,
            const float* __restrict__ qkv_w, const float* __restrict__ qkv_b,
            const float* __restrict__ u, const float* __restrict__ v)
{
    __shared__ float p1s[8192];          // 32768 B
    __shared__ float xs[8][66];          //  2112 B
    __shared__ float fs[8][32];          //  1024 B
    __shared__ float cw[48];             //   192 B
    __shared__ float csh[16];            //    64 B
    __shared__ float wt[32 * 97];        // 12416 B  qkv_w transposed
    // total 48576 B < 49152

    const int tid = threadIdx.x;
    const int blk = blockIdx.x;
    const int b   = blk >> 9;
    const int n0  = (blk & 511) << 3;

    for (int i = tid; i < 2048; i += 256)
        ((float4*)p1s)[i] = ((const float4*)p1_w)[i];
    for (int idx = tid; idx < 3072; idx += 256) {
        int o = idx >> 5, i = idx & 31;
        wt[i * 97 + o] = qkv_w[idx];
    }
    if (tid < 48) {
        int c = tid / 3;
        float sc = bn_g[c] * rsqrtf(1.f + 1e-5f);
        cw[tid] = fe_w[tid] * sc;
    }
    if (tid < 16) {
        float sc = bn_g[tid] * rsqrtf(1.f + 1e-5f);
        csh[tid] = fe_b[tid] * sc + bn_b[tid];
    }
    for (int i = tid; i < 512; i += 256) {
        int node = i & 7, t = i >> 3;
        xs[node][t + 1] = x[(size_t)b * T_ * N_ + (size_t)t * N_ + n0 + node];
    }
    if (tid < 8) { xs[tid][0] = 0.f; xs[tid][65] = 0.f; }
    __syncthreads();

    const int w = tid >> 5, lane = tid & 31;
    const int n = n0 + w;

    float acc[8];
#pragma unroll
    for (int j = 0; j < 8; j++) acc[j] = 0.f;

#pragma unroll
    for (int i = 0; i < 32; i++) {
        int c = i >> 1;
        int t = lane + ((i & 1) << 5);
        float val = xs[w][t] * cw[c * 3] + xs[w][t + 1] * cw[c * 3 + 1]
                  + xs[w][t + 2] * cw[c * 3 + 2] + csh[c];
        val = fmaxf(val, 0.f);
        int base = i * 32 + lane;
#pragma unroll
        for (int j = 0; j < 8; j++) acc[j] += val * p1s[j * 1024 + base];
    }
#pragma unroll
    for (int j = 0; j < 8; j++)
#pragma unroll
        for (int off = 16; off; off >>= 1)
            acc[j] += __shfl_xor_sync(0xffffffffu, acc[j], off);

    float r1[8];
#pragma unroll
    for (int j = 0; j < 8; j++) r1[j] = fmaxf(acc[j] + __ldg(p1_b + j), 0.f);

    float f = __ldg(p2_b + lane);
#pragma unroll
    for (int j = 0; j < 8; j++) f += r1[j] * __ldg(p2_w + lane * 8 + j);
    fs[w][lane] = f;
    __syncwarp();

    float oq = __ldg(qkv_b + lane);
    float ok = __ldg(qkv_b + lane + 32);
    float ov = __ldg(qkv_b + lane + 64);
#pragma unroll
    for (int i = 0; i < 32; i++) {
        float fi = fs[w][i];
        const float* wr = wt + i * 97;
        oq += fi * wr[lane];
        ok += fi * wr[lane + 32];
        ov += fi * wr[lane + 64];
    }

    const int head = lane >> 3, d = lane & 7;
    const size_t ridx = ((size_t)(b * 4 + head) * N_ + n);
    const size_t qidx = ridx * 16;

    float qv = elu1(oq) * (LOG2E * INV_SQRT8);
    float uv = u[(size_t)n * 8 + d] * LOG2E;
    float kv = elu1(ok);
    float vv = v[(size_t)d * N_ + n];

    bsplit(qv, d_Qh[qidx + d],     d_Ql[qidx + d]);
    bsplit(uv, d_Qh[qidx + 8 + d], d_Ql[qidx + 8 + d]);
    bsplit(kv, d_Kh[qidx + d],     d_Kl[qidx + d]);
    bsplit(vv, d_Kh[qidx + 8 + d], d_Kl[qidx + 8 + d]);
    bsplit(ov, d_Vh[ridx * 8 + d], d_Vl[ridx * 8 + d]);
}

// =====================================================================
// Kernel B: tensor-core flash attention (bf16 split-precision)
// grid (N/64, BH), 128 threads = 4 warps; KTILE=128, vectorized K staging
// =====================================================================
#define KTILE 128
__global__ void __launch_bounds__(128)
attn_kernel()
{
    const int bh = blockIdx.y;
    const int qbase = blockIdx.x * 64;
    const int tid = threadIdx.x, w = tid >> 5, l = tid & 31;

    __shared__ __align__(16) unsigned Kh_s[KTILE * 12], Kl_s[KTILE * 12];
    __shared__ unsigned Vh_s[8 * 68], Vl_s[8 * 68];

    const unsigned* Qh_u = (const unsigned*)d_Qh + (size_t)bh * N_ * 8;
    const unsigned* Ql_u = (const unsigned*)d_Ql + (size_t)bh * N_ * 8;
    const uint4* Kh4 = (const uint4*)(d_Kh + (size_t)bh * N_ * 16);
    const uint4* Kl4 = (const uint4*)(d_Kl + (size_t)bh * N_ * 16);
    const __nv_bfloat16* Vh_g = d_Vh + (size_t)bh * N_ * 8;
    const __nv_bfloat16* Vl_g = d_Vl + (size_t)bh * N_ * 8;

    const int qr0 = qbase + w * 16 + (l >> 2);
    const int qr1 = qr0 + 8;
    const int c4 = l & 3;

    unsigned ah[4], al[4];
    ah[0] = Qh_u[qr0 * 8 + c4];     ah[1] = Qh_u[qr1 * 8 + c4];
    ah[2] = Qh_u[qr0 * 8 + c4 + 4]; ah[3] = Qh_u[qr1 * 8 + c4 + 4];
    al[0] = Ql_u[qr0 * 8 + c4];     al[1] = Ql_u[qr1 * 8 + c4];
    al[2] = Ql_u[qr0 * 8 + c4 + 4]; al[3] = Ql_u[qr1 * 8 + c4 + 4];

    float O[4] = {0.f, 0.f, 0.f, 0.f};
    float la = 0.f, lb = 0.f;

    __nv_bfloat16* Vh_sh = (__nv_bfloat16*)Vh_s;
    __nv_bfloat16* Vl_sh = (__nv_bfloat16*)Vl_s;

    for (int kt = 0; kt < N_; kt += KTILE) {
        __syncthreads();
        // K: 128 keys x 32B (hi,lo) via uint4
#pragma unroll
        for (int i = 0; i < 2; i++) {
            int idx = tid + i * 128;           // 0..255
            int key = idx >> 1, half = idx & 1;
            *(uint4*)&Kh_s[key * 12 + half * 4] = Kh4[(size_t)(kt + key) * 2 + half];
            *(uint4*)&Kl_s[key * 12 + half * 4] = Kl4[(size_t)(kt + key) * 2 + half];
        }
        // V: transpose into [vdim][key], stride 136 halves
#pragma unroll
        for (int i = 0; i < 8; i++) {
            int idx = tid + i * 128;           // 0..1023
            int key = idx >> 3, vd = idx & 7;
            Vh_sh[vd * 136 + key] = Vh_g[(size_t)(kt + key) * 8 + vd];
            Vl_sh[vd * 136 + key] = Vl_g[(size_t)(kt + key) * 8 + vd];
        }
        __syncthreads();

#pragma unroll
        for (int c16 = 0; c16 < KTILE; c16 += 16) {
            float S0[4] = {0.f, 0.f, 0.f, 0.f};
            float S1[4] = {0.f, 0.f, 0.f, 0.f};

            const int kr0 = c16 + (l >> 2);
            const int kr1 = kr0 + 8;
            unsigned kh0[2] = {Kh_s[kr0 * 12 + c4], Kh_s[kr0 * 12 + c4 + 4]};
            unsigned kl0[2] = {Kl_s[kr0 * 12 + c4], Kl_s[kr0 * 12 + c4 + 4]};
            unsigned kh1[2] = {Kh_s[kr1 * 12 + c4], Kh_s[kr1 * 12 + c4 + 4]};
            unsigned kl1[2] = {Kl_s[kr1 * 12 + c4], Kl_s[kr1 * 12 + c4 + 4]};

            mma16816(S0, ah, kh0, S0);
            mma16816(S0, al, kh0, S0);
            mma16816(S0, ah, kl0, S0);
            mma16816(S1, ah, kh1, S1);
            mma16816(S1, al, kh1, S1);
            mma16816(S1, ah, kl1, S1);

            float p00 = ex2f(S0[0]), p01 = ex2f(S0[1]);
            float p02 = ex2f(S0[2]), p03 = ex2f(S0[3]);
            float p10 = ex2f(S1[0]), p11 = ex2f(S1[1]);
            float p12 = ex2f(S1[2]), p13 = ex2f(S1[3]);
            la += p00 + p01 + p10 + p11;
            lb += p02 + p03 + p12 + p13;

            unsigned pa_h[4], pa_l[4];
            split2(p00, p01, pa_h[0], pa_l[0]);
            split2(p02, p03, pa_h[1], pa_l[1]);
            split2(p10, p11, pa_h[2], pa_l[2]);
            split2(p12, p13, pa_h[3], pa_l[3]);

            const int vbase = (l >> 2) * 68 + (c16 >> 1) + c4;
            unsigned vh[2] = {Vh_s[vbase], Vh_s[vbase + 4]};
            unsigned vl[2] = {Vl_s[vbase], Vl_s[vbase + 4]};

            mma16816(O, pa_h, vh, O);
            mma16816(O, pa_l, vh, O);
            mma16816(O, pa_h, vl, O);
        }
    }

    la += __shfl_xor_sync(0xffffffffu, la, 1);
    la += __shfl_xor_sync(0xffffffffu, la, 2);
    lb += __shfl_xor_sync(0xffffffffu, lb, 1);
    lb += __shfl_xor_sync(0xffffffffu, lb, 2);

    float inva = 1.f / la, invb = 1.f / lb;
    float* o0 = d_att + ((size_t)bh * N_ + qr0) * 8 + 2 * c4;
    float* o1 = d_att + ((size_t)bh * N_ + qr1) * 8 + 2 * c4;
    o0[0] = O[0] * inva; o0[1] = O[1] * inva;
    o1[0] = O[2] * invb; o1[1] = O[3] * invb;
}

// =====================================================================
// Kernel C: fused op-projection + dilated convs + BN + residual LN
//           + horizon MLP. 16 nodes/block, computes its own 20-row s halo.
// =====================================================================
__global__ void __launch_bounds__(256)
tail_kernel(const float* __restrict__ op_w, const float* __restrict__ op_b,
            const float* __restrict__ tc0_w, const float* __restrict__ tc0_b,
            const float* __restrict__ tc1_w, const float* __restrict__ tc1_b,
            const float* __restrict__ bn_g, const float* __restrict__ bn_b,
            const float* __restrict__ ln_g, const float* __restrict__ ln_b,
            const float* __restrict__ h1_w, const float* __restrict__ h1_b,
            const float* __restrict__ hln_g, const float* __restrict__ hln_b,
            const float* __restrict__ h2_w, const float* __restrict__ h2_b,
            float* __restrict__ out)
{
    __shared__ float ss[20 * 32];        // s rows n0-2 .. n0+17
    __shared__ float at[20 * 33];        // attention rows (padded)
    __shared__ float ow[32 * 33];        // op_w transposed
    __shared__ float tw0[96 * 33];
    __shared__ float tw1[96 * 33];

    const int tid = threadIdx.x;
    const int blk = blockIdx.x;
    const int b   = blk >> 8;
    const int n0  = (blk & 255) << 4;

    for (int idx = tid; idx < 3072; idx += 256) {
        int co = idx / 96, rem = idx % 96;
        tw0[rem * 33 + co] = tc0_w[idx];
        tw1[rem * 33 + co] = tc1_w[idx];
    }
    for (int idx = tid; idx < 1024; idx += 256) {
        int o = idx >> 5, i = idx & 31;
        ow[i * 33 + o] = op_w[idx];
    }
    for (int idx = tid; idx < 640; idx += 256) {
        int rr = idx >> 5, c = idx & 31;
        int gn = n0 - 2 + rr;
        int head = c >> 3, e = c & 7;
        at[rr * 33 + c] = (gn >= 0 && gn < N_)
            ? d_att[((size_t)(b * 4 + head) * N_ + gn) * 8 + e] : 0.f;
    }
    __syncthreads();

    const int w = tid >> 5, lane = tid & 31;

    // op projection for the block's 20 halo rows
    for (int r = w; r < 20; r += 8) {
        int gn = n0 - 2 + r;
        float o = 0.f;
        if (gn >= 0 && gn < N_) {
            o = __ldg(op_b + lane);
#pragma unroll
            for (int i = 0; i < 32; i++)
                o += at[r * 33 + i] * ow[i * 33 + lane];
        }
        ss[r * 32 + lane] = o;
    }
    __syncthreads();

    const float b0 = __ldg(tc0_b + lane), b1 = __ldg(tc1_b + lane);

    float v0[2], v1[2];
#pragma unroll
    for (int t = 0; t < 2; t++) { v0[t] = b0; v1[t] = b1; }

#pragma unroll 8
    for (int ci = 0; ci < 32; ci++) {
        float w00 = tw0[(ci * 3 + 0) * 33 + lane];
        float w01 = tw0[(ci * 3 + 1) * 33 + lane];
        float w02 = tw0[(ci * 3 + 2) * 33 + lane];
        float w10 = tw1[(ci * 3 + 0) * 33 + lane];
        float w11 = tw1[(ci * 3 + 1) * 33 + lane];
        float w12 = tw1[(ci * 3 + 2) * 33 + lane];
#pragma unroll
        for (int t = 0; t < 2; t++) {
            int lr = w * 2 + t + 2;
            float sm2 = ss[(lr - 2) * 32 + ci];
            float sm1 = ss[(lr - 1) * 32 + ci];
            float s0  = ss[lr * 32 + ci];
            float sp1 = ss[(lr + 1) * 32 + ci];
            float sp2 = ss[(lr + 2) * 32 + ci];
            v0[t] += sm1 * w00 + s0 * w01 + sp1 * w02;
            v1[t] += sm2 * w10 + s0 * w11 + sp2 * w12;
        }
    }

    const float bs = __ldg(bn_g + lane) * rsqrtf(1.f + 1e-5f);
    const float bb = __ldg(bn_b + lane);
    const float lng = __ldg(ln_g + lane), lnb = __ldg(ln_b + lane);

#pragma unroll
    for (int t = 0; t < 2; t++) {
        const int lr = w * 2 + t + 2;
        const int n = n0 + w * 2 + t;
        float y0 = fmaxf(v0[t] * bs + bb, 0.f);
        float y1 = fmaxf(v1[t] * bs + bb, 0.f);
        float resid = 0.5f * (y0 + y1) + ss[lr * 32 + lane];

        float sum = resid, sq = resid * resid;
#pragma unroll
        for (int off = 16; off; off >>= 1) {
            sum += __shfl_xor_sync(0xffffffffu, sum, off);
            sq  += __shfl_xor_sync(0xffffffffu, sq, off);
        }
        float mu = sum * (1.f / 32.f);
        float var = sq * (1.f / 32.f) - mu * mu;
        float rstd = rsqrtf(var + 1e-5f);
        float tout = (resid - mu) * rstd * lng + lnb;

        float hj[8];
#pragma unroll
        for (int j = 0; j < 8; j++) hj[j] = tout * __ldg(h1_w + j * 32 + lane);
#pragma unroll
        for (int j = 0; j < 8; j++)
#pragma unroll
            for (int off = 16; off; off >>= 1)
                hj[j] += __shfl_xor_sync(0xffffffffu, hj[j], off);

        float hsum = 0.f;
#pragma unroll
        for (int j = 0; j < 8; j++) { hj[j] += __ldg(h1_b + j); hsum += hj[j]; }
        float hmu = hsum * (1.f / 8.f);
        float hsq = 0.f;
#pragma unroll
        for (int j = 0; j < 8; j++) { float dd = hj[j] - hmu; hsq += dd * dd; }
        float hrstd = rsqrtf(hsq * (1.f / 8.f) + 1e-5f);
        float hh[8];
#pragma unroll
        for (int j = 0; j < 8; j++)
            hh[j] = fmaxf((hj[j] - hmu) * hrstd * __ldg(hln_g + j) + __ldg(hln_b + j), 0.f);

        if (lane < HOR_) {
            float p = __ldg(h2_b + lane);
#pragma unroll
            for (int j = 0; j < 8; j++) p += hh[j] * __ldg(h2_w + lane * 8 + j);
            out[(size_t)b * HOR_ * N_ + (size_t)lane * N_ + n] = p;
        }
    }
}

// =====================================================================
extern "C" void kernel_launch(void* const* d_in, const int* in_sizes, int n_in,
                              void* d_out, int out_size)
{
    const float* x      = (const float*)d_in[0];
    const float* fe_w   = (const float*)d_in[1];
    const float* fe_b   = (const float*)d_in[2];
    const float* fe_bng = (const float*)d_in[3];
    const float* fe_bnb = (const float*)d_in[4];
    const float* p1_w   = (const float*)d_in[5];
    const float* p1_b   = (const float*)d_in[6];
    const float* p2_w   = (const float*)d_in[7];
    const float* p2_b   = (const float*)d_in[8];
    const float* qkv_w  = (const float*)d_in[9];
    const float* qkv_b  = (const float*)d_in[10];
    const float* op_w   = (const float*)d_in[11];
    const float* op_b   = (const float*)d_in[12];
    const float* u      = (const float*)d_in[13];
    const float* v      = (const float*)d_in[14];
    const float* tc0_w  = (const float*)d_in[15];
    const float* tc0_b  = (const float*)d_in[16];
    const float* tc1_w  = (const float*)d_in[17];
    const float* tc1_b  = (const float*)d_in[18];
    const float* t_bng  = (const float*)d_in[19];
    const float* t_bnb  = (const float*)d_in[20];
    const float* t_lng  = (const float*)d_in[21];
    const float* t_lnb  = (const float*)d_in[22];
    const float* h1_w   = (const float*)d_in[23];
    const float* h1_b   = (const float*)d_in[24];
    const float* h_lng  = (const float*)d_in[25];
    const float* h_lnb  = (const float*)d_in[26];
    const float* h2_w   = (const float*)d_in[27];
    const float* h2_b   = (const float*)d_in[28];
    float* out = (float*)d_out;

    feat_kernel<<<(B_ * N_) / 8, 256>>>(x, fe_w, fe_b, fe_bng, fe_bnb,
                                        p1_w, p1_b, p2_w, p2_b,
                                        qkv_w, qkv_b, u, v);

    dim3 agrid(N_ / 64, BH_);               // (64, 8) = 512 blocks
    attn_kernel<<<agrid, 128>>>();

    tail_kernel<<<(B_ * N_) / 16, 256>>>(op_w, op_b,
                                         tc0_w, tc0_b, tc1_w, tc1_b,
                                         t_bng, t_bnb, t_lng, t_lnb,
                                         h1_w, h1_b, h_lng, h_lnb,
                                         h2_w, h2_b, out);
}

// round 9
// speedup vs baseline: 2.8938x; 1.0303x over previous
#include <cuda_runtime.h>
#include <cuda_bf16.h>
#include <math.h>

// ---------------- problem constants ----------------
#define B_    2
#define T_    64
#define N_    4096
#define HOR_  24
#define C_    16
#define HID_  32
#define BD_   8
#define HEADS_ 4
#define HD_   8
#define BH_   (B_*HEADS_)      // 8
#define LOG2E 1.4426950408889634f
#define INV_SQRT8 0.35355339059327373f
#define KSPLIT 2

// ---------------- scratch (device globals; no allocation) ----------------
__device__ __align__(16) __nv_bfloat16 d_Qh[BH_ * N_ * 16];
__device__ __align__(16) __nv_bfloat16 d_Ql[BH_ * N_ * 16];
__device__ __align__(16) __nv_bfloat16 d_Kh[BH_ * N_ * 16];
__device__ __align__(16) __nv_bfloat16 d_Kl[BH_ * N_ * 16];
__device__ __align__(16) __nv_bfloat16 d_Vh[BH_ * N_ * 8];
__device__ __align__(16) __nv_bfloat16 d_Vl[BH_ * N_ * 8];
__device__ float d_patt[KSPLIT * BH_ * N_ * 8];   // unnormalized partial O
__device__ float d_pl[KSPLIT * BH_ * N_];         // partial row sums

__device__ __forceinline__ float ex2f(float x) {
    float y; asm("ex2.approx.ftz.f32 %0, %1;" : "=f"(y) : "f"(x)); return y;
}
__device__ __forceinline__ float elu1(float x) {
    return x > 0.f ? x + 1.f : __expf(x);
}
__device__ __forceinline__ void bsplit(float x, __nv_bfloat16& hi, __nv_bfloat16& lo) {
    __nv_bfloat16 h = __float2bfloat16(x);
    hi = h;
    lo = __float2bfloat16(x - __bfloat162float(h));
}

// bf16 m16n8k16 mma, fp32 accumulate
__device__ __forceinline__ void mma16816(float d[4], const unsigned a[4],
                                         const unsigned b[2], const float c[4]) {
    asm volatile(
        "mma.sync.aligned.m16n8k16.row.col.f32.bf16.bf16.f32 "
        "{%0,%1,%2,%3}, {%4,%5,%6,%7}, {%8,%9}, {%10,%11,%12,%13};"
        : "=f"(d[0]), "=f"(d[1]), "=f"(d[2]), "=f"(d[3])
        : "r"(a[0]), "r"(a[1]), "r"(a[2]), "r"(a[3]),
          "r"(b[0]), "r"(b[1]),
          "f"(c[0]), "f"(c[1]), "f"(c[2]), "f"(c[3]));
}

// pack two fp32 -> bf16x2 hi/lo split
__device__ __forceinline__ void split2(float x, float y, unsigned& hi, unsigned& lo) {
    __nv_bfloat162 h2 = __floats2bfloat162_rn(x, y);
    hi = *(unsigned*)&h2;
    __nv_bfloat162 l2 = __floats2bfloat162_rn(x - __bfloat162float(h2.x),
                                              y - __bfloat162float(h2.y));
    lo = *(unsigned*)&l2;
}

// =====================================================================
// Kernel A: conv feature extractor -> p1 -> p2 -> qkv -> split-bf16 Q'/K'/V
// p1 weights paired [j/2][base][2] for conflict-free LDS.64
// =====================================================================
__global__ void __launch_bounds__(256)
feat_kernel(const float* __restrict__ x,
            const float* __restrict__ fe_w, const float* __restrict__ fe_b,
            const float* __restrict__ bn_g, const float* __restrict__ bn_b,
            const float* __restrict__ p1_w, const float* __restrict__ p1_b,
            const float* __restrict__ p2_w, const float* __restrict__ p2_b,
            const float* __restrict__ qkv_w, const float* __restrict__ qkv_b,
            const float* __restrict__ u, const float* __restrict__ v)
{
    __shared__ float p1p[8192];          // 32768 B  paired p1 weights
    __shared__ float xs[8][66];          //  2112 B
    __shared__ float fs[8][32];          //  1024 B
    __shared__ float cw[48];             //   192 B
    __shared__ float csh[16];            //    64 B
    __shared__ float wt[32 * 97];        // 12416 B  qkv_w transposed
    // total 48576 B < 49152

    const int tid = threadIdx.x;
    const int blk = blockIdx.x;
    const int b   = blk >> 9;
    const int n0  = (blk & 511) << 3;

    // p1_w [8 out][1024 in] -> p1p[(j/2)*2048 + base*2 + (j&1)]
    for (int idx = tid; idx < 8192; idx += 256) {
        int j = idx >> 10, base = idx & 1023;
        p1p[(j >> 1) * 2048 + base * 2 + (j & 1)] = p1_w[idx];
    }
    for (int idx = tid; idx < 3072; idx += 256) {
        int o = idx >> 5, i = idx & 31;
        wt[i * 97 + o] = qkv_w[idx];
    }
    if (tid < 48) {
        int c = tid / 3;
        float sc = bn_g[c] * rsqrtf(1.f + 1e-5f);
        cw[tid] = fe_w[tid] * sc;
    }
    if (tid < 16) {
        float sc = bn_g[tid] * rsqrtf(1.f + 1e-5f);
        csh[tid] = fe_b[tid] * sc + bn_b[tid];
    }
    for (int i = tid; i < 512; i += 256) {
        int node = i & 7, t = i >> 3;
        xs[node][t + 1] = x[(size_t)b * T_ * N_ + (size_t)t * N_ + n0 + node];
    }
    if (tid < 8) { xs[tid][0] = 0.f; xs[tid][65] = 0.f; }
    __syncthreads();

    const int w = tid >> 5, lane = tid & 31;
    const int n = n0 + w;

    // hoist the 6 x values used by all 32 iterations
    const float xa0 = xs[w][lane],      xa1 = xs[w][lane + 1],  xa2 = xs[w][lane + 2];
    const float xb0 = xs[w][lane + 32], xb1 = xs[w][lane + 33], xb2 = xs[w][lane + 34];

    float acc[8];
#pragma unroll
    for (int j = 0; j < 8; j++) acc[j] = 0.f;

#pragma unroll
    for (int i = 0; i < 32; i++) {
        int c = i >> 1;
        float val;
        if ((i & 1) == 0)
            val = xa0 * cw[c * 3] + xa1 * cw[c * 3 + 1] + xa2 * cw[c * 3 + 2] + csh[c];
        else
            val = xb0 * cw[c * 3] + xb1 * cw[c * 3 + 1] + xb2 * cw[c * 3 + 2] + csh[c];
        val = fmaxf(val, 0.f);
        int base2 = (i * 32 + lane) * 2;
#pragma unroll
        for (int jj = 0; jj < 4; jj++) {
            float2 pv = *(const float2*)&p1p[jj * 2048 + base2];
            acc[2 * jj]     += val * pv.x;
            acc[2 * jj + 1] += val * pv.y;
        }
    }
#pragma unroll
    for (int j = 0; j < 8; j++)
#pragma unroll
        for (int off = 16; off; off >>= 1)
            acc[j] += __shfl_xor_sync(0xffffffffu, acc[j], off);

    float r1[8];
#pragma unroll
    for (int j = 0; j < 8; j++) r1[j] = fmaxf(acc[j] + __ldg(p1_b + j), 0.f);

    float f = __ldg(p2_b + lane);
#pragma unroll
    for (int j = 0; j < 8; j++) f += r1[j] * __ldg(p2_w + lane * 8 + j);
    fs[w][lane] = f;
    __syncwarp();

    float oq = __ldg(qkv_b + lane);
    float ok = __ldg(qkv_b + lane + 32);
    float ov = __ldg(qkv_b + lane + 64);
#pragma unroll
    for (int i = 0; i < 32; i++) {
        float fi = fs[w][i];
        const float* wr = wt + i * 97;
        oq += fi * wr[lane];
        ok += fi * wr[lane + 32];
        ov += fi * wr[lane + 64];
    }

    const int head = lane >> 3, d = lane & 7;
    const size_t ridx = ((size_t)(b * 4 + head) * N_ + n);
    const size_t qidx = ridx * 16;

    float qv = elu1(oq) * (LOG2E * INV_SQRT8);
    float uv = u[(size_t)n * 8 + d] * LOG2E;
    float kv = elu1(ok);
    float vv = v[(size_t)d * N_ + n];

    bsplit(qv, d_Qh[qidx + d],     d_Ql[qidx + d]);
    bsplit(uv, d_Qh[qidx + 8 + d], d_Ql[qidx + 8 + d]);
    bsplit(kv, d_Kh[qidx + d],     d_Kl[qidx + d]);
    bsplit(vv, d_Kh[qidx + 8 + d], d_Kl[qidx + 8 + d]);
    bsplit(ov, d_Vh[ridx * 8 + d], d_Vl[ridx * 8 + d]);
}

// =====================================================================
// Kernel B: tensor-core flash attention, split-K=2 partials
// grid (N/64, BH, KSPLIT), 128 threads = 4 warps; interleaved K/V smem
// =====================================================================
#define KTILE 128
__global__ void __launch_bounds__(128)
attn_kernel()
{
    const int bh = blockIdx.y;
    const int qbase = blockIdx.x * 64;
    const int kz = blockIdx.z;
    const int tid = threadIdx.x, w = tid >> 5, l = tid & 31;

    // K: [key][c4][{h_c4, h_c4+4, l_c4, l_c4+4}], key stride 16 uints (8KB)
    __shared__ __align__(16) unsigned Khl[KTILE * 16];
    // V: [vd][c16idx][c4][{vh_j, vh_j+4, vl_j, vl_j+4}], vd stride 144 uints
    __shared__ __align__(16) unsigned Vhl[8 * 144];

    const unsigned* Qh_u = (const unsigned*)d_Qh + (size_t)bh * N_ * 8;
    const unsigned* Ql_u = (const unsigned*)d_Ql + (size_t)bh * N_ * 8;
    const unsigned* Kh_u = (const unsigned*)d_Kh + (size_t)bh * N_ * 8;
    const unsigned* Kl_u = (const unsigned*)d_Kl + (size_t)bh * N_ * 8;
    const __nv_bfloat16* Vh_g = d_Vh + (size_t)bh * N_ * 8;
    const __nv_bfloat16* Vl_g = d_Vl + (size_t)bh * N_ * 8;

    const int qr0 = qbase + w * 16 + (l >> 2);
    const int qr1 = qr0 + 8;
    const int c4 = l & 3;

    unsigned ah[4], al[4];
    ah[0] = Qh_u[qr0 * 8 + c4];     ah[1] = Qh_u[qr1 * 8 + c4];
    ah[2] = Qh_u[qr0 * 8 + c4 + 4]; ah[3] = Qh_u[qr1 * 8 + c4 + 4];
    al[0] = Ql_u[qr0 * 8 + c4];     al[1] = Ql_u[qr1 * 8 + c4];
    al[2] = Ql_u[qr0 * 8 + c4 + 4]; al[3] = Ql_u[qr1 * 8 + c4 + 4];

    float O[4] = {0.f, 0.f, 0.f, 0.f};
    float la = 0.f, lb = 0.f;

    __nv_bfloat16* Vsh = (__nv_bfloat16*)Vhl;

    const int k0 = kz * (N_ / KSPLIT);
    for (int kt = k0; kt < k0 + N_ / KSPLIT; kt += KTILE) {
        __syncthreads();
        // K staging: 512 (key, c4) records, 1 STS.128 each
#pragma unroll
        for (int i = 0; i < 4; i++) {
            int idx = tid + i * 128;
            int key = idx >> 2, kc = idx & 3;
            unsigned h0 = Kh_u[(size_t)(kt + key) * 8 + kc];
            unsigned h4 = Kh_u[(size_t)(kt + key) * 8 + kc + 4];
            unsigned l0 = Kl_u[(size_t)(kt + key) * 8 + kc];
            unsigned l4 = Kl_u[(size_t)(kt + key) * 8 + kc + 4];
            *(uint4*)&Khl[key * 16 + kc * 4] = make_uint4(h0, h4, l0, l4);
        }
        // V staging: transpose, interleaved hi/lo pairs
#pragma unroll
        for (int i = 0; i < 8; i++) {
            int idx = tid + i * 128;
            int key = idx >> 3, vd = idx & 7;
            int j = key >> 1, half = key & 1;
            int ci = j >> 3, c4v = j & 3, hi4 = (j >> 2) & 1;
            int base_u = vd * 144 + ci * 16 + c4v * 4;
            Vsh[2 * (base_u + hi4) + half]     = Vh_g[(size_t)(kt + key) * 8 + vd];
            Vsh[2 * (base_u + 2 + hi4) + half] = Vl_g[(size_t)(kt + key) * 8 + vd];
        }
        __syncthreads();

#pragma unroll
        for (int c16 = 0; c16 < KTILE; c16 += 16) {
            float S0[4] = {0.f, 0.f, 0.f, 0.f};
            float S1[4] = {0.f, 0.f, 0.f, 0.f};

            const int kr0 = c16 + (l >> 2);
            const int kr1 = kr0 + 8;
            uint4 k0v = *(const uint4*)&Khl[kr0 * 16 + c4 * 4];
            uint4 k1v = *(const uint4*)&Khl[kr1 * 16 + c4 * 4];
            unsigned kh0[2] = {k0v.x, k0v.y}, kl0[2] = {k0v.z, k0v.w};
            unsigned kh1[2] = {k1v.x, k1v.y}, kl1[2] = {k1v.z, k1v.w};

            mma16816(S0, ah, kh0, S0);
            mma16816(S0, al, kh0, S0);
            mma16816(S0, ah, kl0, S0);
            mma16816(S1, ah, kh1, S1);
            mma16816(S1, al, kh1, S1);
            mma16816(S1, ah, kl1, S1);

            float p00 = ex2f(S0[0]), p01 = ex2f(S0[1]);
            float p02 = ex2f(S0[2]), p03 = ex2f(S0[3]);
            float p10 = ex2f(S1[0]), p11 = ex2f(S1[1]);
            float p12 = ex2f(S1[2]), p13 = ex2f(S1[3]);
            la += p00 + p01 + p10 + p11;
            lb += p02 + p03 + p12 + p13;

            unsigned pa_h[4], pa_l[4];
            split2(p00, p01, pa_h[0], pa_l[0]);
            split2(p02, p03, pa_h[1], pa_l[1]);
            split2(p10, p11, pa_h[2], pa_l[2]);
            split2(p12, p13, pa_h[3], pa_l[3]);

            uint4 vv = *(const uint4*)&Vhl[(l >> 2) * 144 + (c16 >> 4) * 16 + c4 * 4];
            unsigned vh[2] = {vv.x, vv.y}, vl[2] = {vv.z, vv.w};

            mma16816(O, pa_h, vh, O);
            mma16816(O, pa_l, vh, O);
            mma16816(O, pa_h, vl, O);
        }
    }

    la += __shfl_xor_sync(0xffffffffu, la, 1);
    la += __shfl_xor_sync(0xffffffffu, la, 2);
    lb += __shfl_xor_sync(0xffffffffu, lb, 1);
    lb += __shfl_xor_sync(0xffffffffu, lb, 2);

    const size_t pbase = (size_t)(kz * BH_ + bh) * N_;
    float* o0 = d_patt + (pbase + qr0) * 8 + 2 * c4;
    float* o1 = d_patt + (pbase + qr1) * 8 + 2 * c4;
    o0[0] = O[0]; o0[1] = O[1];
    o1[0] = O[2]; o1[1] = O[3];
    if (c4 == 0) {
        d_pl[pbase + qr0] = la;
        d_pl[pbase + qr1] = lb;
    }
}

// =====================================================================
// Kernel C: fused split-combine + op-projection + dilated convs + BN +
//           residual LN + horizon MLP. 16 nodes/block.
// =====================================================================
__global__ void __launch_bounds__(256)
tail_kernel(const float* __restrict__ op_w, const float* __restrict__ op_b,
            const float* __restrict__ tc0_w, const float* __restrict__ tc0_b,
            const float* __restrict__ tc1_w, const float* __restrict__ tc1_b,
            const float* __restrict__ bn_g, const float* __restrict__ bn_b,
            const float* __restrict__ ln_g, const float* __restrict__ ln_b,
            const float* __restrict__ h1_w, const float* __restrict__ h1_b,
            const float* __restrict__ hln_g, const float* __restrict__ hln_b,
            const float* __restrict__ h2_w, const float* __restrict__ h2_b,
            float* __restrict__ out)
{
    __shared__ float ss[20 * 32];
    __shared__ float at[20 * 33];
    __shared__ float ow[32 * 33];
    __shared__ float tw0[96 * 33];
    __shared__ float tw1[96 * 33];

    const int tid = threadIdx.x;
    const int blk = blockIdx.x;
    const int b   = blk >> 8;
    const int n0  = (blk & 255) << 4;

    for (int idx = tid; idx < 3072; idx += 256) {
        int co = idx / 96, rem = idx % 96;
        tw0[rem * 33 + co] = tc0_w[idx];
        tw1[rem * 33 + co] = tc1_w[idx];
    }
    for (int idx = tid; idx < 1024; idx += 256) {
        int o = idx >> 5, i = idx & 31;
        ow[i * 33 + o] = op_w[idx];
    }
    for (int idx = tid; idx < 640; idx += 256) {
        int rr = idx >> 5, c = idx & 31;
        int gn = n0 - 2 + rr;
        float val = 0.f;
        if (gn >= 0 && gn < N_) {
            int head = c >> 3, e = c & 7;
            size_t r0 = ((size_t)(b * 4 + head) * N_ + gn);
            size_t r1 = ((size_t)(BH_ + b * 4 + head) * N_ + gn);
            float num = d_patt[r0 * 8 + e] + d_patt[r1 * 8 + e];
            float den = d_pl[r0] + d_pl[r1];
            val = __fdividef(num, den);
        }
        at[rr * 33 + c] = val;
    }
    __syncthreads();

    const int w = tid >> 5, lane = tid & 31;

    // op projection for the block's 20 halo rows
    for (int r = w; r < 20; r += 8) {
        int gn = n0 - 2 + r;
        float o = 0.f;
        if (gn >= 0 && gn < N_) {
            o = __ldg(op_b + lane);
#pragma unroll
            for (int i = 0; i < 32; i++)
                o += at[r * 33 + i] * ow[i * 33 + lane];
        }
        ss[r * 32 + lane] = o;
    }
    __syncthreads();

    const float b0 = __ldg(tc0_b + lane), b1 = __ldg(tc1_b + lane);

    float v0[2], v1[2];
#pragma unroll
    for (int t = 0; t < 2; t++) { v0[t] = b0; v1[t] = b1; }

#pragma unroll 8
    for (int ci = 0; ci < 32; ci++) {
        float w00 = tw0[(ci * 3 + 0) * 33 + lane];
        float w01 = tw0[(ci * 3 + 1) * 33 + lane];
        float w02 = tw0[(ci * 3 + 2) * 33 + lane];
        float w10 = tw1[(ci * 3 + 0) * 33 + lane];
        float w11 = tw1[(ci * 3 + 1) * 33 + lane];
        float w12 = tw1[(ci * 3 + 2) * 33 + lane];
#pragma unroll
        for (int t = 0; t < 2; t++) {
            int lr = w * 2 + t + 2;
            float sm2 = ss[(lr - 2) * 32 + ci];
            float sm1 = ss[(lr - 1) * 32 + ci];
            float s0  = ss[lr * 32 + ci];
            float sp1 = ss[(lr + 1) * 32 + ci];
            float sp2 = ss[(lr + 2) * 32 + ci];
            v0[t] += sm1 * w00 + s0 * w01 + sp1 * w02;
            v1[t] += sm2 * w10 + s0 * w11 + sp2 * w12;
        }
    }

    const float bs = __ldg(bn_g + lane) * rsqrtf(1.f + 1e-5f);
    const float bb = __ldg(bn_b + lane);
    const float lng = __ldg(ln_g + lane), lnb = __ldg(ln_b + lane);

#pragma unroll
    for (int t = 0; t < 2; t++) {
        const int lr = w * 2 + t + 2;
        const int n = n0 + w * 2 + t;
        float y0 = fmaxf(v0[t] * bs + bb, 0.f);
        float y1 = fmaxf(v1[t] * bs + bb, 0.f);
        float resid = 0.5f * (y0 + y1) + ss[lr * 32 + lane];

        float sum = resid, sq = resid * resid;
#pragma unroll
        for (int off = 16; off; off >>= 1) {
            sum += __shfl_xor_sync(0xffffffffu, sum, off);
            sq  += __shfl_xor_sync(0xffffffffu, sq, off);
        }
        float mu = sum * (1.f / 32.f);
        float var = sq * (1.f / 32.f) - mu * mu;
        float rstd = rsqrtf(var + 1e-5f);
        float tout = (resid - mu) * rstd * lng + lnb;

        float hj[8];
#pragma unroll
        for (int j = 0; j < 8; j++) hj[j] = tout * __ldg(h1_w + j * 32 + lane);
#pragma unroll
        for (int j = 0; j < 8; j++)
#pragma unroll
            for (int off = 16; off; off >>= 1)
                hj[j] += __shfl_xor_sync(0xffffffffu, hj[j], off);

        float hsum = 0.f;
#pragma unroll
        for (int j = 0; j < 8; j++) { hj[j] += __ldg(h1_b + j); hsum += hj[j]; }
        float hmu = hsum * (1.f / 8.f);
        float hsq = 0.f;
#pragma unroll
        for (int j = 0; j < 8; j++) { float dd = hj[j] - hmu; hsq += dd * dd; }
        float hrstd = rsqrtf(hsq * (1.f / 8.f) + 1e-5f);
        float hh[8];
#pragma unroll
        for (int j = 0; j < 8; j++)
            hh[j] = fmaxf((hj[j] - hmu) * hrstd * __ldg(hln_g + j) + __ldg(hln_b + j), 0.f);

        if (lane < HOR_) {
            float p = __ldg(h2_b + lane);
#pragma unroll
            for (int j = 0; j < 8; j++) p += hh[j] * __ldg(h2_w + lane * 8 + j);
            out[(size_t)b * HOR_ * N_ + (size_t)lane * N_ + n] = p;
        }
    }
}

// =====================================================================
extern "C" void kernel_launch(void* const* d_in, const int* in_sizes, int n_in,
                              void* d_out, int out_size)
{
    const float* x      = (const float*)d_in[0];
    const float* fe_w   = (const float*)d_in[1];
    const float* fe_b   = (const float*)d_in[2];
    const float* fe_bng = (const float*)d_in[3];
    const float* fe_bnb = (const float*)d_in[4];
    const float* p1_w   = (const float*)d_in[5];
    const float* p1_b   = (const float*)d_in[6];
    const float* p2_w   = (const float*)d_in[7];
    const float* p2_b   = (const float*)d_in[8];
    const float* qkv_w  = (const float*)d_in[9];
    const float* qkv_b  = (const float*)d_in[10];
    const float* op_w   = (const float*)d_in[11];
    const float* op_b   = (const float*)d_in[12];
    const float* u      = (const float*)d_in[13];
    const float* v      = (const float*)d_in[14];
    const float* tc0_w  = (const float*)d_in[15];
    const float* tc0_b  = (const float*)d_in[16];
    const float* tc1_w  = (const float*)d_in[17];
    const float* tc1_b  = (const float*)d_in[18];
    const float* t_bng  = (const float*)d_in[19];
    const float* t_bnb  = (const float*)d_in[20];
    const float* t_lng  = (const float*)d_in[21];
    const float* t_lnb  = (const float*)d_in[22];
    const float* h1_w   = (const float*)d_in[23];
    const float* h1_b   = (const float*)d_in[24];
    const float* h_lng  = (const float*)d_in[25];
    const float* h_lnb  = (const float*)d_in[26];
    const float* h2_w   = (const float*)d_in[27];
    const float* h2_b   = (const float*)d_in[28];
    float* out = (float*)d_out;

    feat_kernel<<<(B_ * N_) / 8, 256>>>(x, fe_w, fe_b, fe_bng, fe_bnb,
                                        p1_w, p1_b, p2_w, p2_b,
                                        qkv_w, qkv_b, u, v);

    dim3 agrid(N_ / 64, BH_, KSPLIT);       // (64, 8, 2) = 1024 blocks
    attn_kernel<<<agrid, 128>>>();

    tail_kernel<<<(B_ * N_) / 16, 256>>>(op_w, op_b,
                                         tc0_w, tc0_b, tc1_w, tc1_b,
                                         t_bng, t_bnb, t_lng, t_lnb,
                                         h1_w, h1_b, h_lng, h_lnb,
                                         h2_w, h2_b, out);
}

// round 11
// speedup vs baseline: 2.9337x; 1.0138x over previous
#include <cuda_runtime.h>
#include <cuda_bf16.h>
#include <math.h>

// ---------------- problem constants ----------------
#define B_    2
#define T_    64
#define N_    4096
#define HOR_  24
#define C_    16
#define HID_  32
#define BD_   8
#define HEADS_ 4
#define HD_   8
#define BH_   (B_*HEADS_)      // 8
#define LOG2E 1.4426950408889634f
#define INV_SQRT8 0.35355339059327373f
#define KSPLIT 2

// ---------------- scratch (device globals; no allocation) ----------------
__device__ __align__(16) __nv_bfloat16 d_Qh[BH_ * N_ * 16];
__device__ __align__(16) __nv_bfloat16 d_Ql[BH_ * N_ * 16];
__device__ __align__(16) __nv_bfloat16 d_Kh[BH_ * N_ * 16];
__device__ __align__(16) __nv_bfloat16 d_Kl[BH_ * N_ * 16];
__device__ __align__(16) __nv_bfloat16 d_Vh[BH_ * N_ * 8];
__device__ __align__(16) __nv_bfloat16 d_Vl[BH_ * N_ * 8];
__device__ float d_patt[KSPLIT * BH_ * N_ * 8];   // unnormalized partial O
__device__ float d_pl[KSPLIT * BH_ * N_];         // partial row sums

__device__ __forceinline__ float ex2f(float x) {
    float y; asm("ex2.approx.ftz.f32 %0, %1;" : "=f"(y) : "f"(x)); return y;
}
__device__ __forceinline__ float elu1(float x) {
    return x > 0.f ? x + 1.f : __expf(x);
}
__device__ __forceinline__ void bsplit(float x, __nv_bfloat16& hi, __nv_bfloat16& lo) {
    __nv_bfloat16 h = __float2bfloat16(x);
    hi = h;
    lo = __float2bfloat16(x - __bfloat162float(h));
}

// bf16 m16n8k16 mma, fp32 accumulate
__device__ __forceinline__ void mma16816(float d[4], const unsigned a[4],
                                         const unsigned b[2], const float c[4]) {
    asm volatile(
        "mma.sync.aligned.m16n8k16.row.col.f32.bf16.bf16.f32 "
        "{%0,%1,%2,%3}, {%4,%5,%6,%7}, {%8,%9}, {%10,%11,%12,%13};"
        : "=f"(d[0]), "=f"(d[1]), "=f"(d[2]), "=f"(d[3])
        : "r"(a[0]), "r"(a[1]), "r"(a[2]), "r"(a[3]),
          "r"(b[0]), "r"(b[1]),
          "f"(c[0]), "f"(c[1]), "f"(c[2]), "f"(c[3]));
}

// pack two fp32 -> bf16x2 hi/lo split
__device__ __forceinline__ void split2(float x, float y, unsigned& hi, unsigned& lo) {
    __nv_bfloat162 h2 = __floats2bfloat162_rn(x, y);
    hi = *(unsigned*)&h2;
    __nv_bfloat162 l2 = __floats2bfloat162_rn(x - __bfloat162float(h2.x),
                                              y - __bfloat162float(h2.y));
    lo = *(unsigned*)&l2;
}

// =====================================================================
// Kernel A: conv -> p1 -> p2 -> qkv -> split-bf16 Q'/K'/V
// 2 nodes per warp, 16 nodes/block; phase-aliased smem:
//   phase 1: xs | cw | csh | p1s        (37248 B)
//   phase 2: xs | cw | csh | wt | fs    (wt+fs alias the p1s region)
// =====================================================================
#define XS_OFF  0                       // float[16][66]  = 4224 B
#define CW_OFF  4224                    // float[48]      = 192 B
#define CSH_OFF 4416                    // float[16]      = 64 B
#define P1_OFF  4480                    // float[8192]    = 32768 B  (phase 1)
#define WT_OFF  4480                    // float[32*97]   = 12416 B  (phase 2)
#define FS_OFF  16896                   // float[16][32]  = 2048 B   (phase 2)
#define FEAT_SMEM 37248

__global__ void __launch_bounds__(256)
feat_kernel(const float* __restrict__ x,
            const float* __restrict__ fe_w, const float* __restrict__ fe_b,
            const float* __restrict__ bn_g, const float* __restrict__ bn_b,
            const float* __restrict__ p1_w, const float* __restrict__ p1_b,
            const float* __restrict__ p2_w, const float* __restrict__ p2_b,
            const float* __restrict__ qkv_w, const float* __restrict__ qkv_b,
            const float* __restrict__ u, const float* __restrict__ v)
{
    __shared__ __align__(16) char sbuf[FEAT_SMEM];
    float* xsf  = (float*)(sbuf + XS_OFF);      // [16][66]
    float* cw   = (float*)(sbuf + CW_OFF);
    float* csh  = (float*)(sbuf + CSH_OFF);
    float* p1s  = (float*)(sbuf + P1_OFF);
    float* wt   = (float*)(sbuf + WT_OFF);
    float* fsf  = (float*)(sbuf + FS_OFF);      // [16][32]

    const int tid = threadIdx.x;
    const int blk = blockIdx.x;
    const int b   = blk >> 8;
    const int n0  = (blk & 255) << 4;

    // ---- phase 1 staging ----
    for (int i = tid; i < 2048; i += 256)
        ((float4*)p1s)[i] = ((const float4*)p1_w)[i];
    if (tid < 48) {
        int c = tid / 3;
        float sc = bn_g[c] * rsqrtf(1.f + 1e-5f);
        cw[tid] = fe_w[tid] * sc;
    }
    if (tid < 16) {
        float sc = bn_g[tid] * rsqrtf(1.f + 1e-5f);
        csh[tid] = fe_b[tid] * sc + bn_b[tid];
    }
    for (int i = tid; i < 1024; i += 256) {
        int node = i & 15, t = i >> 4;
        xsf[node * 66 + t + 1] = x[(size_t)b * T_ * N_ + (size_t)t * N_ + n0 + node];
    }
    if (tid < 16) { xsf[tid * 66] = 0.f; xsf[tid * 66 + 65] = 0.f; }
    __syncthreads();

    const int w = tid >> 5, lane = tid & 31;
    const int nA = n0 + 2 * w, nB = nA + 1;

    // hoist conv inputs for both nodes into registers
    const float* xA = xsf + (2 * w) * 66;
    const float* xB = xsf + (2 * w + 1) * 66;
    const float a0 = xA[lane],      a1 = xA[lane + 1],  a2 = xA[lane + 2];
    const float a3 = xA[lane + 32], a4 = xA[lane + 33], a5 = xA[lane + 34];
    const float c0 = xB[lane],      c1 = xB[lane + 1],  c2 = xB[lane + 2];
    const float c3 = xB[lane + 32], c4_ = xB[lane + 33], c5 = xB[lane + 34];

    float accA[8], accB[8];
#pragma unroll
    for (int j = 0; j < 8; j++) { accA[j] = 0.f; accB[j] = 0.f; }

#pragma unroll
    for (int i = 0; i < 32; i++) {
        int cc = i >> 1;
        float w0 = cw[cc * 3], w1 = cw[cc * 3 + 1], w2 = cw[cc * 3 + 2], sh = csh[cc];
        float valA, valB;
        if ((i & 1) == 0) {
            valA = a0 * w0 + a1 * w1 + a2 * w2 + sh;
            valB = c0 * w0 + c1 * w1 + c2 * w2 + sh;
        } else {
            valA = a3 * w0 + a4 * w1 + a5 * w2 + sh;
            valB = c3 * w0 + c4_ * w1 + c5 * w2 + sh;
        }
        valA = fmaxf(valA, 0.f);
        valB = fmaxf(valB, 0.f);
        int base = i * 32 + lane;
#pragma unroll
        for (int j = 0; j < 8; j++) {
            float pw = p1s[j * 1024 + base];
            accA[j] += valA * pw;
            accB[j] += valB * pw;
        }
    }
#pragma unroll
    for (int j = 0; j < 8; j++)
#pragma unroll
        for (int off = 16; off; off >>= 1) {
            accA[j] += __shfl_xor_sync(0xffffffffu, accA[j], off);
            accB[j] += __shfl_xor_sync(0xffffffffu, accB[j], off);
        }

    float r1A[8], r1B[8];
#pragma unroll
    for (int j = 0; j < 8; j++) {
        float pb = __ldg(p1_b + j);
        r1A[j] = fmaxf(accA[j] + pb, 0.f);
        r1B[j] = fmaxf(accB[j] + pb, 0.f);
    }

    float fA = __ldg(p2_b + lane), fB = fA;
#pragma unroll
    for (int j = 0; j < 8; j++) {
        float pw = __ldg(p2_w + lane * 8 + j);
        fA += r1A[j] * pw;
        fB += r1B[j] * pw;
    }

    // ---- phase 2: all p1s reads done; alias wt/fs into its region ----
    __syncthreads();
    for (int idx = tid; idx < 3072; idx += 256) {
        int o = idx >> 5, i = idx & 31;
        wt[i * 97 + o] = qkv_w[idx];
    }
    fsf[(2 * w) * 32 + lane] = fA;
    fsf[(2 * w + 1) * 32 + lane] = fB;
    __syncthreads();

    float oqA = __ldg(qkv_b + lane),      oqB = oqA;
    float okA = __ldg(qkv_b + lane + 32), okB = okA;
    float ovA = __ldg(qkv_b + lane + 64), ovB = ovA;
#pragma unroll
    for (int i = 0; i < 32; i++) {
        float fiA = fsf[(2 * w) * 32 + i];
        float fiB = fsf[(2 * w + 1) * 32 + i];
        const float* wr = wt + i * 97;
        float wq = wr[lane], wk = wr[lane + 32], wv = wr[lane + 64];
        oqA += fiA * wq; oqB += fiB * wq;
        okA += fiA * wk; okB += fiB * wk;
        ovA += fiA * wv; ovB += fiB * wv;
    }

    const int head = lane >> 3, d = lane & 7;
    {
        const size_t ridx = ((size_t)(b * 4 + head) * N_ + nA);
        const size_t qidx = ridx * 16;
        bsplit(elu1(oqA) * (LOG2E * INV_SQRT8), d_Qh[qidx + d],     d_Ql[qidx + d]);
        bsplit(u[(size_t)nA * 8 + d] * LOG2E,   d_Qh[qidx + 8 + d], d_Ql[qidx + 8 + d]);
        bsplit(elu1(okA),                       d_Kh[qidx + d],     d_Kl[qidx + d]);
        bsplit(v[(size_t)d * N_ + nA],          d_Kh[qidx + 8 + d], d_Kl[qidx + 8 + d]);
        bsplit(ovA, d_Vh[ridx * 8 + d], d_Vl[ridx * 8 + d]);
    }
    {
        const size_t ridx = ((size_t)(b * 4 + head) * N_ + nB);
        const size_t qidx = ridx * 16;
        bsplit(elu1(oqB) * (LOG2E * INV_SQRT8), d_Qh[qidx + d],     d_Ql[qidx + d]);
        bsplit(u[(size_t)nB * 8 + d] * LOG2E,   d_Qh[qidx + 8 + d], d_Ql[qidx + 8 + d]);
        bsplit(elu1(okB),                       d_Kh[qidx + d],     d_Kl[qidx + d]);
        bsplit(v[(size_t)d * N_ + nB],          d_Kh[qidx + 8 + d], d_Kl[qidx + 8 + d]);
        bsplit(ovB, d_Vh[ridx * 8 + d], d_Vl[ridx * 8 + d]);
    }
}

// =====================================================================
// Kernel B: tensor-core flash attention, split-K=2, row-sum via ones-mma
// grid (N/64, BH, KSPLIT), 128 threads = 4 warps
// =====================================================================
#define KTILE 128
__global__ void __launch_bounds__(128)
attn_kernel()
{
    const int bh = blockIdx.y;
    const int qbase = blockIdx.x * 64;
    const int kz = blockIdx.z;
    const int tid = threadIdx.x, w = tid >> 5, l = tid & 31;

    __shared__ __align__(16) unsigned Khl[KTILE * 16];
    __shared__ __align__(16) unsigned Vhl[8 * 144];

    const unsigned* Qh_u = (const unsigned*)d_Qh + (size_t)bh * N_ * 8;
    const unsigned* Ql_u = (const unsigned*)d_Ql + (size_t)bh * N_ * 8;
    const unsigned* Kh_u = (const unsigned*)d_Kh + (size_t)bh * N_ * 8;
    const unsigned* Kl_u = (const unsigned*)d_Kl + (size_t)bh * N_ * 8;
    const __nv_bfloat16* Vh_g = d_Vh + (size_t)bh * N_ * 8;
    const __nv_bfloat16* Vl_g = d_Vl + (size_t)bh * N_ * 8;

    const int qr0 = qbase + w * 16 + (l >> 2);
    const int qr1 = qr0 + 8;
    const int c4 = l & 3;

    unsigned ah[4], al[4];
    ah[0] = Qh_u[qr0 * 8 + c4];     ah[1] = Qh_u[qr1 * 8 + c4];
    ah[2] = Qh_u[qr0 * 8 + c4 + 4]; ah[3] = Qh_u[qr1 * 8 + c4 + 4];
    al[0] = Ql_u[qr0 * 8 + c4];     al[1] = Ql_u[qr1 * 8 + c4];
    al[2] = Ql_u[qr0 * 8 + c4 + 4]; al[3] = Ql_u[qr1 * 8 + c4 + 4];

    float O[4] = {0.f, 0.f, 0.f, 0.f};
    float Ol[4] = {0.f, 0.f, 0.f, 0.f};     // row-sum accumulator
    const unsigned ones2 = 0x3F803F80u;     // bf16x2 {1.0, 1.0}
    unsigned bones[2] = {ones2, ones2};

    __nv_bfloat16* Vsh = (__nv_bfloat16*)Vhl;

    const int k0 = kz * (N_ / KSPLIT);
    for (int kt = k0; kt < k0 + N_ / KSPLIT; kt += KTILE) {
        __syncthreads();
#pragma unroll
        for (int i = 0; i < 4; i++) {
            int idx = tid + i * 128;
            int key = idx >> 2, kc = idx & 3;
            unsigned h0 = Kh_u[(size_t)(kt + key) * 8 + kc];
            unsigned h4 = Kh_u[(size_t)(kt + key) * 8 + kc + 4];
            unsigned l0 = Kl_u[(size_t)(kt + key) * 8 + kc];
            unsigned l4 = Kl_u[(size_t)(kt + key) * 8 + kc + 4];
            *(uint4*)&Khl[key * 16 + kc * 4] = make_uint4(h0, h4, l0, l4);
        }
#pragma unroll
        for (int i = 0; i < 8; i++) {
            int idx = tid + i * 128;
            int key = idx >> 3, vd = idx & 7;
            int j = key >> 1, half = key & 1;
            int ci = j >> 3, c4v = j & 3, hi4 = (j >> 2) & 1;
            int base_u = vd * 144 + ci * 16 + c4v * 4;
            Vsh[2 * (base_u + hi4) + half]     = Vh_g[(size_t)(kt + key) * 8 + vd];
            Vsh[2 * (base_u + 2 + hi4) + half] = Vl_g[(size_t)(kt + key) * 8 + vd];
        }
        __syncthreads();

#pragma unroll
        for (int c16 = 0; c16 < KTILE; c16 += 16) {
            float S0[4] = {0.f, 0.f, 0.f, 0.f};
            float S1[4] = {0.f, 0.f, 0.f, 0.f};

            const int kr0 = c16 + (l >> 2);
            const int kr1 = kr0 + 8;
            uint4 k0v = *(const uint4*)&Khl[kr0 * 16 + c4 * 4];
            uint4 k1v = *(const uint4*)&Khl[kr1 * 16 + c4 * 4];
            unsigned kh0[2] = {k0v.x, k0v.y}, kl0[2] = {k0v.z, k0v.w};
            unsigned kh1[2] = {k1v.x, k1v.y}, kl1[2] = {k1v.z, k1v.w};

            mma16816(S0, ah, kh0, S0);
            mma16816(S0, al, kh0, S0);
            mma16816(S0, ah, kl0, S0);
            mma16816(S1, ah, kh1, S1);
            mma16816(S1, al, kh1, S1);
            mma16816(S1, ah, kl1, S1);

            float p00 = ex2f(S0[0]), p01 = ex2f(S0[1]);
            float p02 = ex2f(S0[2]), p03 = ex2f(S0[3]);
            float p10 = ex2f(S1[0]), p11 = ex2f(S1[1]);
            float p12 = ex2f(S1[2]), p13 = ex2f(S1[3]);

            unsigned pa_h[4], pa_l[4];
            split2(p00, p01, pa_h[0], pa_l[0]);
            split2(p02, p03, pa_h[1], pa_l[1]);
            split2(p10, p11, pa_h[2], pa_l[2]);
            split2(p12, p13, pa_h[3], pa_l[3]);

            uint4 vv = *(const uint4*)&Vhl[(l >> 2) * 144 + (c16 >> 4) * 16 + c4 * 4];
            unsigned vh[2] = {vv.x, vv.y}, vl[2] = {vv.z, vv.w};

            mma16816(O, pa_h, vh, O);
            mma16816(O, pa_l, vh, O);
            mma16816(O, pa_h, vl, O);
            mma16816(Ol, pa_h, bones, Ol);     // row sums ride the tensor pipe
            mma16816(Ol, pa_l, bones, Ol);
        }
    }

    const size_t pbase = (size_t)(kz * BH_ + bh) * N_;
    float* o0 = d_patt + (pbase + qr0) * 8 + 2 * c4;
    float* o1 = d_patt + (pbase + qr1) * 8 + 2 * c4;
    o0[0] = O[0]; o0[1] = O[1];
    o1[0] = O[2]; o1[1] = O[3];
    if (c4 == 0) {
        d_pl[pbase + qr0] = Ol[0];
        d_pl[pbase + qr1] = Ol[2];
    }
}

// =====================================================================
// Kernel C: fused split-combine + op-projection + dilated convs + BN +
//           residual LN + horizon MLP. 16 nodes/block.
// =====================================================================
__global__ void __launch_bounds__(256)
tail_kernel(const float* __restrict__ op_w, const float* __restrict__ op_b,
            const float* __restrict__ tc0_w, const float* __restrict__ tc0_b,
            const float* __restrict__ tc1_w, const float* __restrict__ tc1_b,
            const float* __restrict__ bn_g, const float* __restrict__ bn_b,
            const float* __restrict__ ln_g, const float* __restrict__ ln_b,
            const float* __restrict__ h1_w, const float* __restrict__ h1_b,
            const float* __restrict__ hln_g, const float* __restrict__ hln_b,
            const float* __restrict__ h2_w, const float* __restrict__ h2_b,
            float* __restrict__ out)
{
    __shared__ float ss[20 * 32];
    __shared__ float at[20 * 33];
    __shared__ float ow[32 * 33];
    __shared__ float tw0[96 * 33];
    __shared__ float tw1[96 * 33];

    const int tid = threadIdx.x;
    const int blk = blockIdx.x;
    const int b   = blk >> 8;
    const int n0  = (blk & 255) << 4;

    for (int idx = tid; idx < 3072; idx += 256) {
        int co = idx / 96, rem = idx % 96;
        tw0[rem * 33 + co] = tc0_w[idx];
        tw1[rem * 33 + co] = tc1_w[idx];
    }
    for (int idx = tid; idx < 1024; idx += 256) {
        int o = idx >> 5, i = idx & 31;
        ow[i * 33 + o] = op_w[idx];
    }
    for (int idx = tid; idx < 640; idx += 256) {
        int rr = idx >> 5, c = idx & 31;
        int gn = n0 - 2 + rr;
        float val = 0.f;
        if (gn >= 0 && gn < N_) {
            int head = c >> 3, e = c & 7;
            size_t r0 = ((size_t)(b * 4 + head) * N_ + gn);
            size_t r1 = ((size_t)(BH_ + b * 4 + head) * N_ + gn);
            float num = d_patt[r0 * 8 + e] + d_patt[r1 * 8 + e];
            float den = d_pl[r0] + d_pl[r1];
            val = __fdividef(num, den);
        }
        at[rr * 33 + c] = val;
    }
    __syncthreads();

    const int w = tid >> 5, lane = tid & 31;

    for (int r = w; r < 20; r += 8) {
        int gn = n0 - 2 + r;
        float o = 0.f;
        if (gn >= 0 && gn < N_) {
            o = __ldg(op_b + lane);
#pragma unroll
            for (int i = 0; i < 32; i++)
                o += at[r * 33 + i] * ow[i * 33 + lane];
        }
        ss[r * 32 + lane] = o;
    }
    __syncthreads();

    const float b0 = __ldg(tc0_b + lane), b1 = __ldg(tc1_b + lane);

    float v0[2], v1[2];
#pragma unroll
    for (int t = 0; t < 2; t++) { v0[t] = b0; v1[t] = b1; }

#pragma unroll 8
    for (int ci = 0; ci < 32; ci++) {
        float w00 = tw0[(ci * 3 + 0) * 33 + lane];
        float w01 = tw0[(ci * 3 + 1) * 33 + lane];
        float w02 = tw0[(ci * 3 + 2) * 33 + lane];
        float w10 = tw1[(ci * 3 + 0) * 33 + lane];
        float w11 = tw1[(ci * 3 + 1) * 33 + lane];
        float w12 = tw1[(ci * 3 + 2) * 33 + lane];
#pragma unroll
        for (int t = 0; t < 2; t++) {
            int lr = w * 2 + t + 2;
            float sm2 = ss[(lr - 2) * 32 + ci];
            float sm1 = ss[(lr - 1) * 32 + ci];
            float s0  = ss[lr * 32 + ci];
            float sp1 = ss[(lr + 1) * 32 + ci];
            float sp2 = ss[(lr + 2) * 32 + ci];
            v0[t] += sm1 * w00 + s0 * w01 + sp1 * w02;
            v1[t] += sm2 * w10 + s0 * w11 + sp2 * w12;
        }
    }

    const float bs = __ldg(bn_g + lane) * rsqrtf(1.f + 1e-5f);
    const float bb = __ldg(bn_b + lane);
    const float lng = __ldg(ln_g + lane), lnb = __ldg(ln_b + lane);

#pragma unroll
    for (int t = 0; t < 2; t++) {
        const int lr = w * 2 + t + 2;
        const int n = n0 + w * 2 + t;
        float y0 = fmaxf(v0[t] * bs + bb, 0.f);
        float y1 = fmaxf(v1[t] * bs + bb, 0.f);
        float resid = 0.5f * (y0 + y1) + ss[lr * 32 + lane];

        float sum = resid, sq = resid * resid;
#pragma unroll
        for (int off = 16; off; off >>= 1) {
            sum += __shfl_xor_sync(0xffffffffu, sum, off);
            sq  += __shfl_xor_sync(0xffffffffu, sq, off);
        }
        float mu = sum * (1.f / 32.f);
        float var = sq * (1.f / 32.f) - mu * mu;
        float rstd = rsqrtf(var + 1e-5f);
        float tout = (resid - mu) * rstd * lng + lnb;

        float hj[8];
#pragma unroll
        for (int j = 0; j < 8; j++) hj[j] = tout * __ldg(h1_w + j * 32 + lane);
#pragma unroll
        for (int j = 0; j < 8; j++)
#pragma unroll
            for (int off = 16; off; off >>= 1)
                hj[j] += __shfl_xor_sync(0xffffffffu, hj[j], off);

        float hsum = 0.f;
#pragma unroll
        for (int j = 0; j < 8; j++) { hj[j] += __ldg(h1_b + j); hsum += hj[j]; }
        float hmu = hsum * (1.f / 8.f);
        float hsq = 0.f;
#pragma unroll
        for (int j = 0; j < 8; j++) { float dd = hj[j] - hmu; hsq += dd * dd; }
        float hrstd = rsqrtf(hsq * (1.f / 8.f) + 1e-5f);
        float hh[8];
#pragma unroll
        for (int j = 0; j < 8; j++)
            hh[j] = fmaxf((hj[j] - hmu) * hrstd * __ldg(hln_g + j) + __ldg(hln_b + j), 0.f);

        if (lane < HOR_) {
            float p = __ldg(h2_b + lane);
#pragma unroll
            for (int j = 0; j < 8; j++) p += hh[j] * __ldg(h2_w + lane * 8 + j);
            out[(size_t)b * HOR_ * N_ + (size_t)lane * N_ + n] = p;
        }
    }
}

// =====================================================================
extern "C" void kernel_launch(void* const* d_in, const int* in_sizes, int n_in,
                              void* d_out, int out_size)
{
    const float* x      = (const float*)d_in[0];
    const float* fe_w   = (const float*)d_in[1];
    const float* fe_b   = (const float*)d_in[2];
    const float* fe_bng = (const float*)d_in[3];
    const float* fe_bnb = (const float*)d_in[4];
    const float* p1_w   = (const float*)d_in[5];
    const float* p1_b   = (const float*)d_in[6];
    const float* p2_w   = (const float*)d_in[7];
    const float* p2_b   = (const float*)d_in[8];
    const float* qkv_w  = (const float*)d_in[9];
    const float* qkv_b  = (const float*)d_in[10];
    const float* op_w   = (const float*)d_in[11];
    const float* op_b   = (const float*)d_in[12];
    const float* u      = (const float*)d_in[13];
    const float* v      = (const float*)d_in[14];
    const float* tc0_w  = (const float*)d_in[15];
    const float* tc0_b  = (const float*)d_in[16];
    const float* tc1_w  = (const float*)d_in[17];
    const float* tc1_b  = (const float*)d_in[18];
    const float* t_bng  = (const float*)d_in[19];
    const float* t_bnb  = (const float*)d_in[20];
    const float* t_lng  = (const float*)d_in[21];
    const float* t_lnb  = (const float*)d_in[22];
    const float* h1_w   = (const float*)d_in[23];
    const float* h1_b   = (const float*)d_in[24];
    const float* h_lng  = (const float*)d_in[25];
    const float* h_lnb  = (const float*)d_in[26];
    const float* h2_w   = (const float*)d_in[27];
    const float* h2_b   = (const float*)d_in[28];
    float* out = (float*)d_out;

    feat_kernel<<<(B_ * N_) / 16, 256>>>(x, fe_w, fe_b, fe_bng, fe_bnb,
                                         p1_w, p1_b, p2_w, p2_b,
                                         qkv_w, qkv_b, u, v);

    dim3 agrid(N_ / 64, BH_, KSPLIT);       // (64, 8, 2) = 1024 blocks
    attn_kernel<<<agrid, 128>>>();

    tail_kernel<<<(B_ * N_) / 16, 256>>>(op_w, op_b,
                                         tc0_w, tc0_b, tc1_w, tc1_b,
                                         t_bng, t_bnb, t_lng, t_lnb,
                                         h1_w, h1_b, h_lng, h_lnb,
                                         h2_w, h2_b, out);
}

// round 12
// speedup vs baseline: 3.2512x; 1.1082x over previous
#include <cuda_runtime.h>
#include <cuda_bf16.h>
#include <math.h>

// ---------------- problem constants ----------------
#define B_    2
#define T_    64
#define N_    4096
#define HOR_  24
#define C_    16
#define HID_  32
#define BD_   8
#define HEADS_ 4
#define HD_   8
#define BH_   (B_*HEADS_)      // 8
#define LOG2E 1.4426950408889634f
#define INV_SQRT8 0.35355339059327373f
#define KSPLIT 2

// ---------------- scratch (device globals; no allocation) ----------------
__device__ __align__(16) __nv_bfloat16 d_Qh[BH_ * N_ * 16];
__device__ __align__(16) __nv_bfloat16 d_Ql[BH_ * N_ * 16];
__device__ __align__(16) __nv_bfloat16 d_Kh[BH_ * N_ * 16];
__device__ __align__(16) __nv_bfloat16 d_Kl[BH_ * N_ * 16];
__device__ __align__(16) __nv_bfloat16 d_Vh[BH_ * N_ * 8];
__device__ __align__(16) __nv_bfloat16 d_Vl[BH_ * N_ * 8];
__device__ float d_patt[KSPLIT * BH_ * N_ * 8];   // unnormalized partial O
__device__ float d_pl[KSPLIT * BH_ * N_];         // partial row sums

__device__ __forceinline__ float ex2f(float x) {
    float y; asm("ex2.approx.ftz.f32 %0, %1;" : "=f"(y) : "f"(x)); return y;
}
__device__ __forceinline__ float elu1(float x) {
    return x > 0.f ? x + 1.f : __expf(x);
}
__device__ __forceinline__ void bsplit(float x, __nv_bfloat16& hi, __nv_bfloat16& lo) {
    __nv_bfloat16 h = __float2bfloat16(x);
    hi = h;
    lo = __float2bfloat16(x - __bfloat162float(h));
}

// bf16 m16n8k16 mma, fp32 accumulate
__device__ __forceinline__ void mma16816(float d[4], const unsigned a[4],
                                         const unsigned b[2], const float c[4]) {
    asm volatile(
        "mma.sync.aligned.m16n8k16.row.col.f32.bf16.bf16.f32 "
        "{%0,%1,%2,%3}, {%4,%5,%6,%7}, {%8,%9}, {%10,%11,%12,%13};"
        : "=f"(d[0]), "=f"(d[1]), "=f"(d[2]), "=f"(d[3])
        : "r"(a[0]), "r"(a[1]), "r"(a[2]), "r"(a[3]),
          "r"(b[0]), "r"(b[1]),
          "f"(c[0]), "f"(c[1]), "f"(c[2]), "f"(c[3]));
}

// pack two fp32 -> bf16x2 hi/lo split
__device__ __forceinline__ void split2(float x, float y, unsigned& hi, unsigned& lo) {
    __nv_bfloat162 h2 = __floats2bfloat162_rn(x, y);
    hi = *(unsigned*)&h2;
    __nv_bfloat162 l2 = __floats2bfloat162_rn(x - __bfloat162float(h2.x),
                                              y - __bfloat162float(h2.y));
    lo = *(unsigned*)&l2;
}

// =====================================================================
// Kernel A: conv -> p1 -> p2 -> qkv -> split-bf16 Q'/K'/V
// 2 nodes per warp, 16 nodes/block; phase-aliased smem
// =====================================================================
#define XS_OFF  0                       // float[16][66]  = 4224 B
#define CW_OFF  4224                    // float[48]      = 192 B
#define CSH_OFF 4416                    // float[16]      = 64 B
#define P1_OFF  4480                    // float[8192]    = 32768 B  (phase 1)
#define WT_OFF  4480                    // float[32*97]   = 12416 B  (phase 2)
#define FS_OFF  16896                   // float[16][32]  = 2048 B   (phase 2)
#define FEAT_SMEM 37248

__global__ void __launch_bounds__(256)
feat_kernel(const float* __restrict__ x,
            const float* __restrict__ fe_w, const float* __restrict__ fe_b,
            const float* __restrict__ bn_g, const float* __restrict__ bn_b,
            const float* __restrict__ p1_w, const float* __restrict__ p1_b,
            const float* __restrict__ p2_w, const float* __restrict__ p2_b,
            const float* __restrict__ qkv_w, const float* __restrict__ qkv_b,
            const float* __restrict__ u, const float* __restrict__ v)
{
    __shared__ __align__(16) char sbuf[FEAT_SMEM];
    float* xsf  = (float*)(sbuf + XS_OFF);      // [16][66]
    float* cw   = (float*)(sbuf + CW_OFF);
    float* csh  = (float*)(sbuf + CSH_OFF);
    float* p1s  = (float*)(sbuf + P1_OFF);
    float* wt   = (float*)(sbuf + WT_OFF);
    float* fsf  = (float*)(sbuf + FS_OFF);      // [16][32]

    const int tid = threadIdx.x;
    const int blk = blockIdx.x;
    const int b   = blk >> 8;
    const int n0  = (blk & 255) << 4;

    for (int i = tid; i < 2048; i += 256)
        ((float4*)p1s)[i] = ((const float4*)p1_w)[i];
    if (tid < 48) {
        int c = tid / 3;
        float sc = bn_g[c] * rsqrtf(1.f + 1e-5f);
        cw[tid] = fe_w[tid] * sc;
    }
    if (tid < 16) {
        float sc = bn_g[tid] * rsqrtf(1.f + 1e-5f);
        csh[tid] = fe_b[tid] * sc + bn_b[tid];
    }
    for (int i = tid; i < 1024; i += 256) {
        int node = i & 15, t = i >> 4;
        xsf[node * 66 + t + 1] = x[(size_t)b * T_ * N_ + (size_t)t * N_ + n0 + node];
    }
    if (tid < 16) { xsf[tid * 66] = 0.f; xsf[tid * 66 + 65] = 0.f; }
    __syncthreads();

    const int w = tid >> 5, lane = tid & 31;
    const int nA = n0 + 2 * w, nB = nA + 1;

    const float* xA = xsf + (2 * w) * 66;
    const float* xB = xsf + (2 * w + 1) * 66;
    const float a0 = xA[lane],      a1 = xA[lane + 1],  a2 = xA[lane + 2];
    const float a3 = xA[lane + 32], a4 = xA[lane + 33], a5 = xA[lane + 34];
    const float c0 = xB[lane],      c1 = xB[lane + 1],  c2 = xB[lane + 2];
    const float c3 = xB[lane + 32], c4_ = xB[lane + 33], c5 = xB[lane + 34];

    float accA[8], accB[8];
#pragma unroll
    for (int j = 0; j < 8; j++) { accA[j] = 0.f; accB[j] = 0.f; }

#pragma unroll
    for (int i = 0; i < 32; i++) {
        int cc = i >> 1;
        float w0 = cw[cc * 3], w1 = cw[cc * 3 + 1], w2 = cw[cc * 3 + 2], sh = csh[cc];
        float valA, valB;
        if ((i & 1) == 0) {
            valA = a0 * w0 + a1 * w1 + a2 * w2 + sh;
            valB = c0 * w0 + c1 * w1 + c2 * w2 + sh;
        } else {
            valA = a3 * w0 + a4 * w1 + a5 * w2 + sh;
            valB = c3 * w0 + c4_ * w1 + c5 * w2 + sh;
        }
        valA = fmaxf(valA, 0.f);
        valB = fmaxf(valB, 0.f);
        int base = i * 32 + lane;
#pragma unroll
        for (int j = 0; j < 8; j++) {
            float pw = p1s[j * 1024 + base];
            accA[j] += valA * pw;
            accB[j] += valB * pw;
        }
    }
#pragma unroll
    for (int j = 0; j < 8; j++)
#pragma unroll
        for (int off = 16; off; off >>= 1) {
            accA[j] += __shfl_xor_sync(0xffffffffu, accA[j], off);
            accB[j] += __shfl_xor_sync(0xffffffffu, accB[j], off);
        }

    float r1A[8], r1B[8];
#pragma unroll
    for (int j = 0; j < 8; j++) {
        float pb = __ldg(p1_b + j);
        r1A[j] = fmaxf(accA[j] + pb, 0.f);
        r1B[j] = fmaxf(accB[j] + pb, 0.f);
    }

    float fA = __ldg(p2_b + lane), fB = fA;
#pragma unroll
    for (int j = 0; j < 8; j++) {
        float pw = __ldg(p2_w + lane * 8 + j);
        fA += r1A[j] * pw;
        fB += r1B[j] * pw;
    }

    __syncthreads();
    for (int idx = tid; idx < 3072; idx += 256) {
        int o = idx >> 5, i = idx & 31;
        wt[i * 97 + o] = qkv_w[idx];
    }
    fsf[(2 * w) * 32 + lane] = fA;
    fsf[(2 * w + 1) * 32 + lane] = fB;
    __syncthreads();

    float oqA = __ldg(qkv_b + lane),      oqB = oqA;
    float okA = __ldg(qkv_b + lane + 32), okB = okA;
    float ovA = __ldg(qkv_b + lane + 64), ovB = ovA;
#pragma unroll
    for (int i = 0; i < 32; i++) {
        float fiA = fsf[(2 * w) * 32 + i];
        float fiB = fsf[(2 * w + 1) * 32 + i];
        const float* wr = wt + i * 97;
        float wq = wr[lane], wk = wr[lane + 32], wv = wr[lane + 64];
        oqA += fiA * wq; oqB += fiB * wq;
        okA += fiA * wk; okB += fiB * wk;
        ovA += fiA * wv; ovB += fiB * wv;
    }

    const int head = lane >> 3, d = lane & 7;
    {
        const size_t ridx = ((size_t)(b * 4 + head) * N_ + nA);
        const size_t qidx = ridx * 16;
        bsplit(elu1(oqA) * (LOG2E * INV_SQRT8), d_Qh[qidx + d],     d_Ql[qidx + d]);
        bsplit(u[(size_t)nA * 8 + d] * LOG2E,   d_Qh[qidx + 8 + d], d_Ql[qidx + 8 + d]);
        bsplit(elu1(okA),                       d_Kh[qidx + d],     d_Kl[qidx + d]);
        bsplit(v[(size_t)d * N_ + nA],          d_Kh[qidx + 8 + d], d_Kl[qidx + 8 + d]);
        bsplit(ovA, d_Vh[ridx * 8 + d], d_Vl[ridx * 8 + d]);
    }
    {
        const size_t ridx = ((size_t)(b * 4 + head) * N_ + nB);
        const size_t qidx = ridx * 16;
        bsplit(elu1(oqB) * (LOG2E * INV_SQRT8), d_Qh[qidx + d],     d_Ql[qidx + d]);
        bsplit(u[(size_t)nB * 8 + d] * LOG2E,   d_Qh[qidx + 8 + d], d_Ql[qidx + 8 + d]);
        bsplit(elu1(okB),                       d_Kh[qidx + d],     d_Kl[qidx + d]);
        bsplit(v[(size_t)d * N_ + nB],          d_Kh[qidx + 8 + d], d_Kl[qidx + 8 + d]);
        bsplit(ovB, d_Vh[ridx * 8 + d], d_Vl[ridx * 8 + d]);
    }
}

// =====================================================================
// Kernel B: tensor-core flash attention, split-K=2, ones-mma row sums
// 256 threads = 8 warps, 128 q-rows/block; double-buffered KTILE with
// register prefetch and ONE __syncthreads per tile.
// grid (N/128, BH, KSPLIT) = (32, 8, 2) = 512 blocks
// =====================================================================
#define KTILE 128
#define NIT   ((N_ / KSPLIT) / KTILE)   // 16
__global__ void __launch_bounds__(256)
attn_kernel()
{
    const int bh = blockIdx.y;
    const int qbase = blockIdx.x * 128;
    const int kz = blockIdx.z;
    const int tid = threadIdx.x, w = tid >> 5, l = tid & 31;

    __shared__ __align__(16) unsigned Khl[2][KTILE * 16];   // 16 KB
    __shared__ __align__(16) unsigned Vhl[2][8 * 144];      // 9.2 KB

    const unsigned* Qh_u = (const unsigned*)d_Qh + (size_t)bh * N_ * 8;
    const unsigned* Ql_u = (const unsigned*)d_Ql + (size_t)bh * N_ * 8;
    const unsigned* Kh_u = (const unsigned*)d_Kh + (size_t)bh * N_ * 8;
    const unsigned* Kl_u = (const unsigned*)d_Kl + (size_t)bh * N_ * 8;
    const __nv_bfloat16* Vh_g = d_Vh + (size_t)bh * N_ * 8;
    const __nv_bfloat16* Vl_g = d_Vl + (size_t)bh * N_ * 8;

    const int qr0 = qbase + w * 16 + (l >> 2);
    const int qr1 = qr0 + 8;
    const int c4 = l & 3;

    unsigned ah[4], al[4];
    ah[0] = Qh_u[qr0 * 8 + c4];     ah[1] = Qh_u[qr1 * 8 + c4];
    ah[2] = Qh_u[qr0 * 8 + c4 + 4]; ah[3] = Qh_u[qr1 * 8 + c4 + 4];
    al[0] = Ql_u[qr0 * 8 + c4];     al[1] = Ql_u[qr1 * 8 + c4];
    al[2] = Ql_u[qr0 * 8 + c4 + 4]; al[3] = Ql_u[qr1 * 8 + c4 + 4];

    float O[4] = {0.f, 0.f, 0.f, 0.f};
    float Ol[4] = {0.f, 0.f, 0.f, 0.f};
    const unsigned ones2 = 0x3F803F80u;
    unsigned bones[2] = {ones2, ones2};

    // staging registers (per thread: K 2 records, V 4 items)
    unsigned kreg[2][4];
    __nv_bfloat16 vreg[4][2];

    const int kkey0 = tid >> 2, kkc = tid & 3;        // K record 0
    const int kkey1 = (tid + 256) >> 2;               // K record 1 (same kc)
    const int vkey0 = tid >> 3, vvd = tid & 7;

    const int k0 = kz * (N_ / KSPLIT);

    // LDG a tile into registers
    auto ldg_tile = [&](int kt) {
        kreg[0][0] = Kh_u[(size_t)(kt + kkey0) * 8 + kkc];
        kreg[0][1] = Kh_u[(size_t)(kt + kkey0) * 8 + kkc + 4];
        kreg[0][2] = Kl_u[(size_t)(kt + kkey0) * 8 + kkc];
        kreg[0][3] = Kl_u[(size_t)(kt + kkey0) * 8 + kkc + 4];
        kreg[1][0] = Kh_u[(size_t)(kt + kkey1) * 8 + kkc];
        kreg[1][1] = Kh_u[(size_t)(kt + kkey1) * 8 + kkc + 4];
        kreg[1][2] = Kl_u[(size_t)(kt + kkey1) * 8 + kkc];
        kreg[1][3] = Kl_u[(size_t)(kt + kkey1) * 8 + kkc + 4];
#pragma unroll
        for (int i = 0; i < 4; i++) {
            int key = vkey0 + i * 32;
            vreg[i][0] = Vh_g[(size_t)(kt + key) * 8 + vvd];
            vreg[i][1] = Vl_g[(size_t)(kt + key) * 8 + vvd];
        }
    };
    // STS registers into buffer bb
    auto sts_tile = [&](int bb) {
        *(uint4*)&Khl[bb][kkey0 * 16 + kkc * 4] =
            make_uint4(kreg[0][0], kreg[0][1], kreg[0][2], kreg[0][3]);
        *(uint4*)&Khl[bb][kkey1 * 16 + kkc * 4] =
            make_uint4(kreg[1][0], kreg[1][1], kreg[1][2], kreg[1][3]);
        __nv_bfloat16* Vsh = (__nv_bfloat16*)Vhl[bb];
#pragma unroll
        for (int i = 0; i < 4; i++) {
            int key = vkey0 + i * 32;
            int j = key >> 1, half = key & 1;
            int ci = j >> 3, c4v = j & 3, hi4 = (j >> 2) & 1;
            int base_u = vvd * 144 + ci * 16 + c4v * 4;
            Vsh[2 * (base_u + hi4) + half]     = vreg[i][0];
            Vsh[2 * (base_u + 2 + hi4) + half] = vreg[i][1];
        }
    };

    ldg_tile(k0);
    sts_tile(0);
    __syncthreads();

    for (int it = 0; it < NIT; it++) {
        const int bb = it & 1;
        if (it + 1 < NIT) ldg_tile(k0 + (it + 1) * KTILE);   // prefetch (latency hidden)

        const unsigned* Kb = Khl[bb];
        const unsigned* Vb = Vhl[bb];
#pragma unroll
        for (int c16 = 0; c16 < KTILE; c16 += 16) {
            float S0[4] = {0.f, 0.f, 0.f, 0.f};
            float S1[4] = {0.f, 0.f, 0.f, 0.f};

            const int kr0 = c16 + (l >> 2);
            const int kr1 = kr0 + 8;
            uint4 k0v = *(const uint4*)&Kb[kr0 * 16 + c4 * 4];
            uint4 k1v = *(const uint4*)&Kb[kr1 * 16 + c4 * 4];
            unsigned kh0[2] = {k0v.x, k0v.y}, kl0[2] = {k0v.z, k0v.w};
            unsigned kh1[2] = {k1v.x, k1v.y}, kl1[2] = {k1v.z, k1v.w};

            mma16816(S0, ah, kh0, S0);
            mma16816(S0, al, kh0, S0);
            mma16816(S0, ah, kl0, S0);
            mma16816(S1, ah, kh1, S1);
            mma16816(S1, al, kh1, S1);
            mma16816(S1, ah, kl1, S1);

            float p00 = ex2f(S0[0]), p01 = ex2f(S0[1]);
            float p02 = ex2f(S0[2]), p03 = ex2f(S0[3]);
            float p10 = ex2f(S1[0]), p11 = ex2f(S1[1]);
            float p12 = ex2f(S1[2]), p13 = ex2f(S1[3]);

            unsigned pa_h[4], pa_l[4];
            split2(p00, p01, pa_h[0], pa_l[0]);
            split2(p02, p03, pa_h[1], pa_l[1]);
            split2(p10, p11, pa_h[2], pa_l[2]);
            split2(p12, p13, pa_h[3], pa_l[3]);

            uint4 vv = *(const uint4*)&Vb[(l >> 2) * 144 + (c16 >> 4) * 16 + c4 * 4];
            unsigned vh[2] = {vv.x, vv.y}, vl[2] = {vv.z, vv.w};

            mma16816(O, pa_h, vh, O);
            mma16816(O, pa_l, vh, O);
            mma16816(O, pa_h, vl, O);
            mma16816(Ol, pa_h, bones, Ol);
            mma16816(Ol, pa_l, bones, Ol);
        }

        if (it + 1 < NIT) sts_tile(bb ^ 1);   // other buffer; fenced by prev sync
        __syncthreads();
    }

    const size_t pbase = (size_t)(kz * BH_ + bh) * N_;
    float* o0 = d_patt + (pbase + qr0) * 8 + 2 * c4;
    float* o1 = d_patt + (pbase + qr1) * 8 + 2 * c4;
    o0[0] = O[0]; o0[1] = O[1];
    o1[0] = O[2]; o1[1] = O[3];
    if (c4 == 0) {
        d_pl[pbase + qr0] = Ol[0];
        d_pl[pbase + qr1] = Ol[2];
    }
}

// =====================================================================
// Kernel C: fused split-combine + op-projection + dilated convs + BN +
//           residual LN + horizon MLP. 16 nodes/block.
// =====================================================================
__global__ void __launch_bounds__(256)
tail_kernel(const float* __restrict__ op_w, const float* __restrict__ op_b,
            const float* __restrict__ tc0_w, const float* __restrict__ tc0_b,
            const float* __restrict__ tc1_w, const float* __restrict__ tc1_b,
            const float* __restrict__ bn_g, const float* __restrict__ bn_b,
            const float* __restrict__ ln_g, const float* __restrict__ ln_b,
            const float* __restrict__ h1_w, const float* __restrict__ h1_b,
            const float* __restrict__ hln_g, const float* __restrict__ hln_b,
            const float* __restrict__ h2_w, const float* __restrict__ h2_b,
            float* __restrict__ out)
{
    __shared__ float ss[20 * 32];
    __shared__ float at[20 * 33];
    __shared__ float ow[32 * 33];
    __shared__ float tw0[96 * 33];
    __shared__ float tw1[96 * 33];

    const int tid = threadIdx.x;
    const int blk = blockIdx.x;
    const int b   = blk >> 8;
    const int n0  = (blk & 255) << 4;

    for (int idx = tid; idx < 3072; idx += 256) {
        int co = idx / 96, rem = idx % 96;
        tw0[rem * 33 + co] = tc0_w[idx];
        tw1[rem * 33 + co] = tc1_w[idx];
    }
    for (int idx = tid; idx < 1024; idx += 256) {
        int o = idx >> 5, i = idx & 31;
        ow[i * 33 + o] = op_w[idx];
    }
    for (int idx = tid; idx < 640; idx += 256) {
        int rr = idx >> 5, c = idx & 31;
        int gn = n0 - 2 + rr;
        float val = 0.f;
        if (gn >= 0 && gn < N_) {
            int head = c >> 3, e = c & 7;
            size_t r0 = ((size_t)(b * 4 + head) * N_ + gn);
            size_t r1 = ((size_t)(BH_ + b * 4 + head) * N_ + gn);
            float num = d_patt[r0 * 8 + e] + d_patt[r1 * 8 + e];
            float den = d_pl[r0] + d_pl[r1];
            val = __fdividef(num, den);
        }
        at[rr * 33 + c] = val;
    }
    __syncthreads();

    const int w = tid >> 5, lane = tid & 31;

    for (int r = w; r < 20; r += 8) {
        int gn = n0 - 2 + r;
        float o = 0.f;
        if (gn >= 0 && gn < N_) {
            o = __ldg(op_b + lane);
#pragma unroll
            for (int i = 0; i < 32; i++)
                o += at[r * 33 + i] * ow[i * 33 + lane];
        }
        ss[r * 32 + lane] = o;
    }
    __syncthreads();

    const float b0 = __ldg(tc0_b + lane), b1 = __ldg(tc1_b + lane);

    float v0[2], v1[2];
#pragma unroll
    for (int t = 0; t < 2; t++) { v0[t] = b0; v1[t] = b1; }

#pragma unroll 8
    for (int ci = 0; ci < 32; ci++) {
        float w00 = tw0[(ci * 3 + 0) * 33 + lane];
        float w01 = tw0[(ci * 3 + 1) * 33 + lane];
        float w02 = tw0[(ci * 3 + 2) * 33 + lane];
        float w10 = tw1[(ci * 3 + 0) * 33 + lane];
        float w11 = tw1[(ci * 3 + 1) * 33 + lane];
        float w12 = tw1[(ci * 3 + 2) * 33 + lane];
#pragma unroll
        for (int t = 0; t < 2; t++) {
            int lr = w * 2 + t + 2;
            float sm2 = ss[(lr - 2) * 32 + ci];
            float sm1 = ss[(lr - 1) * 32 + ci];
            float s0  = ss[lr * 32 + ci];
            float sp1 = ss[(lr + 1) * 32 + ci];
            float sp2 = ss[(lr + 2) * 32 + ci];
            v0[t] += sm1 * w00 + s0 * w01 + sp1 * w02;
            v1[t] += sm2 * w10 + s0 * w11 + sp2 * w12;
        }
    }

    const float bs = __ldg(bn_g + lane) * rsqrtf(1.f + 1e-5f);
    const float bb = __ldg(bn_b + lane);
    const float lng = __ldg(ln_g + lane), lnb = __ldg(ln_b + lane);

#pragma unroll
    for (int t = 0; t < 2; t++) {
        const int lr = w * 2 + t + 2;
        const int n = n0 + w * 2 + t;
        float y0 = fmaxf(v0[t] * bs + bb, 0.f);
        float y1 = fmaxf(v1[t] * bs + bb, 0.f);
        float resid = 0.5f * (y0 + y1) + ss[lr * 32 + lane];

        float sum = resid, sq = resid * resid;
#pragma unroll
        for (int off = 16; off; off >>= 1) {
            sum += __shfl_xor_sync(0xffffffffu, sum, off);
            sq  += __shfl_xor_sync(0xffffffffu, sq, off);
        }
        float mu = sum * (1.f / 32.f);
        float var = sq * (1.f / 32.f) - mu * mu;
        float rstd = rsqrtf(var + 1e-5f);
        float tout = (resid - mu) * rstd * lng + lnb;

        float hj[8];
#pragma unroll
        for (int j = 0; j < 8; j++) hj[j] = tout * __ldg(h1_w + j * 32 + lane);
#pragma unroll
        for (int j = 0; j < 8; j++)
#pragma unroll
            for (int off = 16; off; off >>= 1)
                hj[j] += __shfl_xor_sync(0xffffffffu, hj[j], off);

        float hsum = 0.f;
#pragma unroll
        for (int j = 0; j < 8; j++) { hj[j] += __ldg(h1_b + j); hsum += hj[j]; }
        float hmu = hsum * (1.f / 8.f);
        float hsq = 0.f;
#pragma unroll
        for (int j = 0; j < 8; j++) { float dd = hj[j] - hmu; hsq += dd * dd; }
        float hrstd = rsqrtf(hsq * (1.f / 8.f) + 1e-5f);
        float hh[8];
#pragma unroll
        for (int j = 0; j < 8; j++)
            hh[j] = fmaxf((hj[j] - hmu) * hrstd * __ldg(hln_g + j) + __ldg(hln_b + j), 0.f);

        if (lane < HOR_) {
            float p = __ldg(h2_b + lane);
#pragma unroll
            for (int j = 0; j < 8; j++) p += hh[j] * __ldg(h2_w + lane * 8 + j);
            out[(size_t)b * HOR_ * N_ + (size_t)lane * N_ + n] = p;
        }
    }
}

// =====================================================================
extern "C" void kernel_launch(void* const* d_in, const int* in_sizes, int n_in,
                              void* d_out, int out_size)
{
    const float* x      = (const float*)d_in[0];
    const float* fe_w   = (const float*)d_in[1];
    const float* fe_b   = (const float*)d_in[2];
    const float* fe_bng = (const float*)d_in[3];
    const float* fe_bnb = (const float*)d_in[4];
    const float* p1_w   = (const float*)d_in[5];
    const float* p1_b   = (const float*)d_in[6];
    const float* p2_w   = (const float*)d_in[7];
    const float* p2_b   = (const float*)d_in[8];
    const float* qkv_w  = (const float*)d_in[9];
    const float* qkv_b  = (const float*)d_in[10];
    const float* op_w   = (const float*)d_in[11];
    const float* op_b   = (const float*)d_in[12];
    const float* u      = (const float*)d_in[13];
    const float* v      = (const float*)d_in[14];
    const float* tc0_w  = (const float*)d_in[15];
    const float* tc0_b  = (const float*)d_in[16];
    const float* tc1_w  = (const float*)d_in[17];
    const float* tc1_b  = (const float*)d_in[18];
    const float* t_bng  = (const float*)d_in[19];
    const float* t_bnb  = (const float*)d_in[20];
    const float* t_lng  = (const float*)d_in[21];
    const float* t_lnb  = (const float*)d_in[22];
    const float* h1_w   = (const float*)d_in[23];
    const float* h1_b   = (const float*)d_in[24];
    const float* h_lng  = (const float*)d_in[25];
    const float* h_lnb  = (const float*)d_in[26];
    const float* h2_w   = (const float*)d_in[27];
    const float* h2_b   = (const float*)d_in[28];
    float* out = (float*)d_out;

    feat_kernel<<<(B_ * N_) / 16, 256>>>(x, fe_w, fe_b, fe_bng, fe_bnb,
                                         p1_w, p1_b, p2_w, p2_b,
                                         qkv_w, qkv_b, u, v);

    dim3 agrid(N_ / 128, BH_, KSPLIT);      // (32, 8, 2) = 512 blocks
    attn_kernel<<<agrid, 256>>>();

    tail_kernel<<<(B_ * N_) / 16, 256>>>(op_w, op_b,
                                         tc0_w, tc0_b, tc1_w, tc1_b,
                                         t_bng, t_bnb, t_lng, t_lnb,
                                         h1_w, h1_b, h_lng, h_lnb,
                                         h2_w, h2_b, out);
}

// round 13
// speedup vs baseline: 3.4885x; 1.0730x over previous
#include <cuda_runtime.h>
#include <cuda_bf16.h>
#include <math.h>

// ---------------- problem constants ----------------
#define B_    2
#define T_    64
#define N_    4096
#define HOR_  24
#define C_    16
#define HID_  32
#define BD_   8
#define HEADS_ 4
#define HD_   8
#define BH_   (B_*HEADS_)      // 8
#define LOG2E 1.4426950408889634f
#define INV_SQRT8 0.35355339059327373f
#define KSPLIT 2

// ---------------- scratch (device globals; no allocation) ----------------
__device__ __align__(16) __nv_bfloat16 d_Qh[BH_ * N_ * 16];
__device__ __align__(16) __nv_bfloat16 d_Ql[BH_ * N_ * 16];
__device__ __align__(16) __nv_bfloat16 d_Kh[BH_ * N_ * 16];
__device__ __align__(16) __nv_bfloat16 d_Kl[BH_ * N_ * 16];
__device__ __align__(16) __nv_bfloat16 d_Vh[BH_ * N_ * 8];
__device__ __align__(16) __nv_bfloat16 d_Vl[BH_ * N_ * 8];
__device__ float d_patt[KSPLIT * BH_ * N_ * 8];   // unnormalized partial O
__device__ float d_pl[KSPLIT * BH_ * N_];         // partial row sums

__device__ __forceinline__ float ex2f(float x) {
    float y; asm("ex2.approx.ftz.f32 %0, %1;" : "=f"(y) : "f"(x)); return y;
}
__device__ __forceinline__ float elu1(float x) {
    return x > 0.f ? x + 1.f : __expf(x);
}
__device__ __forceinline__ void bsplit(float x, __nv_bfloat16& hi, __nv_bfloat16& lo) {
    __nv_bfloat16 h = __float2bfloat16(x);
    hi = h;
    lo = __float2bfloat16(x - __bfloat162float(h));
}

// bf16 m16n8k16 mma, fp32 accumulate
__device__ __forceinline__ void mma16816(float d[4], const unsigned a[4],
                                         const unsigned b[2], const float c[4]) {
    asm volatile(
        "mma.sync.aligned.m16n8k16.row.col.f32.bf16.bf16.f32 "
        "{%0,%1,%2,%3}, {%4,%5,%6,%7}, {%8,%9}, {%10,%11,%12,%13};"
        : "=f"(d[0]), "=f"(d[1]), "=f"(d[2]), "=f"(d[3])
        : "r"(a[0]), "r"(a[1]), "r"(a[2]), "r"(a[3]),
          "r"(b[0]), "r"(b[1]),
          "f"(c[0]), "f"(c[1]), "f"(c[2]), "f"(c[3]));
}

// pack two fp32 -> bf16x2 hi/lo split (hi re-expansion via bit ops, ALU pipe)
__device__ __forceinline__ void split2(float x, float y, unsigned& hi, unsigned& lo) {
    __nv_bfloat162 h2 = __floats2bfloat162_rn(x, y);
    hi = *(unsigned*)&h2;
    float hx = __uint_as_float(hi << 16);
    float hy = __uint_as_float(hi & 0xFFFF0000u);
    __nv_bfloat162 l2 = __floats2bfloat162_rn(x - hx, y - hy);
    lo = *(unsigned*)&l2;
}

// =====================================================================
// Kernel A: conv -> p1 -> p2 -> qkv -> split-bf16 Q'/K'/V
// 2 nodes per warp, 16 nodes/block; phase-aliased smem
// =====================================================================
#define XS_OFF  0                       // float[16][66]  = 4224 B
#define CW_OFF  4224                    // float[48]      = 192 B
#define CSH_OFF 4416                    // float[16]      = 64 B
#define P1_OFF  4480                    // float[8192]    = 32768 B  (phase 1)
#define WT_OFF  4480                    // float[32*97]   = 12416 B  (phase 2)
#define FS_OFF  16896                   // float[16][32]  = 2048 B   (phase 2)
#define FEAT_SMEM 37248

__global__ void __launch_bounds__(256)
feat_kernel(const float* __restrict__ x,
            const float* __restrict__ fe_w, const float* __restrict__ fe_b,
            const float* __restrict__ bn_g, const float* __restrict__ bn_b,
            const float* __restrict__ p1_w, const float* __restrict__ p1_b,
            const float* __restrict__ p2_w, const float* __restrict__ p2_b,
            const float* __restrict__ qkv_w, const float* __restrict__ qkv_b,
            const float* __restrict__ u, const float* __restrict__ v)
{
    __shared__ __align__(16) char sbuf[FEAT_SMEM];
    float* xsf  = (float*)(sbuf + XS_OFF);      // [16][66]
    float* cw   = (float*)(sbuf + CW_OFF);
    float* csh  = (float*)(sbuf + CSH_OFF);
    float* p1s  = (float*)(sbuf + P1_OFF);
    float* wt   = (float*)(sbuf + WT_OFF);
    float* fsf  = (float*)(sbuf + FS_OFF);      // [16][32]

    const int tid = threadIdx.x;
    const int blk = blockIdx.x;
    const int b   = blk >> 8;
    const int n0  = (blk & 255) << 4;

    for (int i = tid; i < 2048; i += 256)
        ((float4*)p1s)[i] = ((const float4*)p1_w)[i];
    if (tid < 48) {
        int c = tid / 3;
        float sc = bn_g[c] * rsqrtf(1.f + 1e-5f);
        cw[tid] = fe_w[tid] * sc;
    }
    if (tid < 16) {
        float sc = bn_g[tid] * rsqrtf(1.f + 1e-5f);
        csh[tid] = fe_b[tid] * sc + bn_b[tid];
    }
    for (int i = tid; i < 1024; i += 256) {
        int node = i & 15, t = i >> 4;
        xsf[node * 66 + t + 1] = x[(size_t)b * T_ * N_ + (size_t)t * N_ + n0 + node];
    }
    if (tid < 16) { xsf[tid * 66] = 0.f; xsf[tid * 66 + 65] = 0.f; }
    __syncthreads();

    const int w = tid >> 5, lane = tid & 31;
    const int nA = n0 + 2 * w, nB = nA + 1;

    const float* xA = xsf + (2 * w) * 66;
    const float* xB = xsf + (2 * w + 1) * 66;
    const float a0 = xA[lane],      a1 = xA[lane + 1],  a2 = xA[lane + 2];
    const float a3 = xA[lane + 32], a4 = xA[lane + 33], a5 = xA[lane + 34];
    const float c0 = xB[lane],      c1 = xB[lane + 1],  c2 = xB[lane + 2];
    const float c3 = xB[lane + 32], c4_ = xB[lane + 33], c5 = xB[lane + 34];

    float accA[8], accB[8];
#pragma unroll
    for (int j = 0; j < 8; j++) { accA[j] = 0.f; accB[j] = 0.f; }

#pragma unroll
    for (int i = 0; i < 32; i++) {
        int cc = i >> 1;
        float w0 = cw[cc * 3], w1 = cw[cc * 3 + 1], w2 = cw[cc * 3 + 2], sh = csh[cc];
        float valA, valB;
        if ((i & 1) == 0) {
            valA = a0 * w0 + a1 * w1 + a2 * w2 + sh;
            valB = c0 * w0 + c1 * w1 + c2 * w2 + sh;
        } else {
            valA = a3 * w0 + a4 * w1 + a5 * w2 + sh;
            valB = c3 * w0 + c4_ * w1 + c5 * w2 + sh;
        }
        valA = fmaxf(valA, 0.f);
        valB = fmaxf(valB, 0.f);
        int base = i * 32 + lane;
#pragma unroll
        for (int j = 0; j < 8; j++) {
            float pw = p1s[j * 1024 + base];
            accA[j] += valA * pw;
            accB[j] += valB * pw;
        }
    }
#pragma unroll
    for (int j = 0; j < 8; j++)
#pragma unroll
        for (int off = 16; off; off >>= 1) {
            accA[j] += __shfl_xor_sync(0xffffffffu, accA[j], off);
            accB[j] += __shfl_xor_sync(0xffffffffu, accB[j], off);
        }

    float r1A[8], r1B[8];
#pragma unroll
    for (int j = 0; j < 8; j++) {
        float pb = __ldg(p1_b + j);
        r1A[j] = fmaxf(accA[j] + pb, 0.f);
        r1B[j] = fmaxf(accB[j] + pb, 0.f);
    }

    float fA = __ldg(p2_b + lane), fB = fA;
#pragma unroll
    for (int j = 0; j < 8; j++) {
        float pw = __ldg(p2_w + lane * 8 + j);
        fA += r1A[j] * pw;
        fB += r1B[j] * pw;
    }

    __syncthreads();
    for (int idx = tid; idx < 3072; idx += 256) {
        int o = idx >> 5, i = idx & 31;
        wt[i * 97 + o] = qkv_w[idx];
    }
    fsf[(2 * w) * 32 + lane] = fA;
    fsf[(2 * w + 1) * 32 + lane] = fB;
    __syncthreads();

    float oqA = __ldg(qkv_b + lane),      oqB = oqA;
    float okA = __ldg(qkv_b + lane + 32), okB = okA;
    float ovA = __ldg(qkv_b + lane + 64), ovB = ovA;
#pragma unroll
    for (int i = 0; i < 32; i++) {
        float fiA = fsf[(2 * w) * 32 + i];
        float fiB = fsf[(2 * w + 1) * 32 + i];
        const float* wr = wt + i * 97;
        float wq = wr[lane], wk = wr[lane + 32], wv = wr[lane + 64];
        oqA += fiA * wq; oqB += fiB * wq;
        okA += fiA * wk; okB += fiB * wk;
        ovA += fiA * wv; ovB += fiB * wv;
    }

    const int head = lane >> 3, d = lane & 7;
    {
        const size_t ridx = ((size_t)(b * 4 + head) * N_ + nA);
        const size_t qidx = ridx * 16;
        bsplit(elu1(oqA) * (LOG2E * INV_SQRT8), d_Qh[qidx + d],     d_Ql[qidx + d]);
        bsplit(u[(size_t)nA * 8 + d] * LOG2E,   d_Qh[qidx + 8 + d], d_Ql[qidx + 8 + d]);
        bsplit(elu1(okA),                       d_Kh[qidx + d],     d_Kl[qidx + d]);
        bsplit(v[(size_t)d * N_ + nA],          d_Kh[qidx + 8 + d], d_Kl[qidx + 8 + d]);
        bsplit(ovA, d_Vh[ridx * 8 + d], d_Vl[ridx * 8 + d]);
    }
    {
        const size_t ridx = ((size_t)(b * 4 + head) * N_ + nB);
        const size_t qidx = ridx * 16;
        bsplit(elu1(oqB) * (LOG2E * INV_SQRT8), d_Qh[qidx + d],     d_Ql[qidx + d]);
        bsplit(u[(size_t)nB * 8 + d] * LOG2E,   d_Qh[qidx + 8 + d], d_Ql[qidx + 8 + d]);
        bsplit(elu1(okB),                       d_Kh[qidx + d],     d_Kl[qidx + d]);
        bsplit(v[(size_t)d * N_ + nB],          d_Kh[qidx + 8 + d], d_Kl[qidx + 8 + d]);
        bsplit(ovB, d_Vh[ridx * 8 + d], d_Vl[ridx * 8 + d]);
    }
}

// =====================================================================
// Kernel B: tensor-core flash attention, split-K=2, ones-mma row sums
// 256 threads = 8 warps, 128 q-rows/block; double-buffered KTILE,
// register prefetch, ONE __syncthreads per tile.
// =====================================================================
#define KTILE 128
#define NIT   ((N_ / KSPLIT) / KTILE)   // 16
__global__ void __launch_bounds__(256)
attn_kernel()
{
    const int bh = blockIdx.y;
    const int qbase = blockIdx.x * 128;
    const int kz = blockIdx.z;
    const int tid = threadIdx.x, w = tid >> 5, l = tid & 31;

    __shared__ __align__(16) unsigned Khl[2][KTILE * 16];
    __shared__ __align__(16) unsigned Vhl[2][8 * 144];

    const unsigned* Qh_u = (const unsigned*)d_Qh + (size_t)bh * N_ * 8;
    const unsigned* Ql_u = (const unsigned*)d_Ql + (size_t)bh * N_ * 8;
    const unsigned* Kh_u = (const unsigned*)d_Kh + (size_t)bh * N_ * 8;
    const unsigned* Kl_u = (const unsigned*)d_Kl + (size_t)bh * N_ * 8;
    const __nv_bfloat16* Vh_g = d_Vh + (size_t)bh * N_ * 8;
    const __nv_bfloat16* Vl_g = d_Vl + (size_t)bh * N_ * 8;

    const int qr0 = qbase + w * 16 + (l >> 2);
    const int qr1 = qr0 + 8;
    const int c4 = l & 3;

    unsigned ah[4], al[4];
    ah[0] = Qh_u[qr0 * 8 + c4];     ah[1] = Qh_u[qr1 * 8 + c4];
    ah[2] = Qh_u[qr0 * 8 + c4 + 4]; ah[3] = Qh_u[qr1 * 8 + c4 + 4];
    al[0] = Ql_u[qr0 * 8 + c4];     al[1] = Ql_u[qr1 * 8 + c4];
    al[2] = Ql_u[qr0 * 8 + c4 + 4]; al[3] = Ql_u[qr1 * 8 + c4 + 4];

    float O[4] = {0.f, 0.f, 0.f, 0.f};
    float Ol[4] = {0.f, 0.f, 0.f, 0.f};
    const unsigned ones2 = 0x3F803F80u;
    unsigned bones[2] = {ones2, ones2};

    unsigned kreg[2][4];
    __nv_bfloat16 vreg[4][2];

    const int kkey0 = tid >> 2, kkc = tid & 3;
    const int kkey1 = (tid + 256) >> 2;
    const int vkey0 = tid >> 3, vvd = tid & 7;

    const int k0 = kz * (N_ / KSPLIT);

    auto ldg_tile = [&](int kt) {
        kreg[0][0] = Kh_u[(size_t)(kt + kkey0) * 8 + kkc];
        kreg[0][1] = Kh_u[(size_t)(kt + kkey0) * 8 + kkc + 4];
        kreg[0][2] = Kl_u[(size_t)(kt + kkey0) * 8 + kkc];
        kreg[0][3] = Kl_u[(size_t)(kt + kkey0) * 8 + kkc + 4];
        kreg[1][0] = Kh_u[(size_t)(kt + kkey1) * 8 + kkc];
        kreg[1][1] = Kh_u[(size_t)(kt + kkey1) * 8 + kkc + 4];
        kreg[1][2] = Kl_u[(size_t)(kt + kkey1) * 8 + kkc];
        kreg[1][3] = Kl_u[(size_t)(kt + kkey1) * 8 + kkc + 4];
#pragma unroll
        for (int i = 0; i < 4; i++) {
            int key = vkey0 + i * 32;
            vreg[i][0] = Vh_g[(size_t)(kt + key) * 8 + vvd];
            vreg[i][1] = Vl_g[(size_t)(kt + key) * 8 + vvd];
        }
    };
    auto sts_tile = [&](int bb) {
        *(uint4*)&Khl[bb][kkey0 * 16 + kkc * 4] =
            make_uint4(kreg[0][0], kreg[0][1], kreg[0][2], kreg[0][3]);
        *(uint4*)&Khl[bb][kkey1 * 16 + kkc * 4] =
            make_uint4(kreg[1][0], kreg[1][1], kreg[1][2], kreg[1][3]);
        __nv_bfloat16* Vsh = (__nv_bfloat16*)Vhl[bb];
#pragma unroll
        for (int i = 0; i < 4; i++) {
            int key = vkey0 + i * 32;
            int j = key >> 1, half = key & 1;
            int ci = j >> 3, c4v = j & 3, hi4 = (j >> 2) & 1;
            int base_u = vvd * 144 + ci * 16 + c4v * 4;
            Vsh[2 * (base_u + hi4) + half]     = vreg[i][0];
            Vsh[2 * (base_u + 2 + hi4) + half] = vreg[i][1];
        }
    };

    ldg_tile(k0);
    sts_tile(0);
    __syncthreads();

    for (int it = 0; it < NIT; it++) {
        const int bb = it & 1;
        if (it + 1 < NIT) ldg_tile(k0 + (it + 1) * KTILE);

        const unsigned* Kb = Khl[bb];
        const unsigned* Vb = Vhl[bb];
#pragma unroll
        for (int c16 = 0; c16 < KTILE; c16 += 16) {
            float S0[4] = {0.f, 0.f, 0.f, 0.f};
            float S1[4] = {0.f, 0.f, 0.f, 0.f};

            const int kr0 = c16 + (l >> 2);
            const int kr1 = kr0 + 8;
            uint4 k0v = *(const uint4*)&Kb[kr0 * 16 + c4 * 4];
            uint4 k1v = *(const uint4*)&Kb[kr1 * 16 + c4 * 4];
            unsigned kh0[2] = {k0v.x, k0v.y}, kl0[2] = {k0v.z, k0v.w};
            unsigned kh1[2] = {k1v.x, k1v.y}, kl1[2] = {k1v.z, k1v.w};

            mma16816(S0, ah, kh0, S0);
            mma16816(S0, al, kh0, S0);
            mma16816(S0, ah, kl0, S0);
            mma16816(S1, ah, kh1, S1);
            mma16816(S1, al, kh1, S1);
            mma16816(S1, ah, kl1, S1);

            float p00 = ex2f(S0[0]), p01 = ex2f(S0[1]);
            float p02 = ex2f(S0[2]), p03 = ex2f(S0[3]);
            float p10 = ex2f(S1[0]), p11 = ex2f(S1[1]);
            float p12 = ex2f(S1[2]), p13 = ex2f(S1[3]);

            unsigned pa_h[4], pa_l[4];
            split2(p00, p01, pa_h[0], pa_l[0]);
            split2(p02, p03, pa_h[1], pa_l[1]);
            split2(p10, p11, pa_h[2], pa_l[2]);
            split2(p12, p13, pa_h[3], pa_l[3]);

            uint4 vv = *(const uint4*)&Vb[(l >> 2) * 144 + (c16 >> 4) * 16 + c4 * 4];
            unsigned vh[2] = {vv.x, vv.y}, vl[2] = {vv.z, vv.w};

            mma16816(O, pa_h, vh, O);
            mma16816(O, pa_l, vh, O);
            mma16816(O, pa_h, vl, O);
            mma16816(Ol, pa_h, bones, Ol);
            mma16816(Ol, pa_l, bones, Ol);
        }

        if (it + 1 < NIT) sts_tile(bb ^ 1);
        __syncthreads();
    }

    const size_t pbase = (size_t)(kz * BH_ + bh) * N_;
    float* o0 = d_patt + (pbase + qr0) * 8 + 2 * c4;
    float* o1 = d_patt + (pbase + qr1) * 8 + 2 * c4;
    o0[0] = O[0]; o0[1] = O[1];
    o1[0] = O[2]; o1[1] = O[3];
    if (c4 == 0) {
        d_pl[pbase + qr0] = Ol[0];
        d_pl[pbase + qr1] = Ol[2];
    }
}

// =====================================================================
// Kernel C: fused split-combine + op-projection + dilated convs + BN +
//           residual LN + horizon MLP. 32 nodes/block (8 warps x 4),
//           conv taps shared across the 4 nodes (8 ss rows per ci).
// =====================================================================
__global__ void __launch_bounds__(256)
tail_kernel(const float* __restrict__ op_w, const float* __restrict__ op_b,
            const float* __restrict__ tc0_w, const float* __restrict__ tc0_b,
            const float* __restrict__ tc1_w, const float* __restrict__ tc1_b,
            const float* __restrict__ bn_g, const float* __restrict__ bn_b,
            const float* __restrict__ ln_g, const float* __restrict__ ln_b,
            const float* __restrict__ h1_w, const float* __restrict__ h1_b,
            const float* __restrict__ hln_g, const float* __restrict__ hln_b,
            const float* __restrict__ h2_w, const float* __restrict__ h2_b,
            float* __restrict__ out)
{
    __shared__ float ss[36 * 32];        // 4608 B  s rows n0-2 .. n0+33
    __shared__ float at[36 * 33];        // 4752 B
    __shared__ float ow[32 * 33];        // 4224 B
    __shared__ float tw0[96 * 33];       // 12672 B
    __shared__ float tw1[96 * 33];       // 12672 B  (total ~38.9 KB)

    const int tid = threadIdx.x;
    const int blk = blockIdx.x;
    const int b   = blk >> 7;
    const int n0  = (blk & 127) << 5;

    for (int idx = tid; idx < 3072; idx += 256) {
        int co = idx / 96, rem = idx % 96;
        tw0[rem * 33 + co] = tc0_w[idx];
        tw1[rem * 33 + co] = tc1_w[idx];
    }
    for (int idx = tid; idx < 1024; idx += 256) {
        int o = idx >> 5, i = idx & 31;
        ow[i * 33 + o] = op_w[idx];
    }
    for (int idx = tid; idx < 1152; idx += 256) {
        int rr = idx >> 5, c = idx & 31;
        int gn = n0 - 2 + rr;
        float val = 0.f;
        if (gn >= 0 && gn < N_) {
            int head = c >> 3, e = c & 7;
            size_t r0 = ((size_t)(b * 4 + head) * N_ + gn);
            size_t r1 = ((size_t)(BH_ + b * 4 + head) * N_ + gn);
            float num = d_patt[r0 * 8 + e] + d_patt[r1 * 8 + e];
            float den = d_pl[r0] + d_pl[r1];
            val = __fdividef(num, den);
        }
        at[rr * 33 + c] = val;
    }
    __syncthreads();

    const int w = tid >> 5, lane = tid & 31;

    // op projection for the block's 36 halo rows
    for (int r = w; r < 36; r += 8) {
        int gn = n0 - 2 + r;
        float o = 0.f;
        if (gn >= 0 && gn < N_) {
            o = __ldg(op_b + lane);
#pragma unroll
            for (int i = 0; i < 32; i++)
                o += at[r * 33 + i] * ow[i * 33 + lane];
        }
        ss[r * 32 + lane] = o;
    }
    __syncthreads();

    const float b0 = __ldg(tc0_b + lane), b1 = __ldg(tc1_b + lane);

    float v0[4], v1[4];
#pragma unroll
    for (int t = 0; t < 4; t++) { v0[t] = b0; v1[t] = b1; }

    // 4 consecutive nodes per warp-row-group: union of conv taps = 8 rows
#pragma unroll 4
    for (int ci = 0; ci < 32; ci++) {
        float w00 = tw0[(ci * 3 + 0) * 33 + lane];
        float w01 = tw0[(ci * 3 + 1) * 33 + lane];
        float w02 = tw0[(ci * 3 + 2) * 33 + lane];
        float w10 = tw1[(ci * 3 + 0) * 33 + lane];
        float w11 = tw1[(ci * 3 + 1) * 33 + lane];
        float w12 = tw1[(ci * 3 + 2) * 33 + lane];
        float s[8];
#pragma unroll
        for (int j = 0; j < 8; j++) s[j] = ss[(w * 4 + j) * 32 + ci];
#pragma unroll
        for (int t = 0; t < 4; t++) {
            // local row lr = w*4 + t + 2 ; s[j] = row w*4 + j
            v0[t] += s[t + 1] * w00 + s[t + 2] * w01 + s[t + 3] * w02;
            v1[t] += s[t]     * w10 + s[t + 2] * w11 + s[t + 4] * w12;
        }
    }

    const float bs = __ldg(bn_g + lane) * rsqrtf(1.f + 1e-5f);
    const float bb = __ldg(bn_b + lane);
    const float lng = __ldg(ln_g + lane), lnb = __ldg(ln_b + lane);

#pragma unroll
    for (int t = 0; t < 4; t++) {
        const int lr = w * 4 + t + 2;
        const int n = n0 + w * 4 + t;
        float y0 = fmaxf(v0[t] * bs + bb, 0.f);
        float y1 = fmaxf(v1[t] * bs + bb, 0.f);
        float resid = 0.5f * (y0 + y1) + ss[lr * 32 + lane];

        float sum = resid, sq = resid * resid;
#pragma unroll
        for (int off = 16; off; off >>= 1) {
            sum += __shfl_xor_sync(0xffffffffu, sum, off);
            sq  += __shfl_xor_sync(0xffffffffu, sq, off);
        }
        float mu = sum * (1.f / 32.f);
        float var = sq * (1.f / 32.f) - mu * mu;
        float rstd = rsqrtf(var + 1e-5f);
        float tout = (resid - mu) * rstd * lng + lnb;

        float hj[8];
#pragma unroll
        for (int j = 0; j < 8; j++) hj[j] = tout * __ldg(h1_w + j * 32 + lane);
#pragma unroll
        for (int j = 0; j < 8; j++)
#pragma unroll
            for (int off = 16; off; off >>= 1)
                hj[j] += __shfl_xor_sync(0xffffffffu, hj[j], off);

        float hsum = 0.f;
#pragma unroll
        for (int j = 0; j < 8; j++) { hj[j] += __ldg(h1_b + j); hsum += hj[j]; }
        float hmu = hsum * (1.f / 8.f);
        float hsq = 0.f;
#pragma unroll
        for (int j = 0; j < 8; j++) { float dd = hj[j] - hmu; hsq += dd * dd; }
        float hrstd = rsqrtf(hsq * (1.f / 8.f) + 1e-5f);
        float hh[8];
#pragma unroll
        for (int j = 0; j < 8; j++)
            hh[j] = fmaxf((hj[j] - hmu) * hrstd * __ldg(hln_g + j) + __ldg(hln_b + j), 0.f);

        if (lane < HOR_) {
            float p = __ldg(h2_b + lane);
#pragma unroll
            for (int j = 0; j < 8; j++) p += hh[j] * __ldg(h2_w + lane * 8 + j);
            out[(size_t)b * HOR_ * N_ + (size_t)lane * N_ + n] = p;
        }
    }
}

// =====================================================================
extern "C" void kernel_launch(void* const* d_in, const int* in_sizes, int n_in,
                              void* d_out, int out_size)
{
    const float* x      = (const float*)d_in[0];
    const float* fe_w   = (const float*)d_in[1];
    const float* fe_b   = (const float*)d_in[2];
    const float* fe_bng = (const float*)d_in[3];
    const float* fe_bnb = (const float*)d_in[4];
    const float* p1_w   = (const float*)d_in[5];
    const float* p1_b   = (const float*)d_in[6];
    const float* p2_w   = (const float*)d_in[7];
    const float* p2_b   = (const float*)d_in[8];
    const float* qkv_w  = (const float*)d_in[9];
    const float* qkv_b  = (const float*)d_in[10];
    const float* op_w   = (const float*)d_in[11];
    const float* op_b   = (const float*)d_in[12];
    const float* u      = (const float*)d_in[13];
    const float* v      = (const float*)d_in[14];
    const float* tc0_w  = (const float*)d_in[15];
    const float* tc0_b  = (const float*)d_in[16];
    const float* tc1_w  = (const float*)d_in[17];
    const float* tc1_b  = (const float*)d_in[18];
    const float* t_bng  = (const float*)d_in[19];
    const float* t_bnb  = (const float*)d_in[20];
    const float* t_lng  = (const float*)d_in[21];
    const float* t_lnb  = (const float*)d_in[22];
    const float* h1_w   = (const float*)d_in[23];
    const float* h1_b   = (const float*)d_in[24];
    const float* h_lng  = (const float*)d_in[25];
    const float* h_lnb  = (const float*)d_in[26];
    const float* h2_w   = (const float*)d_in[27];
    const float* h2_b   = (const float*)d_in[28];
    float* out = (float*)d_out;

    feat_kernel<<<(B_ * N_) / 16, 256>>>(x, fe_w, fe_b, fe_bng, fe_bnb,
                                         p1_w, p1_b, p2_w, p2_b,
                                         qkv_w, qkv_b, u, v);

    dim3 agrid(N_ / 128, BH_, KSPLIT);      // (32, 8, 2) = 512 blocks
    attn_kernel<<<agrid, 256>>>();

    tail_kernel<<<(B_ * N_) / 32, 256>>>(op_w, op_b,
                                         tc0_w, tc0_b, tc1_w, tc1_b,
                                         t_bng, t_bnb, t_lng, t_lnb,
                                         h1_w, h1_b, h_lng, h_lnb,
                                         h2_w, h2_b, out);
}

// round 14
// speedup vs baseline: 3.5562x; 1.0194x over previous
#include <cuda_runtime.h>
#include <cuda_bf16.h>
#include <math.h>

// ---------------- problem constants ----------------
#define B_    2
#define T_    64
#define N_    4096
#define HOR_  24
#define C_    16
#define HID_  32
#define BD_   8
#define HEADS_ 4
#define HD_   8
#define BH_   (B_*HEADS_)      // 8
#define LOG2E 1.4426950408889634f
#define INV_SQRT8 0.35355339059327373f
#define KSPLIT 4

// ---------------- scratch (device globals; no allocation) ----------------
__device__ __align__(16) __nv_bfloat16 d_Qh[BH_ * N_ * 16];
__device__ __align__(16) __nv_bfloat16 d_Ql[BH_ * N_ * 16];
__device__ __align__(16) __nv_bfloat16 d_Kh[BH_ * N_ * 16];
__device__ __align__(16) __nv_bfloat16 d_Kl[BH_ * N_ * 16];
__device__ __align__(16) __nv_bfloat16 d_Vh[BH_ * N_ * 8];
__device__ __align__(16) __nv_bfloat16 d_Vl[BH_ * N_ * 8];
__device__ float d_patt[KSPLIT * BH_ * N_ * 8];   // unnormalized partial O
__device__ float d_pl[KSPLIT * BH_ * N_];         // partial row sums

__device__ __forceinline__ float ex2f(float x) {
    float y; asm("ex2.approx.ftz.f32 %0, %1;" : "=f"(y) : "f"(x)); return y;
}
__device__ __forceinline__ float elu1(float x) {
    return x > 0.f ? x + 1.f : __expf(x);
}
__device__ __forceinline__ void bsplit(float x, __nv_bfloat16& hi, __nv_bfloat16& lo) {
    __nv_bfloat16 h = __float2bfloat16(x);
    hi = h;
    lo = __float2bfloat16(x - __bfloat162float(h));
}

// bf16 m16n8k16 mma, fp32 accumulate
__device__ __forceinline__ void mma16816(float d[4], const unsigned a[4],
                                         const unsigned b[2], const float c[4]) {
    asm volatile(
        "mma.sync.aligned.m16n8k16.row.col.f32.bf16.bf16.f32 "
        "{%0,%1,%2,%3}, {%4,%5,%6,%7}, {%8,%9}, {%10,%11,%12,%13};"
        : "=f"(d[0]), "=f"(d[1]), "=f"(d[2]), "=f"(d[3])
        : "r"(a[0]), "r"(a[1]), "r"(a[2]), "r"(a[3]),
          "r"(b[0]), "r"(b[1]),
          "f"(c[0]), "f"(c[1]), "f"(c[2]), "f"(c[3]));
}

// pack two fp32 -> bf16x2 hi/lo split (hi re-expansion via bit ops, ALU pipe)
__device__ __forceinline__ void split2(float x, float y, unsigned& hi, unsigned& lo) {
    __nv_bfloat162 h2 = __floats2bfloat162_rn(x, y);
    hi = *(unsigned*)&h2;
    float hx = __uint_as_float(hi << 16);
    float hy = __uint_as_float(hi & 0xFFFF0000u);
    __nv_bfloat162 l2 = __floats2bfloat162_rn(x - hx, y - hy);
    lo = *(unsigned*)&l2;
}

// =====================================================================
// Kernel A: conv -> p1 -> p2 -> qkv -> split-bf16 Q'/K'/V
// 2 nodes per warp, 16 nodes/block; phase-aliased smem
// =====================================================================
#define XS_OFF  0                       // float[16][66]  = 4224 B
#define CW_OFF  4224                    // float[48]      = 192 B
#define CSH_OFF 4416                    // float[16]      = 64 B
#define P1_OFF  4480                    // float[8192]    = 32768 B  (phase 1)
#define WT_OFF  4480                    // float[32*97]   = 12416 B  (phase 2)
#define FS_OFF  16896                   // float[16][32]  = 2048 B   (phase 2)
#define FEAT_SMEM 37248

__global__ void __launch_bounds__(256)
feat_kernel(const float* __restrict__ x,
            const float* __restrict__ fe_w, const float* __restrict__ fe_b,
            const float* __restrict__ bn_g, const float* __restrict__ bn_b,
            const float* __restrict__ p1_w, const float* __restrict__ p1_b,
            const float* __restrict__ p2_w, const float* __restrict__ p2_b,
            const float* __restrict__ qkv_w, const float* __restrict__ qkv_b,
            const float* __restrict__ u, const float* __restrict__ v)
{
    __shared__ __align__(16) char sbuf[FEAT_SMEM];
    float* xsf  = (float*)(sbuf + XS_OFF);      // [16][66]
    float* cw   = (float*)(sbuf + CW_OFF);
    float* csh  = (float*)(sbuf + CSH_OFF);
    float* p1s  = (float*)(sbuf + P1_OFF);
    float* wt   = (float*)(sbuf + WT_OFF);
    float* fsf  = (float*)(sbuf + FS_OFF);      // [16][32]

    const int tid = threadIdx.x;
    const int blk = blockIdx.x;
    const int b   = blk >> 8;
    const int n0  = (blk & 255) << 4;

    for (int i = tid; i < 2048; i += 256)
        ((float4*)p1s)[i] = ((const float4*)p1_w)[i];
    if (tid < 48) {
        int c = tid / 3;
        float sc = bn_g[c] * rsqrtf(1.f + 1e-5f);
        cw[tid] = fe_w[tid] * sc;
    }
    if (tid < 16) {
        float sc = bn_g[tid] * rsqrtf(1.f + 1e-5f);
        csh[tid] = fe_b[tid] * sc + bn_b[tid];
    }
    for (int i = tid; i < 1024; i += 256) {
        int node = i & 15, t = i >> 4;
        xsf[node * 66 + t + 1] = x[(size_t)b * T_ * N_ + (size_t)t * N_ + n0 + node];
    }
    if (tid < 16) { xsf[tid * 66] = 0.f; xsf[tid * 66 + 65] = 0.f; }
    __syncthreads();

    const int w = tid >> 5, lane = tid & 31;
    const int nA = n0 + 2 * w, nB = nA + 1;

    const float* xA = xsf + (2 * w) * 66;
    const float* xB = xsf + (2 * w + 1) * 66;
    const float a0 = xA[lane],      a1 = xA[lane + 1],  a2 = xA[lane + 2];
    const float a3 = xA[lane + 32], a4 = xA[lane + 33], a5 = xA[lane + 34];
    const float c0 = xB[lane],      c1 = xB[lane + 1],  c2 = xB[lane + 2];
    const float c3 = xB[lane + 32], c4_ = xB[lane + 33], c5 = xB[lane + 34];

    float accA[8], accB[8];
#pragma unroll
    for (int j = 0; j < 8; j++) { accA[j] = 0.f; accB[j] = 0.f; }

#pragma unroll
    for (int i = 0; i < 32; i++) {
        int cc = i >> 1;
        float w0 = cw[cc * 3], w1 = cw[cc * 3 + 1], w2 = cw[cc * 3 + 2], sh = csh[cc];
        float valA, valB;
        if ((i & 1) == 0) {
            valA = a0 * w0 + a1 * w1 + a2 * w2 + sh;
            valB = c0 * w0 + c1 * w1 + c2 * w2 + sh;
        } else {
            valA = a3 * w0 + a4 * w1 + a5 * w2 + sh;
            valB = c3 * w0 + c4_ * w1 + c5 * w2 + sh;
        }
        valA = fmaxf(valA, 0.f);
        valB = fmaxf(valB, 0.f);
        int base = i * 32 + lane;
#pragma unroll
        for (int j = 0; j < 8; j++) {
            float pw = p1s[j * 1024 + base];
            accA[j] += valA * pw;
            accB[j] += valB * pw;
        }
    }
#pragma unroll
    for (int j = 0; j < 8; j++)
#pragma unroll
        for (int off = 16; off; off >>= 1) {
            accA[j] += __shfl_xor_sync(0xffffffffu, accA[j], off);
            accB[j] += __shfl_xor_sync(0xffffffffu, accB[j], off);
        }

    float r1A[8], r1B[8];
#pragma unroll
    for (int j = 0; j < 8; j++) {
        float pb = __ldg(p1_b + j);
        r1A[j] = fmaxf(accA[j] + pb, 0.f);
        r1B[j] = fmaxf(accB[j] + pb, 0.f);
    }

    float fA = __ldg(p2_b + lane), fB = fA;
#pragma unroll
    for (int j = 0; j < 8; j++) {
        float pw = __ldg(p2_w + lane * 8 + j);
        fA += r1A[j] * pw;
        fB += r1B[j] * pw;
    }

    __syncthreads();
    for (int idx = tid; idx < 3072; idx += 256) {
        int o = idx >> 5, i = idx & 31;
        wt[i * 97 + o] = qkv_w[idx];
    }
    fsf[(2 * w) * 32 + lane] = fA;
    fsf[(2 * w + 1) * 32 + lane] = fB;
    __syncthreads();

    float oqA = __ldg(qkv_b + lane),      oqB = oqA;
    float okA = __ldg(qkv_b + lane + 32), okB = okA;
    float ovA = __ldg(qkv_b + lane + 64), ovB = ovA;
#pragma unroll
    for (int i = 0; i < 32; i++) {
        float fiA = fsf[(2 * w) * 32 + i];
        float fiB = fsf[(2 * w + 1) * 32 + i];
        const float* wr = wt + i * 97;
        float wq = wr[lane], wk = wr[lane + 32], wv = wr[lane + 64];
        oqA += fiA * wq; oqB += fiB * wq;
        okA += fiA * wk; okB += fiB * wk;
        ovA += fiA * wv; ovB += fiB * wv;
    }

    const int head = lane >> 3, d = lane & 7;
    {
        const size_t ridx = ((size_t)(b * 4 + head) * N_ + nA);
        const size_t qidx = ridx * 16;
        bsplit(elu1(oqA) * (LOG2E * INV_SQRT8), d_Qh[qidx + d],     d_Ql[qidx + d]);
        bsplit(u[(size_t)nA * 8 + d] * LOG2E,   d_Qh[qidx + 8 + d], d_Ql[qidx + 8 + d]);
        bsplit(elu1(okA),                       d_Kh[qidx + d],     d_Kl[qidx + d]);
        bsplit(v[(size_t)d * N_ + nA],          d_Kh[qidx + 8 + d], d_Kl[qidx + 8 + d]);
        bsplit(ovA, d_Vh[ridx * 8 + d], d_Vl[ridx * 8 + d]);
    }
    {
        const size_t ridx = ((size_t)(b * 4 + head) * N_ + nB);
        const size_t qidx = ridx * 16;
        bsplit(elu1(oqB) * (LOG2E * INV_SQRT8), d_Qh[qidx + d],     d_Ql[qidx + d]);
        bsplit(u[(size_t)nB * 8 + d] * LOG2E,   d_Qh[qidx + 8 + d], d_Ql[qidx + 8 + d]);
        bsplit(elu1(okB),                       d_Kh[qidx + d],     d_Kl[qidx + d]);
        bsplit(v[(size_t)d * N_ + nB],          d_Kh[qidx + 8 + d], d_Kl[qidx + 8 + d]);
        bsplit(ovB, d_Vh[ridx * 8 + d], d_Vl[ridx * 8 + d]);
    }
}

// =====================================================================
// Kernel B: tensor-core flash attention, split-K=4, ones-mma row sums
// 256 threads = 8 warps, 128 q-rows/block; double-buffered KTILE,
// register prefetch, ONE __syncthreads per tile; independent
// accumulators per PV product to break mma RAW chains.
// grid (N/128, BH, KSPLIT) = (32, 8, 4) = 1024 blocks
// =====================================================================
#define KTILE 128
#define NIT   ((N_ / KSPLIT) / KTILE)   // 8
__global__ void __launch_bounds__(256)
attn_kernel()
{
    const int bh = blockIdx.y;
    const int qbase = blockIdx.x * 128;
    const int kz = blockIdx.z;
    const int tid = threadIdx.x, w = tid >> 5, l = tid & 31;

    __shared__ __align__(16) unsigned Khl[2][KTILE * 16];
    __shared__ __align__(16) unsigned Vhl[2][8 * 144];

    const unsigned* Qh_u = (const unsigned*)d_Qh + (size_t)bh * N_ * 8;
    const unsigned* Ql_u = (const unsigned*)d_Ql + (size_t)bh * N_ * 8;
    const unsigned* Kh_u = (const unsigned*)d_Kh + (size_t)bh * N_ * 8;
    const unsigned* Kl_u = (const unsigned*)d_Kl + (size_t)bh * N_ * 8;
    const __nv_bfloat16* Vh_g = d_Vh + (size_t)bh * N_ * 8;
    const __nv_bfloat16* Vl_g = d_Vl + (size_t)bh * N_ * 8;

    const int qr0 = qbase + w * 16 + (l >> 2);
    const int qr1 = qr0 + 8;
    const int c4 = l & 3;

    unsigned ah[4], al[4];
    ah[0] = Qh_u[qr0 * 8 + c4];     ah[1] = Qh_u[qr1 * 8 + c4];
    ah[2] = Qh_u[qr0 * 8 + c4 + 4]; ah[3] = Qh_u[qr1 * 8 + c4 + 4];
    al[0] = Ql_u[qr0 * 8 + c4];     al[1] = Ql_u[qr1 * 8 + c4];
    al[2] = Ql_u[qr0 * 8 + c4 + 4]; al[3] = Ql_u[qr1 * 8 + c4 + 4];

    // independent accumulators (merged at the end)
    float O0[4] = {0,0,0,0}, O1[4] = {0,0,0,0}, O2[4] = {0,0,0,0};
    float La[4] = {0,0,0,0}, Lb[4] = {0,0,0,0};
    const unsigned ones2 = 0x3F803F80u;
    unsigned bones[2] = {ones2, ones2};

    unsigned kreg[2][4];
    __nv_bfloat16 vreg[4][2];

    const int kkey0 = tid >> 2, kkc = tid & 3;
    const int kkey1 = (tid + 256) >> 2;
    const int vkey0 = tid >> 3, vvd = tid & 7;

    const int k0 = kz * (N_ / KSPLIT);

    auto ldg_tile = [&](int kt) {
        kreg[0][0] = Kh_u[(size_t)(kt + kkey0) * 8 + kkc];
        kreg[0][1] = Kh_u[(size_t)(kt + kkey0) * 8 + kkc + 4];
        kreg[0][2] = Kl_u[(size_t)(kt + kkey0) * 8 + kkc];
        kreg[0][3] = Kl_u[(size_t)(kt + kkey0) * 8 + kkc + 4];
        kreg[1][0] = Kh_u[(size_t)(kt + kkey1) * 8 + kkc];
        kreg[1][1] = Kh_u[(size_t)(kt + kkey1) * 8 + kkc + 4];
        kreg[1][2] = Kl_u[(size_t)(kt + kkey1) * 8 + kkc];
        kreg[1][3] = Kl_u[(size_t)(kt + kkey1) * 8 + kkc + 4];
#pragma unroll
        for (int i = 0; i < 4; i++) {
            int key = vkey0 + i * 32;
            vreg[i][0] = Vh_g[(size_t)(kt + key) * 8 + vvd];
            vreg[i][1] = Vl_g[(size_t)(kt + key) * 8 + vvd];
        }
    };
    auto sts_tile = [&](int bb) {
        *(uint4*)&Khl[bb][kkey0 * 16 + kkc * 4] =
            make_uint4(kreg[0][0], kreg[0][1], kreg[0][2], kreg[0][3]);
        *(uint4*)&Khl[bb][kkey1 * 16 + kkc * 4] =
            make_uint4(kreg[1][0], kreg[1][1], kreg[1][2], kreg[1][3]);
        __nv_bfloat16* Vsh = (__nv_bfloat16*)Vhl[bb];
#pragma unroll
        for (int i = 0; i < 4; i++) {
            int key = vkey0 + i * 32;
            int j = key >> 1, half = key & 1;
            int ci = j >> 3, c4v = j & 3, hi4 = (j >> 2) & 1;
            int base_u = vvd * 144 + ci * 16 + c4v * 4;
            Vsh[2 * (base_u + hi4) + half]     = vreg[i][0];
            Vsh[2 * (base_u + 2 + hi4) + half] = vreg[i][1];
        }
    };

    ldg_tile(k0);
    sts_tile(0);
    __syncthreads();

    for (int it = 0; it < NIT; it++) {
        const int bb = it & 1;
        if (it + 1 < NIT) ldg_tile(k0 + (it + 1) * KTILE);

        const unsigned* Kb = Khl[bb];
        const unsigned* Vb = Vhl[bb];
#pragma unroll
        for (int c16 = 0; c16 < KTILE; c16 += 16) {
            float S0[4] = {0.f, 0.f, 0.f, 0.f};
            float S1[4] = {0.f, 0.f, 0.f, 0.f};

            const int kr0 = c16 + (l >> 2);
            const int kr1 = kr0 + 8;
            uint4 k0v = *(const uint4*)&Kb[kr0 * 16 + c4 * 4];
            uint4 k1v = *(const uint4*)&Kb[kr1 * 16 + c4 * 4];
            unsigned kh0[2] = {k0v.x, k0v.y}, kl0[2] = {k0v.z, k0v.w};
            unsigned kh1[2] = {k1v.x, k1v.y}, kl1[2] = {k1v.z, k1v.w};

            mma16816(S0, ah, kh0, S0);
            mma16816(S0, al, kh0, S0);
            mma16816(S0, ah, kl0, S0);
            mma16816(S1, ah, kh1, S1);
            mma16816(S1, al, kh1, S1);
            mma16816(S1, ah, kl1, S1);

            float p00 = ex2f(S0[0]), p01 = ex2f(S0[1]);
            float p02 = ex2f(S0[2]), p03 = ex2f(S0[3]);
            float p10 = ex2f(S1[0]), p11 = ex2f(S1[1]);
            float p12 = ex2f(S1[2]), p13 = ex2f(S1[3]);

            unsigned pa_h[4], pa_l[4];
            split2(p00, p01, pa_h[0], pa_l[0]);
            split2(p02, p03, pa_h[1], pa_l[1]);
            split2(p10, p11, pa_h[2], pa_l[2]);
            split2(p12, p13, pa_h[3], pa_l[3]);

            uint4 vv = *(const uint4*)&Vb[(l >> 2) * 144 + (c16 >> 4) * 16 + c4 * 4];
            unsigned vh[2] = {vv.x, vv.y}, vl[2] = {vv.z, vv.w};

            mma16816(O0, pa_h, vh, O0);     // independent chains
            mma16816(O1, pa_l, vh, O1);
            mma16816(O2, pa_h, vl, O2);
            mma16816(La, pa_h, bones, La);
            mma16816(Lb, pa_l, bones, Lb);
        }

        if (it + 1 < NIT) sts_tile(bb ^ 1);
        __syncthreads();
    }

    float O[4], Ol[4];
#pragma unroll
    for (int i = 0; i < 4; i++) {
        O[i]  = O0[i] + O1[i] + O2[i];
        Ol[i] = La[i] + Lb[i];
    }

    const size_t pbase = (size_t)(kz * BH_ + bh) * N_;
    float* o0 = d_patt + (pbase + qr0) * 8 + 2 * c4;
    float* o1 = d_patt + (pbase + qr1) * 8 + 2 * c4;
    o0[0] = O[0]; o0[1] = O[1];
    o1[0] = O[2]; o1[1] = O[3];
    if (c4 == 0) {
        d_pl[pbase + qr0] = Ol[0];
        d_pl[pbase + qr1] = Ol[2];
    }
}

// =====================================================================
// Kernel C: fused split-combine + op-projection + dilated convs + BN +
//           residual LN + horizon MLP. 32 nodes/block (8 warps x 4).
// =====================================================================
__global__ void __launch_bounds__(256)
tail_kernel(const float* __restrict__ op_w, const float* __restrict__ op_b,
            const float* __restrict__ tc0_w, const float* __restrict__ tc0_b,
            const float* __restrict__ tc1_w, const float* __restrict__ tc1_b,
            const float* __restrict__ bn_g, const float* __restrict__ bn_b,
            const float* __restrict__ ln_g, const float* __restrict__ ln_b,
            const float* __restrict__ h1_w, const float* __restrict__ h1_b,
            const float* __restrict__ hln_g, const float* __restrict__ hln_b,
            const float* __restrict__ h2_w, const float* __restrict__ h2_b,
            float* __restrict__ out)
{
    __shared__ float ss[36 * 32];
    __shared__ float at[36 * 33];
    __shared__ float ow[32 * 33];
    __shared__ float tw0[96 * 33];
    __shared__ float tw1[96 * 33];

    const int tid = threadIdx.x;
    const int blk = blockIdx.x;
    const int b   = blk >> 7;
    const int n0  = (blk & 127) << 5;

    for (int idx = tid; idx < 3072; idx += 256) {
        int co = idx / 96, rem = idx % 96;
        tw0[rem * 33 + co] = tc0_w[idx];
        tw1[rem * 33 + co] = tc1_w[idx];
    }
    for (int idx = tid; idx < 1024; idx += 256) {
        int o = idx >> 5, i = idx & 31;
        ow[i * 33 + o] = op_w[idx];
    }
    for (int idx = tid; idx < 1152; idx += 256) {
        int rr = idx >> 5, c = idx & 31;
        int gn = n0 - 2 + rr;
        float val = 0.f;
        if (gn >= 0 && gn < N_) {
            int head = c >> 3, e = c & 7;
            float num = 0.f, den = 0.f;
#pragma unroll
            for (int s = 0; s < KSPLIT; s++) {
                size_t r = ((size_t)(s * BH_ + b * 4 + head) * N_ + gn);
                num += d_patt[r * 8 + e];
                den += d_pl[r];
            }
            val = __fdividef(num, den);
        }
        at[rr * 33 + c] = val;
    }
    __syncthreads();

    const int w = tid >> 5, lane = tid & 31;

    for (int r = w; r < 36; r += 8) {
        int gn = n0 - 2 + r;
        float o = 0.f;
        if (gn >= 0 && gn < N_) {
            o = __ldg(op_b + lane);
#pragma unroll
            for (int i = 0; i < 32; i++)
                o += at[r * 33 + i] * ow[i * 33 + lane];
        }
        ss[r * 32 + lane] = o;
    }
    __syncthreads();

    const float b0 = __ldg(tc0_b + lane), b1 = __ldg(tc1_b + lane);

    float v0[4], v1[4];
#pragma unroll
    for (int t = 0; t < 4; t++) { v0[t] = b0; v1[t] = b1; }

#pragma unroll 4
    for (int ci = 0; ci < 32; ci++) {
        float w00 = tw0[(ci * 3 + 0) * 33 + lane];
        float w01 = tw0[(ci * 3 + 1) * 33 + lane];
        float w02 = tw0[(ci * 3 + 2) * 33 + lane];
        float w10 = tw1[(ci * 3 + 0) * 33 + lane];
        float w11 = tw1[(ci * 3 + 1) * 33 + lane];
        float w12 = tw1[(ci * 3 + 2) * 33 + lane];
        float s[8];
#pragma unroll
        for (int j = 0; j < 8; j++) s[j] = ss[(w * 4 + j) * 32 + ci];
#pragma unroll
        for (int t = 0; t < 4; t++) {
            v0[t] += s[t + 1] * w00 + s[t + 2] * w01 + s[t + 3] * w02;
            v1[t] += s[t]     * w10 + s[t + 2] * w11 + s[t + 4] * w12;
        }
    }

    const float bs = __ldg(bn_g + lane) * rsqrtf(1.f + 1e-5f);
    const float bb = __ldg(bn_b + lane);
    const float lng = __ldg(ln_g + lane), lnb = __ldg(ln_b + lane);

#pragma unroll
    for (int t = 0; t < 4; t++) {
        const int lr = w * 4 + t + 2;
        const int n = n0 + w * 4 + t;
        float y0 = fmaxf(v0[t] * bs + bb, 0.f);
        float y1 = fmaxf(v1[t] * bs + bb, 0.f);
        float resid = 0.5f * (y0 + y1) + ss[lr * 32 + lane];

        float sum = resid, sq = resid * resid;
#pragma unroll
        for (int off = 16; off; off >>= 1) {
            sum += __shfl_xor_sync(0xffffffffu, sum, off);
            sq  += __shfl_xor_sync(0xffffffffu, sq, off);
        }
        float mu = sum * (1.f / 32.f);
        float var = sq * (1.f / 32.f) - mu * mu;
        float rstd = rsqrtf(var + 1e-5f);
        float tout = (resid - mu) * rstd * lng + lnb;

        float hj[8];
#pragma unroll
        for (int j = 0; j < 8; j++) hj[j] = tout * __ldg(h1_w + j * 32 + lane);
#pragma unroll
        for (int j = 0; j < 8; j++)
#pragma unroll
            for (int off = 16; off; off >>= 1)
                hj[j] += __shfl_xor_sync(0xffffffffu, hj[j], off);

        float hsum = 0.f;
#pragma unroll
        for (int j = 0; j < 8; j++) { hj[j] += __ldg(h1_b + j); hsum += hj[j]; }
        float hmu = hsum * (1.f / 8.f);
        float hsq = 0.f;
#pragma unroll
        for (int j = 0; j < 8; j++) { float dd = hj[j] - hmu; hsq += dd * dd; }
        float hrstd = rsqrtf(hsq * (1.f / 8.f) + 1e-5f);
        float hh[8];
#pragma unroll
        for (int j = 0; j < 8; j++)
            hh[j] = fmaxf((hj[j] - hmu) * hrstd * __ldg(hln_g + j) + __ldg(hln_b + j), 0.f);

        if (lane < HOR_) {
            float p = __ldg(h2_b + lane);
#pragma unroll
            for (int j = 0; j < 8; j++) p += hh[j] * __ldg(h2_w + lane * 8 + j);
            out[(size_t)b * HOR_ * N_ + (size_t)lane * N_ + n] = p;
        }
    }
}

// =====================================================================
extern "C" void kernel_launch(void* const* d_in, const int* in_sizes, int n_in,
                              void* d_out, int out_size)
{
    const float* x      = (const float*)d_in[0];
    const float* fe_w   = (const float*)d_in[1];
    const float* fe_b   = (const float*)d_in[2];
    const float* fe_bng = (const float*)d_in[3];
    const float* fe_bnb = (const float*)d_in[4];
    const float* p1_w   = (const float*)d_in[5];
    const float* p1_b   = (const float*)d_in[6];
    const float* p2_w   = (const float*)d_in[7];
    const float* p2_b   = (const float*)d_in[8];
    const float* qkv_w  = (const float*)d_in[9];
    const float* qkv_b  = (const float*)d_in[10];
    const float* op_w   = (const float*)d_in[11];
    const float* op_b   = (const float*)d_in[12];
    const float* u      = (const float*)d_in[13];
    const float* v      = (const float*)d_in[14];
    const float* tc0_w  = (const float*)d_in[15];
    const float* tc0_b  = (const float*)d_in[16];
    const float* tc1_w  = (const float*)d_in[17];
    const float* tc1_b  = (const float*)d_in[18];
    const float* t_bng  = (const float*)d_in[19];
    const float* t_bnb  = (const float*)d_in[20];
    const float* t_lng  = (const float*)d_in[21];
    const float* t_lnb  = (const float*)d_in[22];
    const float* h1_w   = (const float*)d_in[23];
    const float* h1_b   = (const float*)d_in[24];
    const float* h_lng  = (const float*)d_in[25];
    const float* h_lnb  = (const float*)d_in[26];
    const float* h2_w   = (const float*)d_in[27];
    const float* h2_b   = (const float*)d_in[28];
    float* out = (float*)d_out;

    feat_kernel<<<(B_ * N_) / 16, 256>>>(x, fe_w, fe_b, fe_bng, fe_bnb,
                                         p1_w, p1_b, p2_w, p2_b,
                                         qkv_w, qkv_b, u, v);

    dim3 agrid(N_ / 128, BH_, KSPLIT);      // (32, 8, 4) = 1024 blocks
    attn_kernel<<<agrid, 256>>>();

    tail_kernel<<<(B_ * N_) / 32, 256>>>(op_w, op_b,
                                         tc0_w, tc0_b, tc1_w, tc1_b,
                                         t_bng, t_bnb, t_lng, t_lnb,
                                         h1_w, h1_b, h_lng, h_lnb,
                                         h2_w, h2_b, out);
}

// round 15
// speedup vs baseline: 4.1940x; 1.1793x over previous
#include <cuda_runtime.h>
#include <cuda_bf16.h>
#include <cuda_fp16.h>
#include <math.h>

// ---------------- problem constants ----------------
#define B_    2
#define T_    64
#define N_    4096
#define HOR_  24
#define C_    16
#define HID_  32
#define BD_   8
#define HEADS_ 4
#define HD_   8
#define BH_   (B_*HEADS_)      // 8
#define LOG2E 1.4426950408889634f
#define INV_SQRT8 0.35355339059327373f
#define KSPLIT 4

// ---------------- scratch (device globals; no allocation) ----------------
__device__ __align__(16) __nv_bfloat16 d_Qh[BH_ * N_ * 16];
__device__ __align__(16) __nv_bfloat16 d_Ql[BH_ * N_ * 16];
__device__ __align__(16) __nv_bfloat16 d_Kh[BH_ * N_ * 16];
__device__ __align__(16) __nv_bfloat16 d_Kl[BH_ * N_ * 16];
__device__ __align__(16) __half d_Vh[BH_ * N_ * 8];
__device__ __align__(16) __half d_Vl[BH_ * N_ * 8];
__device__ float d_patt[KSPLIT * BH_ * N_ * 8];   // unnormalized partial O
__device__ float d_pl[KSPLIT * BH_ * N_];         // partial row sums

__device__ __forceinline__ float elu1(float x) {
    return x > 0.f ? x + 1.f : __expf(x);
}
__device__ __forceinline__ void bsplit(float x, __nv_bfloat16& hi, __nv_bfloat16& lo) {
    __nv_bfloat16 h = __float2bfloat16(x);
    hi = h;
    lo = __float2bfloat16(x - __bfloat162float(h));
}
__device__ __forceinline__ void hsplit(float x, __half& hi, __half& lo) {
    __half h = __float2half_rn(x);
    hi = h;
    lo = __float2half_rn(x - __half2float(h));
}

// bf16 m16n8k16 mma, fp32 accumulate
__device__ __forceinline__ void mma16816(float d[4], const unsigned a[4],
                                         const unsigned b[2], const float c[4]) {
    asm volatile(
        "mma.sync.aligned.m16n8k16.row.col.f32.bf16.bf16.f32 "
        "{%0,%1,%2,%3}, {%4,%5,%6,%7}, {%8,%9}, {%10,%11,%12,%13};"
        : "=f"(d[0]), "=f"(d[1]), "=f"(d[2]), "=f"(d[3])
        : "r"(a[0]), "r"(a[1]), "r"(a[2]), "r"(a[3]),
          "r"(b[0]), "r"(b[1]),
          "f"(c[0]), "f"(c[1]), "f"(c[2]), "f"(c[3]));
}
// fp16 m16n8k16 mma, fp32 accumulate
__device__ __forceinline__ void mma16816h(float d[4], const unsigned a[4],
                                          const unsigned b[2], const float c[4]) {
    asm volatile(
        "mma.sync.aligned.m16n8k16.row.col.f32.f16.f16.f32 "
        "{%0,%1,%2,%3}, {%4,%5,%6,%7}, {%8,%9}, {%10,%11,%12,%13};"
        : "=f"(d[0]), "=f"(d[1]), "=f"(d[2]), "=f"(d[3])
        : "r"(a[0]), "r"(a[1]), "r"(a[2]), "r"(a[3]),
          "r"(b[0]), "r"(b[1]),
          "f"(c[0]), "f"(c[1]), "f"(c[2]), "f"(c[3]));
}
// pack two fp32 (clamped) into fp16x2: lo = x, hi = y
__device__ __forceinline__ unsigned packh2(float x, float y) {
    unsigned r;
    asm("cvt.rn.f16x2.f32 %0, %1, %2;" : "=r"(r) : "f"(y), "f"(x));
    return r;
}
__device__ __forceinline__ unsigned ex2h2(unsigned s) {
    unsigned r;
    asm("ex2.approx.f16x2 %0, %1;" : "=r"(r) : "r"(s));
    return r;
}

// =====================================================================
// Kernel A: conv -> p1 -> p2 -> qkv -> split Q'/K' (bf16), V (fp16)
// 2 nodes per warp, 16 nodes/block; phase-aliased smem
// =====================================================================
#define XS_OFF  0
#define CW_OFF  4224
#define CSH_OFF 4416
#define P1_OFF  4480
#define WT_OFF  4480
#define FS_OFF  16896
#define FEAT_SMEM 37248

__global__ void __launch_bounds__(256)
feat_kernel(const float* __restrict__ x,
            const float* __restrict__ fe_w, const float* __restrict__ fe_b,
            const float* __restrict__ bn_g, const float* __restrict__ bn_b,
            const float* __restrict__ p1_w, const float* __restrict__ p1_b,
            const float* __restrict__ p2_w, const float* __restrict__ p2_b,
            const float* __restrict__ qkv_w, const float* __restrict__ qkv_b,
            const float* __restrict__ u, const float* __restrict__ v)
{
    __shared__ __align__(16) char sbuf[FEAT_SMEM];
    float* xsf  = (float*)(sbuf + XS_OFF);
    float* cw   = (float*)(sbuf + CW_OFF);
    float* csh  = (float*)(sbuf + CSH_OFF);
    float* p1s  = (float*)(sbuf + P1_OFF);
    float* wt   = (float*)(sbuf + WT_OFF);
    float* fsf  = (float*)(sbuf + FS_OFF);

    const int tid = threadIdx.x;
    const int blk = blockIdx.x;
    const int b   = blk >> 8;
    const int n0  = (blk & 255) << 4;

    for (int i = tid; i < 2048; i += 256)
        ((float4*)p1s)[i] = ((const float4*)p1_w)[i];
    if (tid < 48) {
        int c = tid / 3;
        float sc = bn_g[c] * rsqrtf(1.f + 1e-5f);
        cw[tid] = fe_w[tid] * sc;
    }
    if (tid < 16) {
        float sc = bn_g[tid] * rsqrtf(1.f + 1e-5f);
        csh[tid] = fe_b[tid] * sc + bn_b[tid];
    }
    for (int i = tid; i < 1024; i += 256) {
        int node = i & 15, t = i >> 4;
        xsf[node * 66 + t + 1] = x[(size_t)b * T_ * N_ + (size_t)t * N_ + n0 + node];
    }
    if (tid < 16) { xsf[tid * 66] = 0.f; xsf[tid * 66 + 65] = 0.f; }
    __syncthreads();

    const int w = tid >> 5, lane = tid & 31;
    const int nA = n0 + 2 * w, nB = nA + 1;

    const float* xA = xsf + (2 * w) * 66;
    const float* xB = xsf + (2 * w + 1) * 66;
    const float a0 = xA[lane],      a1 = xA[lane + 1],  a2 = xA[lane + 2];
    const float a3 = xA[lane + 32], a4 = xA[lane + 33], a5 = xA[lane + 34];
    const float c0 = xB[lane],      c1 = xB[lane + 1],  c2 = xB[lane + 2];
    const float c3 = xB[lane + 32], c4_ = xB[lane + 33], c5 = xB[lane + 34];

    float accA[8], accB[8];
#pragma unroll
    for (int j = 0; j < 8; j++) { accA[j] = 0.f; accB[j] = 0.f; }

#pragma unroll
    for (int i = 0; i < 32; i++) {
        int cc = i >> 1;
        float w0 = cw[cc * 3], w1 = cw[cc * 3 + 1], w2 = cw[cc * 3 + 2], sh = csh[cc];
        float valA, valB;
        if ((i & 1) == 0) {
            valA = a0 * w0 + a1 * w1 + a2 * w2 + sh;
            valB = c0 * w0 + c1 * w1 + c2 * w2 + sh;
        } else {
            valA = a3 * w0 + a4 * w1 + a5 * w2 + sh;
            valB = c3 * w0 + c4_ * w1 + c5 * w2 + sh;
        }
        valA = fmaxf(valA, 0.f);
        valB = fmaxf(valB, 0.f);
        int base = i * 32 + lane;
#pragma unroll
        for (int j = 0; j < 8; j++) {
            float pw = p1s[j * 1024 + base];
            accA[j] += valA * pw;
            accB[j] += valB * pw;
        }
    }
#pragma unroll
    for (int j = 0; j < 8; j++)
#pragma unroll
        for (int off = 16; off; off >>= 1) {
            accA[j] += __shfl_xor_sync(0xffffffffu, accA[j], off);
            accB[j] += __shfl_xor_sync(0xffffffffu, accB[j], off);
        }

    float r1A[8], r1B[8];
#pragma unroll
    for (int j = 0; j < 8; j++) {
        float pb = __ldg(p1_b + j);
        r1A[j] = fmaxf(accA[j] + pb, 0.f);
        r1B[j] = fmaxf(accB[j] + pb, 0.f);
    }

    float fA = __ldg(p2_b + lane), fB = fA;
#pragma unroll
    for (int j = 0; j < 8; j++) {
        float pw = __ldg(p2_w + lane * 8 + j);
        fA += r1A[j] * pw;
        fB += r1B[j] * pw;
    }

    __syncthreads();
    for (int idx = tid; idx < 3072; idx += 256) {
        int o = idx >> 5, i = idx & 31;
        wt[i * 97 + o] = qkv_w[idx];
    }
    fsf[(2 * w) * 32 + lane] = fA;
    fsf[(2 * w + 1) * 32 + lane] = fB;
    __syncthreads();

    float oqA = __ldg(qkv_b + lane),      oqB = oqA;
    float okA = __ldg(qkv_b + lane + 32), okB = okA;
    float ovA = __ldg(qkv_b + lane + 64), ovB = ovA;
#pragma unroll
    for (int i = 0; i < 32; i++) {
        float fiA = fsf[(2 * w) * 32 + i];
        float fiB = fsf[(2 * w + 1) * 32 + i];
        const float* wr = wt + i * 97;
        float wq = wr[lane], wk = wr[lane + 32], wv = wr[lane + 64];
        oqA += fiA * wq; oqB += fiB * wq;
        okA += fiA * wk; okB += fiB * wk;
        ovA += fiA * wv; ovB += fiB * wv;
    }

    const int head = lane >> 3, d = lane & 7;
    {
        const size_t ridx = ((size_t)(b * 4 + head) * N_ + nA);
        const size_t qidx = ridx * 16;
        bsplit(elu1(oqA) * (LOG2E * INV_SQRT8), d_Qh[qidx + d],     d_Ql[qidx + d]);
        bsplit(u[(size_t)nA * 8 + d] * LOG2E,   d_Qh[qidx + 8 + d], d_Ql[qidx + 8 + d]);
        bsplit(elu1(okA),                       d_Kh[qidx + d],     d_Kl[qidx + d]);
        bsplit(v[(size_t)d * N_ + nA],          d_Kh[qidx + 8 + d], d_Kl[qidx + 8 + d]);
        hsplit(ovA, d_Vh[ridx * 8 + d], d_Vl[ridx * 8 + d]);
    }
    {
        const size_t ridx = ((size_t)(b * 4 + head) * N_ + nB);
        const size_t qidx = ridx * 16;
        bsplit(elu1(oqB) * (LOG2E * INV_SQRT8), d_Qh[qidx + d],     d_Ql[qidx + d]);
        bsplit(u[(size_t)nB * 8 + d] * LOG2E,   d_Qh[qidx + 8 + d], d_Ql[qidx + 8 + d]);
        bsplit(elu1(okB),                       d_Kh[qidx + d],     d_Kl[qidx + d]);
        bsplit(v[(size_t)d * N_ + nB],          d_Kh[qidx + 8 + d], d_Kl[qidx + 8 + d]);
        hsplit(ovB, d_Vh[ridx * 8 + d], d_Vl[ridx * 8 + d]);
    }
}

// =====================================================================
// Kernel B: tensor-core flash attention; QK bf16-split, softmax+PV in
// packed fp16 (ex2.approx.f16x2, P fp16, V fp16 hi/lo). split-K=4,
// 256 threads, double-buffered, one sync per tile.
// grid (N/128, BH, KSPLIT) = (32, 8, 4) = 1024 blocks
// =====================================================================
#define KTILE 128
#define NIT   ((N_ / KSPLIT) / KTILE)   // 8
#define SCLAMP 15.5f
__global__ void __launch_bounds__(256)
attn_kernel()
{
    const int bh = blockIdx.y;
    const int qbase = blockIdx.x * 128;
    const int kz = blockIdx.z;
    const int tid = threadIdx.x, w = tid >> 5, l = tid & 31;

    __shared__ __align__(16) unsigned Khl[2][KTILE * 16];
    __shared__ __align__(16) unsigned Vhl[2][8 * 144];

    const unsigned* Qh_u = (const unsigned*)d_Qh + (size_t)bh * N_ * 8;
    const unsigned* Ql_u = (const unsigned*)d_Ql + (size_t)bh * N_ * 8;
    const unsigned* Kh_u = (const unsigned*)d_Kh + (size_t)bh * N_ * 8;
    const unsigned* Kl_u = (const unsigned*)d_Kl + (size_t)bh * N_ * 8;
    const __half* Vh_g = d_Vh + (size_t)bh * N_ * 8;
    const __half* Vl_g = d_Vl + (size_t)bh * N_ * 8;

    const int qr0 = qbase + w * 16 + (l >> 2);
    const int qr1 = qr0 + 8;
    const int c4 = l & 3;

    unsigned ah[4], al[4];
    ah[0] = Qh_u[qr0 * 8 + c4];     ah[1] = Qh_u[qr1 * 8 + c4];
    ah[2] = Qh_u[qr0 * 8 + c4 + 4]; ah[3] = Qh_u[qr1 * 8 + c4 + 4];
    al[0] = Ql_u[qr0 * 8 + c4];     al[1] = Ql_u[qr1 * 8 + c4];
    al[2] = Ql_u[qr0 * 8 + c4 + 4]; al[3] = Ql_u[qr1 * 8 + c4 + 4];

    float O0[4] = {0,0,0,0}, O2[4] = {0,0,0,0}, La[4] = {0,0,0,0};
    const unsigned ones2 = 0x3C003C00u;      // fp16x2 {1,1}
    unsigned bones[2] = {ones2, ones2};

    unsigned kreg[2][4];
    __half vreg[4][2];

    const int kkey0 = tid >> 2, kkc = tid & 3;
    const int kkey1 = (tid + 256) >> 2;
    const int vkey0 = tid >> 3, vvd = tid & 7;

    const int k0 = kz * (N_ / KSPLIT);

    auto ldg_tile = [&](int kt) {
        kreg[0][0] = Kh_u[(size_t)(kt + kkey0) * 8 + kkc];
        kreg[0][1] = Kh_u[(size_t)(kt + kkey0) * 8 + kkc + 4];
        kreg[0][2] = Kl_u[(size_t)(kt + kkey0) * 8 + kkc];
        kreg[0][3] = Kl_u[(size_t)(kt + kkey0) * 8 + kkc + 4];
        kreg[1][0] = Kh_u[(size_t)(kt + kkey1) * 8 + kkc];
        kreg[1][1] = Kh_u[(size_t)(kt + kkey1) * 8 + kkc + 4];
        kreg[1][2] = Kl_u[(size_t)(kt + kkey1) * 8 + kkc];
        kreg[1][3] = Kl_u[(size_t)(kt + kkey1) * 8 + kkc + 4];
#pragma unroll
        for (int i = 0; i < 4; i++) {
            int key = vkey0 + i * 32;
            vreg[i][0] = Vh_g[(size_t)(kt + key) * 8 + vvd];
            vreg[i][1] = Vl_g[(size_t)(kt + key) * 8 + vvd];
        }
    };
    auto sts_tile = [&](int bb) {
        *(uint4*)&Khl[bb][kkey0 * 16 + kkc * 4] =
            make_uint4(kreg[0][0], kreg[0][1], kreg[0][2], kreg[0][3]);
        *(uint4*)&Khl[bb][kkey1 * 16 + kkc * 4] =
            make_uint4(kreg[1][0], kreg[1][1], kreg[1][2], kreg[1][3]);
        __half* Vsh = (__half*)Vhl[bb];
#pragma unroll
        for (int i = 0; i < 4; i++) {
            int key = vkey0 + i * 32;
            int j = key >> 1, half = key & 1;
            int ci = j >> 3, c4v = j & 3, hi4 = (j >> 2) & 1;
            int base_u = vvd * 144 + ci * 16 + c4v * 4;
            Vsh[2 * (base_u + hi4) + half]     = vreg[i][0];
            Vsh[2 * (base_u + 2 + hi4) + half] = vreg[i][1];
        }
    };

    ldg_tile(k0);
    sts_tile(0);
    __syncthreads();

    for (int it = 0; it < NIT; it++) {
        const int bb = it & 1;
        if (it + 1 < NIT) ldg_tile(k0 + (it + 1) * KTILE);

        const unsigned* Kb = Khl[bb];
        const unsigned* Vb = Vhl[bb];
#pragma unroll
        for (int c16 = 0; c16 < KTILE; c16 += 16) {
            float S0[4] = {0.f, 0.f, 0.f, 0.f};
            float S1[4] = {0.f, 0.f, 0.f, 0.f};

            const int kr0 = c16 + (l >> 2);
            const int kr1 = kr0 + 8;
            uint4 k0v = *(const uint4*)&Kb[kr0 * 16 + c4 * 4];
            uint4 k1v = *(const uint4*)&Kb[kr1 * 16 + c4 * 4];
            unsigned kh0[2] = {k0v.x, k0v.y}, kl0[2] = {k0v.z, k0v.w};
            unsigned kh1[2] = {k1v.x, k1v.y}, kl1[2] = {k1v.z, k1v.w};

            mma16816(S0, ah, kh0, S0);
            mma16816(S0, al, kh0, S0);
            mma16816(S0, ah, kl0, S0);
            mma16816(S1, ah, kh1, S1);
            mma16816(S1, al, kh1, S1);
            mma16816(S1, ah, kl1, S1);

            // packed fp16 softmax: clamp -> cvt f16x2 -> ex2.f16x2
            unsigned pa[4];
            pa[0] = ex2h2(packh2(fminf(S0[0], SCLAMP), fminf(S0[1], SCLAMP)));
            pa[1] = ex2h2(packh2(fminf(S0[2], SCLAMP), fminf(S0[3], SCLAMP)));
            pa[2] = ex2h2(packh2(fminf(S1[0], SCLAMP), fminf(S1[1], SCLAMP)));
            pa[3] = ex2h2(packh2(fminf(S1[2], SCLAMP), fminf(S1[3], SCLAMP)));

            uint4 vv = *(const uint4*)&Vb[(l >> 2) * 144 + (c16 >> 4) * 16 + c4 * 4];
            unsigned vh[2] = {vv.x, vv.y}, vl[2] = {vv.z, vv.w};

            mma16816h(O0, pa, vh, O0);
            mma16816h(O2, pa, vl, O2);
            mma16816h(La, pa, bones, La);
        }

        if (it + 1 < NIT) sts_tile(bb ^ 1);
        __syncthreads();
    }

    float O[4];
#pragma unroll
    for (int i = 0; i < 4; i++) O[i] = O0[i] + O2[i];

    const size_t pbase = (size_t)(kz * BH_ + bh) * N_;
    float* o0 = d_patt + (pbase + qr0) * 8 + 2 * c4;
    float* o1 = d_patt + (pbase + qr1) * 8 + 2 * c4;
    o0[0] = O[0]; o0[1] = O[1];
    o1[0] = O[2]; o1[1] = O[3];
    if (c4 == 0) {
        d_pl[pbase + qr0] = La[0];
        d_pl[pbase + qr1] = La[2];
    }
}

// =====================================================================
// Kernel C: fused split-combine + op-projection + dilated convs + BN +
//           residual LN + horizon MLP. 32 nodes/block (8 warps x 4).
// =====================================================================
__global__ void __launch_bounds__(256)
tail_kernel(const float* __restrict__ op_w, const float* __restrict__ op_b,
            const float* __restrict__ tc0_w, const float* __restrict__ tc0_b,
            const float* __restrict__ tc1_w, const float* __restrict__ tc1_b,
            const float* __restrict__ bn_g, const float* __restrict__ bn_b,
            const float* __restrict__ ln_g, const float* __restrict__ ln_b,
            const float* __restrict__ h1_w, const float* __restrict__ h1_b,
            const float* __restrict__ hln_g, const float* __restrict__ hln_b,
            const float* __restrict__ h2_w, const float* __restrict__ h2_b,
            float* __restrict__ out)
{
    __shared__ float ss[36 * 32];
    __shared__ float at[36 * 33];
    __shared__ float ow[32 * 33];
    __shared__ float tw0[96 * 33];
    __shared__ float tw1[96 * 33];

    const int tid = threadIdx.x;
    const int blk = blockIdx.x;
    const int b   = blk >> 7;
    const int n0  = (blk & 127) << 5;

    for (int idx = tid; idx < 3072; idx += 256) {
        int co = idx / 96, rem = idx % 96;
        tw0[rem * 33 + co] = tc0_w[idx];
        tw1[rem * 33 + co] = tc1_w[idx];
    }
    for (int idx = tid; idx < 1024; idx += 256) {
        int o = idx >> 5, i = idx & 31;
        ow[i * 33 + o] = op_w[idx];
    }
    for (int idx = tid; idx < 1152; idx += 256) {
        int rr = idx >> 5, c = idx & 31;
        int gn = n0 - 2 + rr;
        float val = 0.f;
        if (gn >= 0 && gn < N_) {
            int head = c >> 3, e = c & 7;
            float num = 0.f, den = 0.f;
#pragma unroll
            for (int s = 0; s < KSPLIT; s++) {
                size_t r = ((size_t)(s * BH_ + b * 4 + head) * N_ + gn);
                num += d_patt[r * 8 + e];
                den += d_pl[r];
            }
            val = __fdividef(num, den);
        }
        at[rr * 33 + c] = val;
    }
    __syncthreads();

    const int w = tid >> 5, lane = tid & 31;

    for (int r = w; r < 36; r += 8) {
        int gn = n0 - 2 + r;
        float o = 0.f;
        if (gn >= 0 && gn < N_) {
            o = __ldg(op_b + lane);
#pragma unroll
            for (int i = 0; i < 32; i++)
                o += at[r * 33 + i] * ow[i * 33 + lane];
        }
        ss[r * 32 + lane] = o;
    }
    __syncthreads();

    const float b0 = __ldg(tc0_b + lane), b1 = __ldg(tc1_b + lane);

    float v0[4], v1[4];
#pragma unroll
    for (int t = 0; t < 4; t++) { v0[t] = b0; v1[t] = b1; }

#pragma unroll 4
    for (int ci = 0; ci < 32; ci++) {
        float w00 = tw0[(ci * 3 + 0) * 33 + lane];
        float w01 = tw0[(ci * 3 + 1) * 33 + lane];
        float w02 = tw0[(ci * 3 + 2) * 33 + lane];
        float w10 = tw1[(ci * 3 + 0) * 33 + lane];
        float w11 = tw1[(ci * 3 + 1) * 33 + lane];
        float w12 = tw1[(ci * 3 + 2) * 33 + lane];
        float s[8];
#pragma unroll
        for (int j = 0; j < 8; j++) s[j] = ss[(w * 4 + j) * 32 + ci];
#pragma unroll
        for (int t = 0; t < 4; t++) {
            v0[t] += s[t + 1] * w00 + s[t + 2] * w01 + s[t + 3] * w02;
            v1[t] += s[t]     * w10 + s[t + 2] * w11 + s[t + 4] * w12;
        }
    }

    const float bs = __ldg(bn_g + lane) * rsqrtf(1.f + 1e-5f);
    const float bb = __ldg(bn_b + lane);
    const float lng = __ldg(ln_g + lane), lnb = __ldg(ln_b + lane);

#pragma unroll
    for (int t = 0; t < 4; t++) {
        const int lr = w * 4 + t + 2;
        const int n = n0 + w * 4 + t;
        float y0 = fmaxf(v0[t] * bs + bb, 0.f);
        float y1 = fmaxf(v1[t] * bs + bb, 0.f);
        float resid = 0.5f * (y0 + y1) + ss[lr * 32 + lane];

        float sum = resid, sq = resid * resid;
#pragma unroll
        for (int off = 16; off; off >>= 1) {
            sum += __shfl_xor_sync(0xffffffffu, sum, off);
            sq  += __shfl_xor_sync(0xffffffffu, sq, off);
        }
        float mu = sum * (1.f / 32.f);
        float var = sq * (1.f / 32.f) - mu * mu;
        float rstd = rsqrtf(var + 1e-5f);
        float tout = (resid - mu) * rstd * lng + lnb;

        float hj[8];
#pragma unroll
        for (int j = 0; j < 8; j++) hj[j] = tout * __ldg(h1_w + j * 32 + lane);
#pragma unroll
        for (int j = 0; j < 8; j++)
#pragma unroll
            for (int off = 16; off; off >>= 1)
                hj[j] += __shfl_xor_sync(0xffffffffu, hj[j], off);

        float hsum = 0.f;
#pragma unroll
        for (int j = 0; j < 8; j++) { hj[j] += __ldg(h1_b + j); hsum += hj[j]; }
        float hmu = hsum * (1.f / 8.f);
        float hsq = 0.f;
#pragma unroll
        for (int j = 0; j < 8; j++) { float dd = hj[j] - hmu; hsq += dd * dd; }
        float hrstd = rsqrtf(hsq * (1.f / 8.f) + 1e-5f);
        float hh[8];
#pragma unroll
        for (int j = 0; j < 8; j++)
            hh[j] = fmaxf((hj[j] - hmu) * hrstd * __ldg(hln_g + j) + __ldg(hln_b + j), 0.f);

        if (lane < HOR_) {
            float p = __ldg(h2_b + lane);
#pragma unroll
            for (int j = 0; j < 8; j++) p += hh[j] * __ldg(h2_w + lane * 8 + j);
            out[(size_t)b * HOR_ * N_ + (size_t)lane * N_ + n] = p;
        }
    }
}

// =====================================================================
extern "C" void kernel_launch(void* const* d_in, const int* in_sizes, int n_in,
                              void* d_out, int out_size)
{
    const float* x      = (const float*)d_in[0];
    const float* fe_w   = (const float*)d_in[1];
    const float* fe_b   = (const float*)d_in[2];
    const float* fe_bng = (const float*)d_in[3];
    const float* fe_bnb = (const float*)d_in[4];
    const float* p1_w   = (const float*)d_in[5];
    const float* p1_b   = (const float*)d_in[6];
    const float* p2_w   = (const float*)d_in[7];
    const float* p2_b   = (const float*)d_in[8];
    const float* qkv_w  = (const float*)d_in[9];
    const float* qkv_b  = (const float*)d_in[10];
    const float* op_w   = (const float*)d_in[11];
    const float* op_b   = (const float*)d_in[12];
    const float* u      = (const float*)d_in[13];
    const float* v      = (const float*)d_in[14];
    const float* tc0_w  = (const float*)d_in[15];
    const float* tc0_b  = (const float*)d_in[16];
    const float* tc1_w  = (const float*)d_in[17];
    const float* tc1_b  = (const float*)d_in[18];
    const float* t_bng  = (const float*)d_in[19];
    const float* t_bnb  = (const float*)d_in[20];
    const float* t_lng  = (const float*)d_in[21];
    const float* t_lnb  = (const float*)d_in[22];
    const float* h1_w   = (const float*)d_in[23];
    const float* h1_b   = (const float*)d_in[24];
    const float* h_lng  = (const float*)d_in[25];
    const float* h_lnb  = (const float*)d_in[26];
    const float* h2_w   = (const float*)d_in[27];
    const float* h2_b   = (const float*)d_in[28];
    float* out = (float*)d_out;

    feat_kernel<<<(B_ * N_) / 16, 256>>>(x, fe_w, fe_b, fe_bng, fe_bnb,
                                         p1_w, p1_b, p2_w, p2_b,
                                         qkv_w, qkv_b, u, v);

    dim3 agrid(N_ / 128, BH_, KSPLIT);      // (32, 8, 4) = 1024 blocks
    attn_kernel<<<agrid, 256>>>();

    tail_kernel<<<(B_ * N_) / 32, 256>>>(op_w, op_b,
                                         tc0_w, tc0_b, tc1_w, tc1_b,
                                         t_bng, t_bnb, t_lng, t_lnb,
                                         h1_w, h1_b, h_lng, h_lnb,
                                         h2_w, h2_b, out);
}

// round 16
// speedup vs baseline: 4.4803x; 1.0683x over previous
#include <cuda_runtime.h>
#include <cuda_bf16.h>
#include <cuda_fp16.h>
#include <math.h>

// ---------------- problem constants ----------------
#define B_    2
#define T_    64
#define N_    4096
#define HOR_  24
#define C_    16
#define HID_  32
#define BD_   8
#define HEADS_ 4
#define HD_   8
#define BH_   (B_*HEADS_)      // 8
#define LOG2E 1.4426950408889634f
#define INV_SQRT8 0.35355339059327373f
#define KSPLIT 4

// ---------------- scratch (device globals; no allocation) ----------------
__device__ __align__(16) __nv_bfloat16 d_Qh[BH_ * N_ * 16];
__device__ __align__(16) __nv_bfloat16 d_Ql[BH_ * N_ * 16];
__device__ __align__(16) __nv_bfloat16 d_Kh[BH_ * N_ * 16];
__device__ __align__(16) __nv_bfloat16 d_Kl[BH_ * N_ * 16];
__device__ __align__(16) __half d_Vh[BH_ * N_ * 8];
__device__ float d_patt[KSPLIT * BH_ * N_ * 8];   // unnormalized partial O
__device__ float d_pl[KSPLIT * BH_ * N_];         // partial row sums

__device__ __forceinline__ float elu1(float x) {
    return x > 0.f ? x + 1.f : __expf(x);
}
__device__ __forceinline__ void bsplit(float x, __nv_bfloat16& hi, __nv_bfloat16& lo) {
    __nv_bfloat16 h = __float2bfloat16(x);
    hi = h;
    lo = __float2bfloat16(x - __bfloat162float(h));
}

// bf16 m16n8k16 mma, fp32 accumulate
__device__ __forceinline__ void mma16816(float d[4], const unsigned a[4],
                                         const unsigned b[2], const float c[4]) {
    asm volatile(
        "mma.sync.aligned.m16n8k16.row.col.f32.bf16.bf16.f32 "
        "{%0,%1,%2,%3}, {%4,%5,%6,%7}, {%8,%9}, {%10,%11,%12,%13};"
        : "=f"(d[0]), "=f"(d[1]), "=f"(d[2]), "=f"(d[3])
        : "r"(a[0]), "r"(a[1]), "r"(a[2]), "r"(a[3]),
          "r"(b[0]), "r"(b[1]),
          "f"(c[0]), "f"(c[1]), "f"(c[2]), "f"(c[3]));
}
// fp16 m16n8k16 mma, fp32 accumulate
__device__ __forceinline__ void mma16816h(float d[4], const unsigned a[4],
                                          const unsigned b[2], const float c[4]) {
    asm volatile(
        "mma.sync.aligned.m16n8k16.row.col.f32.f16.f16.f32 "
        "{%0,%1,%2,%3}, {%4,%5,%6,%7}, {%8,%9}, {%10,%11,%12,%13};"
        : "=f"(d[0]), "=f"(d[1]), "=f"(d[2]), "=f"(d[3])
        : "r"(a[0]), "r"(a[1]), "r"(a[2]), "r"(a[3]),
          "r"(b[0]), "r"(b[1]),
          "f"(c[0]), "f"(c[1]), "f"(c[2]), "f"(c[3]));
}
// pack two fp32 into fp16x2: lo half = x, hi half = y
__device__ __forceinline__ unsigned packh2(float x, float y) {
    unsigned r;
    asm("cvt.rn.f16x2.f32 %0, %1, %2;" : "=r"(r) : "f"(y), "f"(x));
    return r;
}
__device__ __forceinline__ unsigned ex2h2(unsigned s) {
    unsigned r;
    asm("ex2.approx.f16x2 %0, %1;" : "=r"(r) : "r"(s));
    return r;
}

// =====================================================================
// Kernel A: conv -> p1 -> p2 -> qkv -> split Q'/K' (bf16), V (fp16)
// 2 nodes per warp, 16 nodes/block; phase-aliased smem
// =====================================================================
#define XS_OFF  0
#define CW_OFF  4224
#define CSH_OFF 4416
#define P1_OFF  4480
#define WT_OFF  4480
#define FS_OFF  16896
#define FEAT_SMEM 37248

__global__ void __launch_bounds__(256)
feat_kernel(const float* __restrict__ x,
            const float* __restrict__ fe_w, const float* __restrict__ fe_b,
            const float* __restrict__ bn_g, const float* __restrict__ bn_b,
            const float* __restrict__ p1_w, const float* __restrict__ p1_b,
            const float* __restrict__ p2_w, const float* __restrict__ p2_b,
            const float* __restrict__ qkv_w, const float* __restrict__ qkv_b,
            const float* __restrict__ u, const float* __restrict__ v)
{
    __shared__ __align__(16) char sbuf[FEAT_SMEM];
    float* xsf  = (float*)(sbuf + XS_OFF);
    float* cw   = (float*)(sbuf + CW_OFF);
    float* csh  = (float*)(sbuf + CSH_OFF);
    float* p1s  = (float*)(sbuf + P1_OFF);
    float* wt   = (float*)(sbuf + WT_OFF);
    float* fsf  = (float*)(sbuf + FS_OFF);

    const int tid = threadIdx.x;
    const int blk = blockIdx.x;
    const int b   = blk >> 8;
    const int n0  = (blk & 255) << 4;

    for (int i = tid; i < 2048; i += 256)
        ((float4*)p1s)[i] = ((const float4*)p1_w)[i];
    if (tid < 48) {
        int c = tid / 3;
        float sc = bn_g[c] * rsqrtf(1.f + 1e-5f);
        cw[tid] = fe_w[tid] * sc;
    }
    if (tid < 16) {
        float sc = bn_g[tid] * rsqrtf(1.f + 1e-5f);
        csh[tid] = fe_b[tid] * sc + bn_b[tid];
    }
    for (int i = tid; i < 1024; i += 256) {
        int node = i & 15, t = i >> 4;
        xsf[node * 66 + t + 1] = x[(size_t)b * T_ * N_ + (size_t)t * N_ + n0 + node];
    }
    if (tid < 16) { xsf[tid * 66] = 0.f; xsf[tid * 66 + 65] = 0.f; }
    __syncthreads();

    const int w = tid >> 5, lane = tid & 31;
    const int nA = n0 + 2 * w, nB = nA + 1;

    const float* xA = xsf + (2 * w) * 66;
    const float* xB = xsf + (2 * w + 1) * 66;
    const float a0 = xA[lane],      a1 = xA[lane + 1],  a2 = xA[lane + 2];
    const float a3 = xA[lane + 32], a4 = xA[lane + 33], a5 = xA[lane + 34];
    const float c0 = xB[lane],      c1 = xB[lane + 1],  c2 = xB[lane + 2];
    const float c3 = xB[lane + 32], c4_ = xB[lane + 33], c5 = xB[lane + 34];

    float accA[8], accB[8];
#pragma unroll
    for (int j = 0; j < 8; j++) { accA[j] = 0.f; accB[j] = 0.f; }

#pragma unroll
    for (int i = 0; i < 32; i++) {
        int cc = i >> 1;
        float w0 = cw[cc * 3], w1 = cw[cc * 3 + 1], w2 = cw[cc * 3 + 2], sh = csh[cc];
        float valA, valB;
        if ((i & 1) == 0) {
            valA = a0 * w0 + a1 * w1 + a2 * w2 + sh;
            valB = c0 * w0 + c1 * w1 + c2 * w2 + sh;
        } else {
            valA = a3 * w0 + a4 * w1 + a5 * w2 + sh;
            valB = c3 * w0 + c4_ * w1 + c5 * w2 + sh;
        }
        valA = fmaxf(valA, 0.f);
        valB = fmaxf(valB, 0.f);
        int base = i * 32 + lane;
#pragma unroll
        for (int j = 0; j < 8; j++) {
            float pw = p1s[j * 1024 + base];
            accA[j] += valA * pw;
            accB[j] += valB * pw;
        }
    }
#pragma unroll
    for (int j = 0; j < 8; j++)
#pragma unroll
        for (int off = 16; off; off >>= 1) {
            accA[j] += __shfl_xor_sync(0xffffffffu, accA[j], off);
            accB[j] += __shfl_xor_sync(0xffffffffu, accB[j], off);
        }

    float r1A[8], r1B[8];
#pragma unroll
    for (int j = 0; j < 8; j++) {
        float pb = __ldg(p1_b + j);
        r1A[j] = fmaxf(accA[j] + pb, 0.f);
        r1B[j] = fmaxf(accB[j] + pb, 0.f);
    }

    float fA = __ldg(p2_b + lane), fB = fA;
#pragma unroll
    for (int j = 0; j < 8; j++) {
        float pw = __ldg(p2_w + lane * 8 + j);
        fA += r1A[j] * pw;
        fB += r1B[j] * pw;
    }

    __syncthreads();
    for (int idx = tid; idx < 3072; idx += 256) {
        int o = idx >> 5, i = idx & 31;
        wt[i * 97 + o] = qkv_w[idx];
    }
    fsf[(2 * w) * 32 + lane] = fA;
    fsf[(2 * w + 1) * 32 + lane] = fB;
    __syncthreads();

    float oqA = __ldg(qkv_b + lane),      oqB = oqA;
    float okA = __ldg(qkv_b + lane + 32), okB = okA;
    float ovA = __ldg(qkv_b + lane + 64), ovB = ovA;
#pragma unroll
    for (int i = 0; i < 32; i++) {
        float fiA = fsf[(2 * w) * 32 + i];
        float fiB = fsf[(2 * w + 1) * 32 + i];
        const float* wr = wt + i * 97;
        float wq = wr[lane], wk = wr[lane + 32], wv = wr[lane + 64];
        oqA += fiA * wq; oqB += fiB * wq;
        okA += fiA * wk; okB += fiB * wk;
        ovA += fiA * wv; ovB += fiB * wv;
    }

    const int head = lane >> 3, d = lane & 7;
    {
        const size_t ridx = ((size_t)(b * 4 + head) * N_ + nA);
        const size_t qidx = ridx * 16;
        bsplit(elu1(oqA) * (LOG2E * INV_SQRT8), d_Qh[qidx + d],     d_Ql[qidx + d]);
        bsplit(u[(size_t)nA * 8 + d] * LOG2E,   d_Qh[qidx + 8 + d], d_Ql[qidx + 8 + d]);
        bsplit(elu1(okA),                       d_Kh[qidx + d],     d_Kl[qidx + d]);
        bsplit(v[(size_t)d * N_ + nA],          d_Kh[qidx + 8 + d], d_Kl[qidx + 8 + d]);
        d_Vh[ridx * 8 + d] = __float2half_rn(ovA);
    }
    {
        const size_t ridx = ((size_t)(b * 4 + head) * N_ + nB);
        const size_t qidx = ridx * 16;
        bsplit(elu1(oqB) * (LOG2E * INV_SQRT8), d_Qh[qidx + d],     d_Ql[qidx + d]);
        bsplit(u[(size_t)nB * 8 + d] * LOG2E,   d_Qh[qidx + 8 + d], d_Ql[qidx + 8 + d]);
        bsplit(elu1(okB),                       d_Kh[qidx + d],     d_Kl[qidx + d]);
        bsplit(v[(size_t)d * N_ + nB],          d_Kh[qidx + 8 + d], d_Kl[qidx + 8 + d]);
        d_Vh[ridx * 8 + d] = __float2half_rn(ovB);
    }
}

// =====================================================================
// Kernel B: tensor-core flash attention; QK bf16-split, softmax+PV in
// packed fp16 (ex2.approx.f16x2, P fp16, V fp16 single). split-K=4,
// 256 threads, double-buffered, one sync per tile.
// grid (N/128, BH, KSPLIT) = (32, 8, 4) = 1024 blocks
// =====================================================================
#define KTILE 128
#define NIT   ((N_ / KSPLIT) / KTILE)   // 8
#define SCLAMP 15.5f
__global__ void __launch_bounds__(256)
attn_kernel()
{
    const int bh = blockIdx.y;
    const int qbase = blockIdx.x * 128;
    const int kz = blockIdx.z;
    const int tid = threadIdx.x, w = tid >> 5, l = tid & 31;

    __shared__ __align__(16) unsigned Khl[2][KTILE * 16];   // 16 KB
    __shared__ __align__(16) unsigned Vs_[2][8 * 72];       // 4.6 KB (fp16 V only)

    const unsigned* Qh_u = (const unsigned*)d_Qh + (size_t)bh * N_ * 8;
    const unsigned* Ql_u = (const unsigned*)d_Ql + (size_t)bh * N_ * 8;
    const unsigned* Kh_u = (const unsigned*)d_Kh + (size_t)bh * N_ * 8;
    const unsigned* Kl_u = (const unsigned*)d_Kl + (size_t)bh * N_ * 8;
    const __half* Vh_g = d_Vh + (size_t)bh * N_ * 8;

    const int qr0 = qbase + w * 16 + (l >> 2);
    const int qr1 = qr0 + 8;
    const int c4 = l & 3;

    unsigned ah[4], al[4];
    ah[0] = Qh_u[qr0 * 8 + c4];     ah[1] = Qh_u[qr1 * 8 + c4];
    ah[2] = Qh_u[qr0 * 8 + c4 + 4]; ah[3] = Qh_u[qr1 * 8 + c4 + 4];
    al[0] = Ql_u[qr0 * 8 + c4];     al[1] = Ql_u[qr1 * 8 + c4];
    al[2] = Ql_u[qr0 * 8 + c4 + 4]; al[3] = Ql_u[qr1 * 8 + c4 + 4];

    float O0[4] = {0,0,0,0}, La[4] = {0,0,0,0};
    const unsigned ones2 = 0x3C003C00u;      // fp16x2 {1,1}
    unsigned bones[2] = {ones2, ones2};

    unsigned kreg[2][4];
    __half vreg[4];

    const int kkey0 = tid >> 2, kkc = tid & 3;
    const int kkey1 = (tid + 256) >> 2;
    const int vkey0 = tid >> 3, vvd = tid & 7;

    const int k0 = kz * (N_ / KSPLIT);

    auto ldg_tile = [&](int kt) {
        kreg[0][0] = Kh_u[(size_t)(kt + kkey0) * 8 + kkc];
        kreg[0][1] = Kh_u[(size_t)(kt + kkey0) * 8 + kkc + 4];
        kreg[0][2] = Kl_u[(size_t)(kt + kkey0) * 8 + kkc];
        kreg[0][3] = Kl_u[(size_t)(kt + kkey0) * 8 + kkc + 4];
        kreg[1][0] = Kh_u[(size_t)(kt + kkey1) * 8 + kkc];
        kreg[1][1] = Kh_u[(size_t)(kt + kkey1) * 8 + kkc + 4];
        kreg[1][2] = Kl_u[(size_t)(kt + kkey1) * 8 + kkc];
        kreg[1][3] = Kl_u[(size_t)(kt + kkey1) * 8 + kkc + 4];
#pragma unroll
        for (int i = 0; i < 4; i++) {
            int key = vkey0 + i * 32;
            vreg[i] = Vh_g[(size_t)(kt + key) * 8 + vvd];
        }
    };
    auto sts_tile = [&](int bb) {
        *(uint4*)&Khl[bb][kkey0 * 16 + kkc * 4] =
            make_uint4(kreg[0][0], kreg[0][1], kreg[0][2], kreg[0][3]);
        *(uint4*)&Khl[bb][kkey1 * 16 + kkc * 4] =
            make_uint4(kreg[1][0], kreg[1][1], kreg[1][2], kreg[1][3]);
        __half* Vsh = (__half*)Vs_[bb];
#pragma unroll
        for (int i = 0; i < 4; i++) {
            int key = vkey0 + i * 32;
            int j = key >> 1, half = key & 1;
            int ci = j >> 3, c4v = j & 3, hi4 = (j >> 2) & 1;
            // uint index = vd*72 + ci*8 + c4v*2 + hi4; 16-bit half within
            Vsh[2 * (vvd * 72 + ci * 8 + c4v * 2 + hi4) + half] = vreg[i];
        }
    };

    ldg_tile(k0);
    sts_tile(0);
    __syncthreads();

    for (int it = 0; it < NIT; it++) {
        const int bb = it & 1;
        if (it + 1 < NIT) ldg_tile(k0 + (it + 1) * KTILE);

        const unsigned* Kb = Khl[bb];
        const unsigned* Vb = Vs_[bb];
#pragma unroll
        for (int c16 = 0; c16 < KTILE; c16 += 16) {
            float S0[4] = {0.f, 0.f, 0.f, 0.f};
            float S1[4] = {0.f, 0.f, 0.f, 0.f};

            const int kr0 = c16 + (l >> 2);
            const int kr1 = kr0 + 8;
            uint4 k0v = *(const uint4*)&Kb[kr0 * 16 + c4 * 4];
            uint4 k1v = *(const uint4*)&Kb[kr1 * 16 + c4 * 4];
            unsigned kh0[2] = {k0v.x, k0v.y}, kl0[2] = {k0v.z, k0v.w};
            unsigned kh1[2] = {k1v.x, k1v.y}, kl1[2] = {k1v.z, k1v.w};

            mma16816(S0, ah, kh0, S0);
            mma16816(S0, al, kh0, S0);
            mma16816(S0, ah, kl0, S0);
            mma16816(S1, ah, kh1, S1);
            mma16816(S1, al, kh1, S1);
            mma16816(S1, ah, kl1, S1);

            // packed fp16 softmax: clamp -> cvt f16x2 -> ex2.f16x2
            unsigned pa[4];
            pa[0] = ex2h2(packh2(fminf(S0[0], SCLAMP), fminf(S0[1], SCLAMP)));
            pa[1] = ex2h2(packh2(fminf(S0[2], SCLAMP), fminf(S0[3], SCLAMP)));
            pa[2] = ex2h2(packh2(fminf(S1[0], SCLAMP), fminf(S1[1], SCLAMP)));
            pa[3] = ex2h2(packh2(fminf(S1[2], SCLAMP), fminf(S1[3], SCLAMP)));

            // V: LDS.64, conflict-free (stride 72 uints per vd)
            uint2 vv = *(const uint2*)&Vb[(l >> 2) * 72 + (c16 >> 4) * 8 + c4 * 2];
            unsigned vh[2] = {vv.x, vv.y};

            mma16816h(O0, pa, vh, O0);
            mma16816h(La, pa, bones, La);
        }

        if (it + 1 < NIT) sts_tile(bb ^ 1);
        __syncthreads();
    }

    const size_t pbase = (size_t)(kz * BH_ + bh) * N_;
    float* o0 = d_patt + (pbase + qr0) * 8 + 2 * c4;
    float* o1 = d_patt + (pbase + qr1) * 8 + 2 * c4;
    o0[0] = O0[0]; o0[1] = O0[1];
    o1[0] = O0[2]; o1[1] = O0[3];
    if (c4 == 0) {
        d_pl[pbase + qr0] = La[0];
        d_pl[pbase + qr1] = La[2];
    }
}

// =====================================================================
// Kernel C: fused split-combine + op-projection + dilated convs + BN +
//           residual LN + horizon MLP. 32 nodes/block (8 warps x 4).
// =====================================================================
__global__ void __launch_bounds__(256)
tail_kernel(const float* __restrict__ op_w, const float* __restrict__ op_b,
            const float* __restrict__ tc0_w, const float* __restrict__ tc0_b,
            const float* __restrict__ tc1_w, const float* __restrict__ tc1_b,
            const float* __restrict__ bn_g, const float* __restrict__ bn_b,
            const float* __restrict__ ln_g, const float* __restrict__ ln_b,
            const float* __restrict__ h1_w, const float* __restrict__ h1_b,
            const float* __restrict__ hln_g, const float* __restrict__ hln_b,
            const float* __restrict__ h2_w, const float* __restrict__ h2_b,
            float* __restrict__ out)
{
    __shared__ float ss[36 * 32];
    __shared__ float at[36 * 33];
    __shared__ float ow[32 * 33];
    __shared__ float tw0[96 * 33];
    __shared__ float tw1[96 * 33];

    const int tid = threadIdx.x;
    const int blk = blockIdx.x;
    const int b   = blk >> 7;
    const int n0  = (blk & 127) << 5;

    for (int idx = tid; idx < 3072; idx += 256) {
        int co = idx / 96, rem = idx % 96;
        tw0[rem * 33 + co] = tc0_w[idx];
        tw1[rem * 33 + co] = tc1_w[idx];
    }
    for (int idx = tid; idx < 1024; idx += 256) {
        int o = idx >> 5, i = idx & 31;
        ow[i * 33 + o] = op_w[idx];
    }
    for (int idx = tid; idx < 1152; idx += 256) {
        int rr = idx >> 5, c = idx & 31;
        int gn = n0 - 2 + rr;
        float val = 0.f;
        if (gn >= 0 && gn < N_) {
            int head = c >> 3, e = c & 7;
            float num = 0.f, den = 0.f;
#pragma unroll
            for (int s = 0; s < KSPLIT; s++) {
                size_t r = ((size_t)(s * BH_ + b * 4 + head) * N_ + gn);
                num += d_patt[r * 8 + e];
                den += d_pl[r];
            }
            val = __fdividef(num, den);
        }
        at[rr * 33 + c] = val;
    }
    __syncthreads();

    const int w = tid >> 5, lane = tid & 31;

    for (int r = w; r < 36; r += 8) {
        int gn = n0 - 2 + r;
        float o = 0.f;
        if (gn >= 0 && gn < N_) {
            o = __ldg(op_b + lane);
#pragma unroll
            for (int i = 0; i < 32; i++)
                o += at[r * 33 + i] * ow[i * 33 + lane];
        }
        ss[r * 32 + lane] = o;
    }
    __syncthreads();

    const float b0 = __ldg(tc0_b + lane), b1 = __ldg(tc1_b + lane);

    float v0[4], v1[4];
#pragma unroll
    for (int t = 0; t < 4; t++) { v0[t] = b0; v1[t] = b1; }

#pragma unroll 4
    for (int ci = 0; ci < 32; ci++) {
        float w00 = tw0[(ci * 3 + 0) * 33 + lane];
        float w01 = tw0[(ci * 3 + 1) * 33 + lane];
        float w02 = tw0[(ci * 3 + 2) * 33 + lane];
        float w10 = tw1[(ci * 3 + 0) * 33 + lane];
        float w11 = tw1[(ci * 3 + 1) * 33 + lane];
        float w12 = tw1[(ci * 3 + 2) * 33 + lane];
        float s[8];
#pragma unroll
        for (int j = 0; j < 8; j++) s[j] = ss[(w * 4 + j) * 32 + ci];
#pragma unroll
        for (int t = 0; t < 4; t++) {
            v0[t] += s[t + 1] * w00 + s[t + 2] * w01 + s[t + 3] * w02;
            v1[t] += s[t]     * w10 + s[t + 2] * w11 + s[t + 4] * w12;
        }
    }

    const float bs = __ldg(bn_g + lane) * rsqrtf(1.f + 1e-5f);
    const float bb = __ldg(bn_b + lane);
    const float lng = __ldg(ln_g + lane), lnb = __ldg(ln_b + lane);

#pragma unroll
    for (int t = 0; t < 4; t++) {
        const int lr = w * 4 + t + 2;
        const int n = n0 + w * 4 + t;
        float y0 = fmaxf(v0[t] * bs + bb, 0.f);
        float y1 = fmaxf(v1[t] * bs + bb, 0.f);
        float resid = 0.5f * (y0 + y1) + ss[lr * 32 + lane];

        float sum = resid, sq = resid * resid;
#pragma unroll
        for (int off = 16; off; off >>= 1) {
            sum += __shfl_xor_sync(0xffffffffu, sum, off);
            sq  += __shfl_xor_sync(0xffffffffu, sq, off);
        }
        float mu = sum * (1.f / 32.f);
        float var = sq * (1.f / 32.f) - mu * mu;
        float rstd = rsqrtf(var + 1e-5f);
        float tout = (resid - mu) * rstd * lng + lnb;

        float hj[8];
#pragma unroll
        for (int j = 0; j < 8; j++) hj[j] = tout * __ldg(h1_w + j * 32 + lane);
#pragma unroll
        for (int j = 0; j < 8; j++)
#pragma unroll
            for (int off = 16; off; off >>= 1)
                hj[j] += __shfl_xor_sync(0xffffffffu, hj[j], off);

        float hsum = 0.f;
#pragma unroll
        for (int j = 0; j < 8; j++) { hj[j] += __ldg(h1_b + j); hsum += hj[j]; }
        float hmu = hsum * (1.f / 8.f);
        float hsq = 0.f;
#pragma unroll
        for (int j = 0; j < 8; j++) { float dd = hj[j] - hmu; hsq += dd * dd; }
        float hrstd = rsqrtf(hsq * (1.f / 8.f) + 1e-5f);
        float hh[8];
#pragma unroll
        for (int j = 0; j < 8; j++)
            hh[j] = fmaxf((hj[j] - hmu) * hrstd * __ldg(hln_g + j) + __ldg(hln_b + j), 0.f);

        if (lane < HOR_) {
            float p = __ldg(h2_b + lane);
#pragma unroll
            for (int j = 0; j < 8; j++) p += hh[j] * __ldg(h2_w + lane * 8 + j);
            out[(size_t)b * HOR_ * N_ + (size_t)lane * N_ + n] = p;
        }
    }
}

// =====================================================================
extern "C" void kernel_launch(void* const* d_in, const int* in_sizes, int n_in,
                              void* d_out, int out_size)
{
    const float* x      = (const float*)d_in[0];
    const float* fe_w   = (const float*)d_in[1];
    const float* fe_b   = (const float*)d_in[2];
    const float* fe_bng = (const float*)d_in[3];
    const float* fe_bnb = (const float*)d_in[4];
    const float* p1_w   = (const float*)d_in[5];
    const float* p1_b   = (const float*)d_in[6];
    const float* p2_w   = (const float*)d_in[7];
    const float* p2_b   = (const float*)d_in[8];
    const float* qkv_w  = (const float*)d_in[9];
    const float* qkv_b  = (const float*)d_in[10];
    const float* op_w   = (const float*)d_in[11];
    const float* op_b   = (const float*)d_in[12];
    const float* u      = (const float*)d_in[13];
    const float* v      = (const float*)d_in[14];
    const float* tc0_w  = (const float*)d_in[15];
    const float* tc0_b  = (const float*)d_in[16];
    const float* tc1_w  = (const float*)d_in[17];
    const float* tc1_b  = (const float*)d_in[18];
    const float* t_bng  = (const float*)d_in[19];
    const float* t_bnb  = (const float*)d_in[20];
    const float* t_lng  = (const float*)d_in[21];
    const float* t_lnb  = (const float*)d_in[22];
    const float* h1_w   = (const float*)d_in[23];
    const float* h1_b   = (const float*)d_in[24];
    const float* h_lng  = (const float*)d_in[25];
    const float* h_lnb  = (const float*)d_in[26];
    const float* h2_w   = (const float*)d_in[27];
    const float* h2_b   = (const float*)d_in[28];
    float* out = (float*)d_out;

    feat_kernel<<<(B_ * N_) / 16, 256>>>(x, fe_w, fe_b, fe_bng, fe_bnb,
                                         p1_w, p1_b, p2_w, p2_b,
                                         qkv_w, qkv_b, u, v);

    dim3 agrid(N_ / 128, BH_, KSPLIT);      // (32, 8, 4) = 1024 blocks
    attn_kernel<<<agrid, 256>>>();

    tail_kernel<<<(B_ * N_) / 32, 256>>>(op_w, op_b,
                                         tc0_w, tc0_b, tc1_w, tc1_b,
                                         t_bng, t_bnb, t_lng, t_lnb,
                                         h1_w, h1_b, h_lng, h_lnb,
                                         h2_w, h2_b, out);
}